// round 1
// baseline (speedup 1.0000x reference)
#include <cuda_runtime.h>
#include <math.h>
#include <stdint.h>

// ---------------- problem constants ----------------
#define BB   2
#define TT   1024
#define CC   768
#define HH   12
#define DD   64
#define LL   12
#define VV   50257
#define MR   (BB*TT)      // 2048 rows
#define C3   (3*CC)       // 2304
#define C4   (4*CC)       // 3072

// ---------------- scratch (no allocations allowed) ----------------
__device__ float g_x  [MR*CC];   // residual stream
__device__ float g_ln [MR*CC];   // layernorm output
__device__ float g_qkv[MR*C3];   // qkv
__device__ float g_y  [MR*CC];   // attention output
__device__ float g_fc [MR*C4];   // fc hidden

// ---------------- embedding ----------------
__global__ void embed_kernel(const int* __restrict__ idx,
                             const float* __restrict__ wte,
                             const float* __restrict__ wpe) {
    int row = blockIdx.x;            // 0..2047
    int t   = row % TT;
    int tok = idx[row];
    const float* we = wte + (size_t)tok * CC;
    const float* wp = wpe + (size_t)t   * CC;
    float* out = g_x + (size_t)row * CC;
    for (int i = threadIdx.x; i < CC; i += blockDim.x)
        out[i] = we[i] + wp[i];
}

// ---------------- layernorm (one block per row) ----------------
__global__ __launch_bounds__(256)
void ln_kernel(const float* __restrict__ x,
               const float* __restrict__ g,
               const float* __restrict__ b,
               float* __restrict__ out) {
    int row = blockIdx.x;
    const float* xr = x + (size_t)row * CC;
    float s = 0.f, s2 = 0.f;
    for (int i = threadIdx.x; i < CC; i += 256) {
        float v = xr[i];
        s += v; s2 += v * v;
    }
    for (int o = 16; o; o >>= 1) {
        s  += __shfl_xor_sync(0xffffffffu, s,  o);
        s2 += __shfl_xor_sync(0xffffffffu, s2, o);
    }
    __shared__ float sh0[8], sh1[8];
    int w = threadIdx.x >> 5, l = threadIdx.x & 31;
    if (l == 0) { sh0[w] = s; sh1[w] = s2; }
    __syncthreads();
    if (w == 0) {
        s  = (l < 8) ? sh0[l] : 0.f;
        s2 = (l < 8) ? sh1[l] : 0.f;
        for (int o = 4; o; o >>= 1) {
            s  += __shfl_xor_sync(0xffffffffu, s,  o);
            s2 += __shfl_xor_sync(0xffffffffu, s2, o);
        }
        if (l == 0) { sh0[0] = s; sh1[0] = s2; }
    }
    __syncthreads();
    float mean = sh0[0] * (1.0f / CC);
    float var  = sh1[0] * (1.0f / CC) - mean * mean;
    float rstd = rsqrtf(var + 1e-5f);
    float* orow = out + (size_t)row * CC;
    for (int i = threadIdx.x; i < CC; i += 256)
        orow[i] = (xr[i] - mean) * rstd * g[i] + b[i];
}

// ---------------- GELU (tanh approx, matches jax approximate=True) ----------------
__device__ __forceinline__ float gelu_f(float x) {
    float x3 = x * x * x;
    return 0.5f * x * (1.0f + tanhf(0.7978845608028654f * (x + 0.044715f * x3)));
}

// ---------------- GEMM: C = epi(A[M,K] @ B[K,N]) ----------------
// EPI bits: 1=+bias, 2=gelu, 4=+residual
#define GBM 128
#define GBN 64
#define GBK 16
#define GTM 8
#define GTN 4
// 256 threads: tx = t%16 (n dir), ty = t/16 (m dir)

template<int EPI>
__global__ __launch_bounds__(256)
void gemm_kernel(const float* __restrict__ A, const float* __restrict__ B,
                 const float* __restrict__ bias, const float* __restrict__ res,
                 float* __restrict__ C, int M, int N, int K) {
    __shared__ __align__(16) float As[GBK][GBM];
    __shared__ __align__(16) float Bs[GBK][GBN];

    int m0 = blockIdx.y * GBM;
    int n0 = blockIdx.x * GBN;
    int t  = threadIdx.x;
    int tx = t & 15, ty = t >> 4;

    float acc[GTM][GTN];
#pragma unroll
    for (int i = 0; i < GTM; i++)
#pragma unroll
        for (int j = 0; j < GTN; j++) acc[i][j] = 0.f;

    int arow = t >> 2;           // 0..63 (two passes: +0, +64)
    int acol = (t & 3) * 4;      // 0,4,8,12
    int brow = t >> 4;           // 0..15
    int bcol = (t & 15) * 4;     // 0..60

    const bool nfull = (n0 + GBN <= N) && ((N & 3) == 0);

    for (int k0 = 0; k0 < K; k0 += GBK) {
        // A tile: 128x16, float4 per thread x2, stored transposed
#pragma unroll
        for (int r = 0; r < 2; r++) {
            int m = m0 + arow + r * 64;
            float4 v = *(const float4*)(A + (size_t)m * K + k0 + acol);
            As[acol + 0][arow + r * 64] = v.x;
            As[acol + 1][arow + r * 64] = v.y;
            As[acol + 2][arow + r * 64] = v.z;
            As[acol + 3][arow + r * 64] = v.w;
        }
        // B tile: 16x64
        {
            int kk = k0 + brow;
            if (nfull) {
                float4 v = *(const float4*)(B + (size_t)kk * N + n0 + bcol);
                *(float4*)&Bs[brow][bcol] = v;
            } else {
#pragma unroll
                for (int j = 0; j < 4; j++) {
                    int n = n0 + bcol + j;
                    Bs[brow][bcol + j] = (n < N) ? B[(size_t)kk * N + n] : 0.f;
                }
            }
        }
        __syncthreads();

#pragma unroll
        for (int k = 0; k < GBK; k++) {
            float4 a0 = *(const float4*)&As[k][ty * GTM];
            float4 a1 = *(const float4*)&As[k][ty * GTM + 4];
            float4 bv = *(const float4*)&Bs[k][tx * GTN];
            float a[GTM] = {a0.x, a0.y, a0.z, a0.w, a1.x, a1.y, a1.z, a1.w};
            float bb2[GTN] = {bv.x, bv.y, bv.z, bv.w};
#pragma unroll
            for (int i = 0; i < GTM; i++)
#pragma unroll
                for (int j = 0; j < GTN; j++)
                    acc[i][j] = fmaf(a[i], bb2[j], acc[i][j]);
        }
        __syncthreads();
    }

#pragma unroll
    for (int i = 0; i < GTM; i++) {
        int m = m0 + ty * GTM + i;
#pragma unroll
        for (int j = 0; j < GTN; j++) {
            int n = n0 + tx * GTN + j;
            if (n < N) {
                float v = acc[i][j];
                if (EPI & 1) v += bias[n];
                if (EPI & 2) v = gelu_f(v);
                if (EPI & 4) v += res[(size_t)m * N + n];
                C[(size_t)m * N + n] = v;
            }
        }
    }
}

// ---------------- attention: one warp per query row, online softmax ----------------
__global__ __launch_bounds__(128)
void attn_kernel(const float* __restrict__ qkv, float* __restrict__ y) {
    int warp = threadIdx.x >> 5, lane = threadIdx.x & 31;
    int q = blockIdx.x * 4 + warp;
    int h = blockIdx.y, b = blockIdx.z;

    const float* qp = qkv + ((size_t)(b * TT + q)) * C3 + h * DD;
    const float scale = 0.125f;  // 1/sqrt(64)
    float q0 = qp[0]      * scale;  // placeholder; replaced below with lane index
    q0 = qp[lane] * scale;
    float q1 = qp[lane + 32] * scale;

    const float* Kbase = qkv + (size_t)b * TT * C3 + CC  + h * DD;
    const float* Vbase = qkv + (size_t)b * TT * C3 + 2*CC + h * DD;

    float m = -1e30f, se = 0.f, a0 = 0.f, a1 = 0.f;
    for (int j = 0; j <= q; j++) {
        const float* kr = Kbase + (size_t)j * C3;
        float s = q0 * kr[lane] + q1 * kr[lane + 32];
#pragma unroll
        for (int o = 16; o; o >>= 1) s += __shfl_xor_sync(0xffffffffu, s, o);
        float mn = fmaxf(m, s);
        float p  = __expf(s - mn);
        float c  = __expf(m - mn);
        const float* vr = Vbase + (size_t)j * C3;
        a0 = a0 * c + p * vr[lane];
        a1 = a1 * c + p * vr[lane + 32];
        se = se * c + p;
        m = mn;
    }
    float inv = 1.f / se;
    float* yr = y + ((size_t)(b * TT + q)) * CC + h * DD;
    yr[lane]      = a0 * inv;
    yr[lane + 32] = a1 * inv;
}

// ---------------- host orchestration ----------------
extern "C" void kernel_launch(void* const* d_in, const int* in_sizes, int n_in,
                              void* d_out, int out_size) {
    const int*   idx   = (const int*)  d_in[0];
    const float* wte   = (const float*)d_in[1];
    const float* wpe   = (const float*)d_in[2];
    const float* ln1_g = (const float*)d_in[3];
    const float* ln1_b = (const float*)d_in[4];
    const float* wqkv  = (const float*)d_in[5];
    const float* bqkv  = (const float*)d_in[6];
    const float* wproj = (const float*)d_in[7];
    const float* bproj = (const float*)d_in[8];
    const float* ln2_g = (const float*)d_in[9];
    const float* ln2_b = (const float*)d_in[10];
    const float* wfc   = (const float*)d_in[11];
    const float* bfc   = (const float*)d_in[12];
    const float* wfc2  = (const float*)d_in[13];
    const float* bfc2  = (const float*)d_in[14];
    const float* lnf_g = (const float*)d_in[15];
    const float* lnf_b = (const float*)d_in[16];
    const float* lm_w  = (const float*)d_in[17];
    float* out = (float*)d_out;

    float *x, *lnb, *qkv, *y, *fc;
    cudaGetSymbolAddress((void**)&x,   g_x);
    cudaGetSymbolAddress((void**)&lnb, g_ln);
    cudaGetSymbolAddress((void**)&qkv, g_qkv);
    cudaGetSymbolAddress((void**)&y,   g_y);
    cudaGetSymbolAddress((void**)&fc,  g_fc);

    embed_kernel<<<MR, 256>>>(idx, wte, wpe);

    for (int l = 0; l < LL; l++) {
        ln_kernel<<<MR, 256>>>(x, ln1_g + (size_t)l * CC, ln1_b + (size_t)l * CC, lnb);

        // qkv = ln @ wqkv + bqkv   [2048 x 2304]
        gemm_kernel<1><<<dim3(C3 / GBN, MR / GBM), 256>>>(
            lnb, wqkv + (size_t)l * CC * C3, bqkv + (size_t)l * C3, nullptr,
            qkv, MR, C3, CC);

        attn_kernel<<<dim3(TT / 4, HH, BB), 128>>>(qkv, y);

        // x = x + y @ wproj + bproj
        gemm_kernel<5><<<dim3(CC / GBN, MR / GBM), 256>>>(
            y, wproj + (size_t)l * CC * CC, bproj + (size_t)l * CC, x,
            x, MR, CC, CC);

        ln_kernel<<<MR, 256>>>(x, ln2_g + (size_t)l * CC, ln2_b + (size_t)l * CC, lnb);

        // fc = gelu(ln @ wfc + bfc)   [2048 x 3072]
        gemm_kernel<3><<<dim3(C4 / GBN, MR / GBM), 256>>>(
            lnb, wfc + (size_t)l * CC * C4, bfc + (size_t)l * C4, nullptr,
            fc, MR, C4, CC);

        // x = x + fc @ wfc2 + bfc2
        gemm_kernel<5><<<dim3(CC / GBN, MR / GBM), 256>>>(
            fc, wfc2 + (size_t)l * C4 * CC, bfc2 + (size_t)l * CC, x,
            x, MR, CC, C4);
    }

    ln_kernel<<<MR, 256>>>(x, lnf_g, lnf_b, lnb);

    // logits = ln @ lm_w   [2048 x 50257]
    int gn = (VV + GBN - 1) / GBN;
    gemm_kernel<0><<<dim3(gn, MR / GBM), 256>>>(
        lnb, lm_w, nullptr, nullptr, out, MR, VV, CC);
}

// round 3
// speedup vs baseline: 1.4223x; 1.4223x over previous
#include <cuda_runtime.h>
#include <math.h>
#include <stdint.h>

// ---------------- problem constants ----------------
#define BB   2
#define TT   1024
#define CC   768
#define HH   12
#define DD   64
#define LL   12
#define VV   50257
#define MR   (BB*TT)      // 2048 rows
#define C3   (3*CC)       // 2304
#define C4   (4*CC)       // 3072

// ---------------- scratch (no allocations allowed) ----------------
__device__ float g_x  [MR*CC];   // residual stream
__device__ float g_ln [MR*CC];   // layernorm output
__device__ float g_qkv[MR*C3];   // qkv
__device__ float g_y  [MR*CC];   // attention output
__device__ float g_fc [MR*C4];   // fc hidden

// ---------------- helpers ----------------
__device__ __forceinline__ float tf32r(float x) {
    float y;
    asm("cvt.rna.tf32.f32 %0, %1;" : "=f"(y) : "f"(x));
    return y;
}

__device__ __forceinline__ void mma_tf32(float* c, uint32_t a0, uint32_t a1,
                                         uint32_t a2, uint32_t a3,
                                         uint32_t b0, uint32_t b1) {
    asm volatile(
        "mma.sync.aligned.m16n8k8.row.col.f32.tf32.tf32.f32 "
        "{%0,%1,%2,%3}, {%4,%5,%6,%7}, {%8,%9}, {%0,%1,%2,%3};"
        : "+f"(c[0]), "+f"(c[1]), "+f"(c[2]), "+f"(c[3])
        : "r"(a0), "r"(a1), "r"(a2), "r"(a3), "r"(b0), "r"(b1));
}

__device__ __forceinline__ float gelu_f(float x) {
    float x3 = x * x * x;
    return 0.5f * x * (1.0f + tanhf(0.7978845608028654f * (x + 0.044715f * x3)));
}

// ---------------- embedding ----------------
__global__ void embed_kernel(const int* __restrict__ idx,
                             const float* __restrict__ wte,
                             const float* __restrict__ wpe) {
    int row = blockIdx.x;
    int t   = row % TT;
    int tok = idx[row];
    const float* we = wte + (size_t)tok * CC;
    const float* wp = wpe + (size_t)t   * CC;
    float* out = g_x + (size_t)row * CC;
    for (int i = threadIdx.x; i < CC; i += blockDim.x)
        out[i] = we[i] + wp[i];
}

// ---------------- layernorm ----------------
__global__ __launch_bounds__(256)
void ln_kernel(const float* __restrict__ x,
               const float* __restrict__ g,
               const float* __restrict__ b,
               float* __restrict__ out) {
    int row = blockIdx.x;
    const float* xr = x + (size_t)row * CC;
    float s = 0.f, s2 = 0.f;
    for (int i = threadIdx.x; i < CC; i += 256) {
        float v = xr[i];
        s += v; s2 += v * v;
    }
    for (int o = 16; o; o >>= 1) {
        s  += __shfl_xor_sync(0xffffffffu, s,  o);
        s2 += __shfl_xor_sync(0xffffffffu, s2, o);
    }
    __shared__ float sh0[8], sh1[8];
    int w = threadIdx.x >> 5, l = threadIdx.x & 31;
    if (l == 0) { sh0[w] = s; sh1[w] = s2; }
    __syncthreads();
    if (w == 0) {
        s  = (l < 8) ? sh0[l] : 0.f;
        s2 = (l < 8) ? sh1[l] : 0.f;
        for (int o = 4; o; o >>= 1) {
            s  += __shfl_xor_sync(0xffffffffu, s,  o);
            s2 += __shfl_xor_sync(0xffffffffu, s2, o);
        }
        if (l == 0) { sh0[0] = s; sh1[0] = s2; }
    }
    __syncthreads();
    float mean = sh0[0] * (1.0f / CC);
    float var  = sh1[0] * (1.0f / CC) - mean * mean;
    float rstd = rsqrtf(var + 1e-5f);
    float* orow = out + (size_t)row * CC;
    for (int i = threadIdx.x; i < 256 * ((CC + 255) / 256); i += 256)
        if (i < CC)
            orow[i] = (xr[i] - mean) * rstd * g[i] + b[i];
}

// ---------------- tf32 mma.sync GEMM ----------------
// C[M,N] = epi(A[M,K] @ B[K,N]); EPI bits: 1=+bias, 2=gelu, 4=+residual
// CTA tile 128x128x32; 8 warps in 2x4; warp tile 64x32 (4x4 frags of 16x8).
#define BM 128
#define BN 128
#define BK 32
#define SAP 36    // sA row pad (floats)
#define SBP 136   // sB row pad (floats)

template<int EPI>
__global__ __launch_bounds__(256, 2)
void gemm_mma(const float* __restrict__ A, const float* __restrict__ B,
              const float* __restrict__ bias, const float* __restrict__ res,
              float* __restrict__ C, int M, int N, int K) {
    __shared__ __align__(16) float sA[BM][SAP];   // [M][K]
    __shared__ __align__(16) float sB[BK][SBP];   // [K][N]

    const int t = threadIdx.x;
    const int wid = t >> 5, lane = t & 31;
    const int grp = lane >> 2, tig = lane & 3;
    const int warp_m = wid >> 2;          // 0..1
    const int warp_n = wid & 3;           // 0..3
    const int m0 = blockIdx.y * BM;
    const int n0 = blockIdx.x * BN;

    float acc[4][4][4];
#pragma unroll
    for (int im = 0; im < 4; im++)
#pragma unroll
        for (int in = 0; in < 4; in++)
#pragma unroll
            for (int r = 0; r < 4; r++) acc[im][in][r] = 0.f;

    const bool n4 = ((N & 3) == 0);
    const int nchunks = K / BK;

    for (int c = 0; c < nchunks; c++) {
        const int k0 = c * BK;
        // A tile: 128x32 floats, [M][K]
#pragma unroll
        for (int i = 0; i < 4; i++) {
            int idx = t + i * 256;
            int row = idx >> 3, c4 = (idx & 7) * 4;
            float4 v = *(const float4*)(A + (size_t)(m0 + row) * K + k0 + c4);
            float4 w;
            w.x = tf32r(v.x); w.y = tf32r(v.y); w.z = tf32r(v.z); w.w = tf32r(v.w);
            *(float4*)&sA[row][c4] = w;
        }
        // B tile: 32x128 floats, [K][N] (no transpose)
#pragma unroll
        for (int i = 0; i < 4; i++) {
            int idx = t + i * 256;
            int kk = idx >> 5, nn = (idx & 31) * 4;
            int nb = n0 + nn;
            const float* Brow = B + (size_t)(k0 + kk) * N;
            float4 w;
            if (n4 && nb + 3 < N) {
                float4 v = *(const float4*)(Brow + nb);
                w.x = tf32r(v.x); w.y = tf32r(v.y); w.z = tf32r(v.z); w.w = tf32r(v.w);
            } else {
                w.x = (nb + 0 < N) ? tf32r(Brow[nb + 0]) : 0.f;
                w.y = (nb + 1 < N) ? tf32r(Brow[nb + 1]) : 0.f;
                w.z = (nb + 2 < N) ? tf32r(Brow[nb + 2]) : 0.f;
                w.w = (nb + 3 < N) ? tf32r(Brow[nb + 3]) : 0.f;
            }
            *(float4*)&sB[kk][nn] = w;
        }
        __syncthreads();

#pragma unroll
        for (int ks = 0; ks < 4; ks++) {
            const int kb = ks * 8;
            uint32_t au[4][4];
#pragma unroll
            for (int im = 0; im < 4; im++) {
                int rb = warp_m * 64 + im * 16;
                au[im][0] = __float_as_uint(sA[rb + grp    ][kb + tig    ]);
                au[im][1] = __float_as_uint(sA[rb + grp + 8][kb + tig    ]);
                au[im][2] = __float_as_uint(sA[rb + grp    ][kb + tig + 4]);
                au[im][3] = __float_as_uint(sA[rb + grp + 8][kb + tig + 4]);
            }
            uint32_t bu[4][2];
#pragma unroll
            for (int in = 0; in < 4; in++) {
                int nb = warp_n * 32 + in * 8 + grp;
                bu[in][0] = __float_as_uint(sB[kb + tig    ][nb]);
                bu[in][1] = __float_as_uint(sB[kb + tig + 4][nb]);
            }
#pragma unroll
            for (int im = 0; im < 4; im++)
#pragma unroll
                for (int in = 0; in < 4; in++)
                    mma_tf32(acc[im][in], au[im][0], au[im][1], au[im][2], au[im][3],
                             bu[in][0], bu[in][1]);
        }
        __syncthreads();
    }

    // ---- epilogue: regs -> global, fused bias/gelu/residual ----
    const bool n2 = ((N & 1) == 0);
#pragma unroll
    for (int im = 0; im < 4; im++) {
        int r0 = m0 + warp_m * 64 + im * 16 + grp;
        int r1 = r0 + 8;
#pragma unroll
        for (int in = 0; in < 4; in++) {
            int nc = n0 + warp_n * 32 + in * 8 + tig * 2;
            float v00 = acc[im][in][0], v01 = acc[im][in][1];
            float v10 = acc[im][in][2], v11 = acc[im][in][3];
            if (EPI & 1) {
                float b0v = (nc < N) ? bias[nc] : 0.f;
                float b1v = (nc + 1 < N) ? bias[nc + 1] : 0.f;
                v00 += b0v; v10 += b0v; v01 += b1v; v11 += b1v;
            }
            if (EPI & 2) {
                v00 = gelu_f(v00); v01 = gelu_f(v01);
                v10 = gelu_f(v10); v11 = gelu_f(v11);
            }
            if (EPI & 4) {
                if (nc < N) { v00 += res[(size_t)r0 * N + nc]; v10 += res[(size_t)r1 * N + nc]; }
                if (nc + 1 < N) { v01 += res[(size_t)r0 * N + nc + 1]; v11 += res[(size_t)r1 * N + nc + 1]; }
            }
            if (n2 && nc + 1 < N) {
                *(float2*)(C + (size_t)r0 * N + nc) = make_float2(v00, v01);
                *(float2*)(C + (size_t)r1 * N + nc) = make_float2(v10, v11);
            } else {
                if (nc < N)     { C[(size_t)r0 * N + nc]     = v00; C[(size_t)r1 * N + nc]     = v10; }
                if (nc + 1 < N) { C[(size_t)r0 * N + nc + 1] = v01; C[(size_t)r1 * N + nc + 1] = v11; }
            }
        }
    }
}

// ---------------- attention: one warp per query row, online softmax ----------------
__global__ __launch_bounds__(128)
void attn_kernel(const float* __restrict__ qkv, float* __restrict__ y) {
    int warp = threadIdx.x >> 5, lane = threadIdx.x & 31;
    int q = blockIdx.x * 4 + warp;
    int h = blockIdx.y, b = blockIdx.z;

    const float* qp = qkv + ((size_t)(b * TT + q)) * C3 + h * DD;
    const float scale = 0.125f;
    float q0 = qp[lane] * scale;
    float q1 = qp[lane + 32] * scale;

    const float* Kbase = qkv + (size_t)b * TT * C3 + CC  + h * DD;
    const float* Vbase = qkv + (size_t)b * TT * C3 + 2*CC + h * DD;

    float m = -1e30f, se = 0.f, a0 = 0.f, a1 = 0.f;
    for (int j = 0; j <= q; j++) {
        const float* kr = Kbase + (size_t)j * C3;
        float s = q0 * kr[lane] + q1 * kr[lane + 32];
#pragma unroll
        for (int o = 16; o; o >>= 1) s += __shfl_xor_sync(0xffffffffu, s, o);
        float mn = fmaxf(m, s);
        float p  = __expf(s - mn);
        float cc = __expf(m - mn);
        const float* vr = Vbase + (size_t)j * C3;
        a0 = a0 * cc + p * vr[lane];
        a1 = a1 * cc + p * vr[lane + 32];
        se = se * cc + p;
        m = mn;
    }
    float inv = 1.f / se;
    float* yr = y + ((size_t)(b * TT + q)) * CC + h * DD;
    yr[lane]      = a0 * inv;
    yr[lane + 32] = a1 * inv;
}

// ---------------- host orchestration ----------------
extern "C" void kernel_launch(void* const* d_in, const int* in_sizes, int n_in,
                              void* d_out, int out_size) {
    const int*   idx   = (const int*)  d_in[0];
    const float* wte   = (const float*)d_in[1];
    const float* wpe   = (const float*)d_in[2];
    const float* ln1_g = (const float*)d_in[3];
    const float* ln1_b = (const float*)d_in[4];
    const float* wqkv  = (const float*)d_in[5];
    const float* bqkv  = (const float*)d_in[6];
    const float* wproj = (const float*)d_in[7];
    const float* bproj = (const float*)d_in[8];
    const float* ln2_g = (const float*)d_in[9];
    const float* ln2_b = (const float*)d_in[10];
    const float* wfc   = (const float*)d_in[11];
    const float* bfc   = (const float*)d_in[12];
    const float* wfc2  = (const float*)d_in[13];
    const float* bfc2  = (const float*)d_in[14];
    const float* lnf_g = (const float*)d_in[15];
    const float* lnf_b = (const float*)d_in[16];
    const float* lm_w  = (const float*)d_in[17];
    float* out = (float*)d_out;

    float *x, *lnb, *qkv, *y, *fc;
    cudaGetSymbolAddress((void**)&x,   g_x);
    cudaGetSymbolAddress((void**)&lnb, g_ln);
    cudaGetSymbolAddress((void**)&qkv, g_qkv);
    cudaGetSymbolAddress((void**)&y,   g_y);
    cudaGetSymbolAddress((void**)&fc,  g_fc);

    embed_kernel<<<MR, 256>>>(idx, wte, wpe);

    for (int l = 0; l < LL; l++) {
        ln_kernel<<<MR, 256>>>(x, ln1_g + (size_t)l * CC, ln1_b + (size_t)l * CC, lnb);

        // qkv = ln @ wqkv + bqkv   [2048 x 2304]
        gemm_mma<1><<<dim3(C3 / BN, MR / BM), 256>>>(
            lnb, wqkv + (size_t)l * CC * C3, bqkv + (size_t)l * C3, nullptr,
            qkv, MR, C3, CC);

        attn_kernel<<<dim3(TT / 4, HH, BB), 128>>>(qkv, y);

        // x = x + y @ wproj + bproj
        gemm_mma<5><<<dim3(CC / BN, MR / BM), 256>>>(
            y, wproj + (size_t)l * CC * CC, bproj + (size_t)l * CC, x,
            x, MR, CC, CC);

        ln_kernel<<<MR, 256>>>(x, ln2_g + (size_t)l * CC, ln2_b + (size_t)l * CC, lnb);

        // fc = gelu(ln @ wfc + bfc)   [2048 x 3072]
        gemm_mma<3><<<dim3(C4 / BN, MR / BM), 256>>>(
            lnb, wfc + (size_t)l * CC * C4, bfc + (size_t)l * C4, nullptr,
            fc, MR, C4, CC);

        // x = x + fc @ wfc2 + bfc2
        gemm_mma<5><<<dim3(CC / BN, MR / BM), 256>>>(
            fc, wfc2 + (size_t)l * C4 * CC, bfc2 + (size_t)l * CC, x,
            x, MR, CC, C4);
    }

    ln_kernel<<<MR, 256>>>(x, lnf_g, lnf_b, lnb);

    // logits = ln @ lm_w   [2048 x 50257]
    int gn = (VV + BN - 1) / BN;
    gemm_mma<0><<<dim3(gn, MR / BM), 256>>>(
        lnb, lm_w, nullptr, nullptr, out, MR, VV, CC);
}

// round 4
// speedup vs baseline: 2.0067x; 1.4109x over previous
#include <cuda_runtime.h>
#include <cuda_fp16.h>
#include <math.h>
#include <stdint.h>

// ---------------- problem constants ----------------
#define BB   2
#define TT   1024
#define CC   768
#define HH   12
#define DD   64
#define LL   12
#define VV   50257
#define MR   (BB*TT)      // 2048 rows
#define C3   (3*CC)       // 2304
#define C4   (4*CC)       // 3072

// ---------------- scratch (no allocations allowed) ----------------
__device__ float g_x  [MR*CC];   // residual stream
__device__ float g_ln [MR*CC];   // layernorm output
__device__ float g_qkv[MR*C3];   // qkv
__device__ float g_y  [MR*CC];   // attention output
__device__ float g_fc [MR*C4];   // fc hidden

// ---------------- helpers ----------------
__device__ __forceinline__ void mma_f16(float* c, uint32_t a0, uint32_t a1,
                                        uint32_t a2, uint32_t a3,
                                        uint32_t b0, uint32_t b1) {
    asm volatile(
        "mma.sync.aligned.m16n8k16.row.col.f32.f16.f16.f32 "
        "{%0,%1,%2,%3}, {%4,%5,%6,%7}, {%8,%9}, {%0,%1,%2,%3};"
        : "+f"(c[0]), "+f"(c[1]), "+f"(c[2]), "+f"(c[3])
        : "r"(a0), "r"(a1), "r"(a2), "r"(a3), "r"(b0), "r"(b1));
}

// split two floats into packed (hi, lo) half2 pairs; elem0 = low 16 bits
__device__ __forceinline__ void split2(float a, float b, uint32_t& hi, uint32_t& lo) {
    __half ha = __float2half_rn(a), hb = __float2half_rn(b);
    float ra = a - __half2float(ha), rb = b - __half2float(hb);
    __half la = __float2half_rn(ra), lb = __float2half_rn(rb);
    hi = (uint32_t)__half_as_ushort(ha) | ((uint32_t)__half_as_ushort(hb) << 16);
    lo = (uint32_t)__half_as_ushort(la) | ((uint32_t)__half_as_ushort(lb) << 16);
}

__device__ __forceinline__ float gelu_f(float x) {
    float x3 = x * x * x;
    return 0.5f * x * (1.0f + tanhf(0.7978845608028654f * (x + 0.044715f * x3)));
}

// ---------------- embedding ----------------
__global__ void embed_kernel(const int* __restrict__ idx,
                             const float* __restrict__ wte,
                             const float* __restrict__ wpe) {
    int row = blockIdx.x;
    int t   = row % TT;
    int tok = idx[row];
    const float* we = wte + (size_t)tok * CC;
    const float* wp = wpe + (size_t)t   * CC;
    float* out = g_x + (size_t)row * CC;
    for (int i = threadIdx.x; i < CC; i += blockDim.x)
        out[i] = we[i] + wp[i];
}

// ---------------- layernorm ----------------
__global__ __launch_bounds__(256)
void ln_kernel(const float* __restrict__ x,
               const float* __restrict__ g,
               const float* __restrict__ b,
               float* __restrict__ out) {
    int row = blockIdx.x;
    const float* xr = x + (size_t)row * CC;
    float s = 0.f, s2 = 0.f;
    for (int i = threadIdx.x; i < CC; i += 256) {
        float v = xr[i];
        s += v; s2 += v * v;
    }
    for (int o = 16; o; o >>= 1) {
        s  += __shfl_xor_sync(0xffffffffu, s,  o);
        s2 += __shfl_xor_sync(0xffffffffu, s2, o);
    }
    __shared__ float sh0[8], sh1[8];
    int w = threadIdx.x >> 5, l = threadIdx.x & 31;
    if (l == 0) { sh0[w] = s; sh1[w] = s2; }
    __syncthreads();
    if (w == 0) {
        s  = (l < 8) ? sh0[l] : 0.f;
        s2 = (l < 8) ? sh1[l] : 0.f;
        for (int o = 4; o; o >>= 1) {
            s  += __shfl_xor_sync(0xffffffffu, s,  o);
            s2 += __shfl_xor_sync(0xffffffffu, s2, o);
        }
        if (l == 0) { sh0[0] = s; sh1[0] = s2; }
    }
    __syncthreads();
    float mean = sh0[0] * (1.0f / CC);
    float var  = sh1[0] * (1.0f / CC) - mean * mean;
    float rstd = rsqrtf(var + 1e-5f);
    float* orow = out + (size_t)row * CC;
    for (int i = threadIdx.x; i < CC; i += 256)
        orow[i] = (xr[i] - mean) * rstd * g[i] + b[i];
}

// ---------------- fp16-split mma.sync GEMM ----------------
// C[M,N] = epi(A[M,K] @ B[K,N]); EPI bits: 1=+bias, 2=gelu, 4=+residual
// CTA tile 128x128x32; 8 warps 2x4; warp tile 64x32; m16n8k16, 3 MMA passes (hi/lo split).
#define BM 128
#define BN 128
#define BK 32
#define PA 20    // uint32 (k-pair) row stride for sA: 16 pairs + 4 pad
#define PB 132   // uint32 row stride for sB: 128 n + 4 pad

template<int EPI>
__global__ __launch_bounds__(256, 2)
void gemm_mma(const float* __restrict__ A, const float* __restrict__ B,
              const float* __restrict__ bias, const float* __restrict__ res,
              float* __restrict__ C, int M, int N, int K) {
    __shared__ __align__(16) uint32_t sAh[BM * PA];   // [M][K/2] hi pairs
    __shared__ __align__(16) uint32_t sAl[BM * PA];   // lo
    __shared__ __align__(16) uint32_t sBh[16 * PB];   // [K/2][N] hi pairs
    __shared__ __align__(16) uint32_t sBl[16 * PB];   // lo

    const int t = threadIdx.x;
    const int wid = t >> 5, lane = t & 31;
    const int grp = lane >> 2, tig = lane & 3;
    const int warp_m = wid >> 2;          // 0..1
    const int warp_n = wid & 3;           // 0..3
    const int m0 = blockIdx.y * BM;
    const int n0 = blockIdx.x * BN;

    float acc[4][4][4];
#pragma unroll
    for (int im = 0; im < 4; im++)
#pragma unroll
        for (int in = 0; in < 4; in++)
#pragma unroll
            for (int r = 0; r < 4; r++) acc[im][in][r] = 0.f;

    const bool n4 = ((N & 3) == 0);
    const int nchunks = K / BK;

    for (int c = 0; c < nchunks; c++) {
        const int k0 = c * BK;
        // A tile: 128 rows x 32 floats -> hi/lo packed pairs
#pragma unroll
        for (int i = 0; i < 4; i++) {
            int idx = t + i * 256;                 // 0..1023
            int row = idx >> 3;                    // 0..127
            int kp  = (idx & 7) * 2;               // pair index 0..14
            float4 v = *(const float4*)(A + (size_t)(m0 + row) * K + k0 + kp * 2);
            uint32_t h0, l0, h1, l1;
            split2(v.x, v.y, h0, l0);
            split2(v.z, v.w, h1, l1);
            sAh[row * PA + kp]     = h0;
            sAh[row * PA + kp + 1] = h1;
            sAl[row * PA + kp]     = l0;
            sAl[row * PA + kp + 1] = l1;
        }
        // B tile: 32 K-rows x 128 N -> pairs (k even, k odd) per n
#pragma unroll
        for (int i = 0; i < 2; i++) {
            int idx = t + i * 256;                 // 0..511
            int kp = idx >> 5;                     // 0..15
            int ng = (idx & 31) * 4;               // n offset 0..124
            int nb = n0 + ng;
            const float* B0 = B + (size_t)(k0 + kp * 2) * N;
            const float* B1 = B0 + N;
            float4 r0, r1;
            if (n4 && nb + 3 < N) {
                r0 = *(const float4*)(B0 + nb);
                r1 = *(const float4*)(B1 + nb);
            } else {
                r0.x = (nb + 0 < N) ? B0[nb + 0] : 0.f;
                r0.y = (nb + 1 < N) ? B0[nb + 1] : 0.f;
                r0.z = (nb + 2 < N) ? B0[nb + 2] : 0.f;
                r0.w = (nb + 3 < N) ? B0[nb + 3] : 0.f;
                r1.x = (nb + 0 < N) ? B1[nb + 0] : 0.f;
                r1.y = (nb + 1 < N) ? B1[nb + 1] : 0.f;
                r1.z = (nb + 2 < N) ? B1[nb + 2] : 0.f;
                r1.w = (nb + 3 < N) ? B1[nb + 3] : 0.f;
            }
            uint32_t h, l;
            split2(r0.x, r1.x, h, l); sBh[kp * PB + ng + 0] = h; sBl[kp * PB + ng + 0] = l;
            split2(r0.y, r1.y, h, l); sBh[kp * PB + ng + 1] = h; sBl[kp * PB + ng + 1] = l;
            split2(r0.z, r1.z, h, l); sBh[kp * PB + ng + 2] = h; sBl[kp * PB + ng + 2] = l;
            split2(r0.w, r1.w, h, l); sBh[kp * PB + ng + 3] = h; sBl[kp * PB + ng + 3] = l;
        }
        __syncthreads();

#pragma unroll
        for (int ks = 0; ks < 2; ks++) {
            const int kb = ks * 8;                 // pair offset
            uint32_t ah[4][4], al[4][4];
#pragma unroll
            for (int im = 0; im < 4; im++) {
                int r0 = (warp_m * 64 + im * 16 + grp) * PA;
                int r1 = r0 + 8 * PA;
                ah[im][0] = sAh[r0 + kb + tig];
                ah[im][1] = sAh[r1 + kb + tig];
                ah[im][2] = sAh[r0 + kb + tig + 4];
                ah[im][3] = sAh[r1 + kb + tig + 4];
                al[im][0] = sAl[r0 + kb + tig];
                al[im][1] = sAl[r1 + kb + tig];
                al[im][2] = sAl[r0 + kb + tig + 4];
                al[im][3] = sAl[r1 + kb + tig + 4];
            }
            uint32_t bh[4][2], bl[4][2];
#pragma unroll
            for (int in = 0; in < 4; in++) {
                int nb = warp_n * 32 + in * 8 + grp;
                bh[in][0] = sBh[(kb + tig) * PB + nb];
                bh[in][1] = sBh[(kb + tig + 4) * PB + nb];
                bl[in][0] = sBl[(kb + tig) * PB + nb];
                bl[in][1] = sBl[(kb + tig + 4) * PB + nb];
            }
#pragma unroll
            for (int im = 0; im < 4; im++)
#pragma unroll
                for (int in = 0; in < 4; in++) {
                    mma_f16(acc[im][in], ah[im][0], ah[im][1], ah[im][2], ah[im][3],
                            bh[in][0], bh[in][1]);
                    mma_f16(acc[im][in], ah[im][0], ah[im][1], ah[im][2], ah[im][3],
                            bl[in][0], bl[in][1]);
                    mma_f16(acc[im][in], al[im][0], al[im][1], al[im][2], al[im][3],
                            bh[in][0], bh[in][1]);
                }
        }
        __syncthreads();
    }

    // ---- epilogue: regs -> global, fused bias/gelu/residual ----
    const bool n2 = ((N & 1) == 0);
#pragma unroll
    for (int im = 0; im < 4; im++) {
        int r0 = m0 + warp_m * 64 + im * 16 + grp;
        int r1 = r0 + 8;
#pragma unroll
        for (int in = 0; in < 4; in++) {
            int nc = n0 + warp_n * 32 + in * 8 + tig * 2;
            float v00 = acc[im][in][0], v01 = acc[im][in][1];
            float v10 = acc[im][in][2], v11 = acc[im][in][3];
            if (EPI & 1) {
                float b0v = (nc < N) ? bias[nc] : 0.f;
                float b1v = (nc + 1 < N) ? bias[nc + 1] : 0.f;
                v00 += b0v; v10 += b0v; v01 += b1v; v11 += b1v;
            }
            if (EPI & 2) {
                v00 = gelu_f(v00); v01 = gelu_f(v01);
                v10 = gelu_f(v10); v11 = gelu_f(v11);
            }
            if (EPI & 4) {
                if (nc < N) { v00 += res[(size_t)r0 * N + nc]; v10 += res[(size_t)r1 * N + nc]; }
                if (nc + 1 < N) { v01 += res[(size_t)r0 * N + nc + 1]; v11 += res[(size_t)r1 * N + nc + 1]; }
            }
            if (n2 && nc + 1 < N) {
                *(float2*)(C + (size_t)r0 * N + nc) = make_float2(v00, v01);
                *(float2*)(C + (size_t)r1 * N + nc) = make_float2(v10, v11);
            } else {
                if (nc < N)     { C[(size_t)r0 * N + nc]     = v00; C[(size_t)r1 * N + nc]     = v10; }
                if (nc + 1 < N) { C[(size_t)r0 * N + nc + 1] = v01; C[(size_t)r1 * N + nc + 1] = v11; }
            }
        }
    }
}

// ---------------- tiled attention (fp32, online softmax) ----------------
// block = (q-tile of 32, head, batch); 256 threads = 8 warps x 4 queries.
// lane: qi = lane>>3 (query within warp), jg = lane&7.
// K/V tiles (32 x 64 floats) in smem as float4 with XOR swizzle: slot = row*17 + (c4 ^ (row>>2)).
#define QT 32
#define JT 32

__global__ __launch_bounds__(256)
void attn_tile_kernel(const float* __restrict__ qkv, float* __restrict__ y) {
    __shared__ __align__(16) float4 sQ[QT * 17];
    __shared__ __align__(16) float4 sK[JT * 17];
    __shared__ __align__(16) float4 sV[JT * 17];
    __shared__ float sP[8][144];   // per-warp P: 4 q * 32 j, row stride 36

    const int t = threadIdx.x;
    const int warp = t >> 5, lane = t & 31;
    const int qi = lane >> 3, jg = lane & 7;
    const int h = blockIdx.y, b = blockIdx.z;
    const int qb = blockIdx.x * QT;
    const int lq = warp * 4 + qi;         // local q row 0..31
    const int q  = qb + lq;               // global q

    // load Q tile (scaled)
    {
        const float* Qb = qkv + ((size_t)(b * TT + qb)) * C3 + h * DD;
#pragma unroll
        for (int i = 0; i < 2; i++) {
            int idx = t + i * 256;         // 0..511
            int row = idx >> 4, c4 = idx & 15;
            float4 v = *(const float4*)(Qb + (size_t)row * C3 + c4 * 4);
            v.x *= 0.125f; v.y *= 0.125f; v.z *= 0.125f; v.w *= 0.125f;
            sQ[row * 17 + c4] = v;
        }
    }

    const float* Kb = qkv + (size_t)b * TT * C3 + CC     + h * DD;
    const float* Vb = qkv + (size_t)b * TT * C3 + 2 * CC + h * DD;

    float yacc[8];
#pragma unroll
    for (int i = 0; i < 8; i++) yacc[i] = 0.f;
    float mrow = -1e30f, lrow = 0.f;

    const int ntiles = blockIdx.x + 1;
    for (int jt = 0; jt < ntiles; jt++) {
        const int j0 = jt * JT;
        __syncthreads();
        // load K/V tiles, swizzled
#pragma unroll
        for (int i = 0; i < 2; i++) {
            int idx = t + i * 256;
            int row = idx >> 4, c4 = idx & 15;
            int slot = row * 17 + (c4 ^ ((row >> 2) & 7));
            sK[slot] = *(const float4*)(Kb + (size_t)(j0 + row) * C3 + c4 * 4);
            sV[slot] = *(const float4*)(Vb + (size_t)(j0 + row) * C3 + c4 * 4);
        }
        __syncthreads();

        // scores: lane computes s for (lq, j = j0 + jg*4 + ji)
        float s[4] = {0.f, 0.f, 0.f, 0.f};
#pragma unroll
        for (int dc = 0; dc < 16; dc++) {
            float4 qv = sQ[lq * 17 + dc];
#pragma unroll
            for (int ji = 0; ji < 4; ji++) {
                int jr = jg * 4 + ji;
                float4 kv = sK[jr * 17 + (dc ^ ((jr >> 2) & 7))];
                s[ji] += qv.x * kv.x + qv.y * kv.y + qv.z * kv.z + qv.w * kv.w;
            }
        }
        // causal mask
#pragma unroll
        for (int ji = 0; ji < 4; ji++) {
            int j = j0 + jg * 4 + ji;
            if (j > q) s[ji] = -1e30f;
        }
        // row max over 32 j (8 lanes share q)
        float tm = fmaxf(fmaxf(s[0], s[1]), fmaxf(s[2], s[3]));
#pragma unroll
        for (int o = 1; o < 8; o <<= 1) tm = fmaxf(tm, __shfl_xor_sync(0xffffffffu, tm, o));
        float mnew = fmaxf(mrow, tm);
        float cscale = __expf(mrow - mnew);
        float p[4], ts = 0.f;
#pragma unroll
        for (int ji = 0; ji < 4; ji++) { p[ji] = __expf(s[ji] - mnew); ts += p[ji]; }
#pragma unroll
        for (int o = 1; o < 8; o <<= 1) ts += __shfl_xor_sync(0xffffffffu, ts, o);
        lrow = lrow * cscale + ts;
        mrow = mnew;
#pragma unroll
        for (int i = 0; i < 8; i++) yacc[i] *= cscale;
        // stage P (per-warp region)
        *(float4*)&sP[warp][qi * 36 + jg * 4] = make_float4(p[0], p[1], p[2], p[3]);
        __syncwarp();
        // P @ V: lane accumulates d-slices jg*4..+3 and jg*4+32..+35
#pragma unroll 4
        for (int j = 0; j < JT; j++) {
            float pj = sP[warp][qi * 36 + j];
            int sw = (j >> 2) & 7;
            float4 v0 = sV[j * 17 + (jg ^ sw)];
            float4 v1 = sV[j * 17 + ((jg + 8) ^ sw)];
            yacc[0] += pj * v0.x; yacc[1] += pj * v0.y;
            yacc[2] += pj * v0.z; yacc[3] += pj * v0.w;
            yacc[4] += pj * v1.x; yacc[5] += pj * v1.y;
            yacc[6] += pj * v1.z; yacc[7] += pj * v1.w;
        }
    }

    float inv = 1.f / lrow;
    float* yr = y + ((size_t)(b * TT + q)) * CC + h * DD;
    *(float4*)(yr + jg * 4)      = make_float4(yacc[0] * inv, yacc[1] * inv, yacc[2] * inv, yacc[3] * inv);
    *(float4*)(yr + jg * 4 + 32) = make_float4(yacc[4] * inv, yacc[5] * inv, yacc[6] * inv, yacc[7] * inv);
}

// ---------------- host orchestration ----------------
extern "C" void kernel_launch(void* const* d_in, const int* in_sizes, int n_in,
                              void* d_out, int out_size) {
    const int*   idx   = (const int*)  d_in[0];
    const float* wte   = (const float*)d_in[1];
    const float* wpe   = (const float*)d_in[2];
    const float* ln1_g = (const float*)d_in[3];
    const float* ln1_b = (const float*)d_in[4];
    const float* wqkv  = (const float*)d_in[5];
    const float* bqkv  = (const float*)d_in[6];
    const float* wproj = (const float*)d_in[7];
    const float* bproj = (const float*)d_in[8];
    const float* ln2_g = (const float*)d_in[9];
    const float* ln2_b = (const float*)d_in[10];
    const float* wfc   = (const float*)d_in[11];
    const float* bfc   = (const float*)d_in[12];
    const float* wfc2  = (const float*)d_in[13];
    const float* bfc2  = (const float*)d_in[14];
    const float* lnf_g = (const float*)d_in[15];
    const float* lnf_b = (const float*)d_in[16];
    const float* lm_w  = (const float*)d_in[17];
    float* out = (float*)d_out;

    float *x, *lnb, *qkv, *y, *fc;
    cudaGetSymbolAddress((void**)&x,   g_x);
    cudaGetSymbolAddress((void**)&lnb, g_ln);
    cudaGetSymbolAddress((void**)&qkv, g_qkv);
    cudaGetSymbolAddress((void**)&y,   g_y);
    cudaGetSymbolAddress((void**)&fc,  g_fc);

    embed_kernel<<<MR, 256>>>(idx, wte, wpe);

    for (int l = 0; l < LL; l++) {
        ln_kernel<<<MR, 256>>>(x, ln1_g + (size_t)l * CC, ln1_b + (size_t)l * CC, lnb);

        // qkv = ln @ wqkv + bqkv   [2048 x 2304]
        gemm_mma<1><<<dim3(C3 / BN, MR / BM), 256>>>(
            lnb, wqkv + (size_t)l * CC * C3, bqkv + (size_t)l * C3, nullptr,
            qkv, MR, C3, CC);

        attn_tile_kernel<<<dim3(TT / QT, HH, BB), 256>>>(qkv, y);

        // x = x + y @ wproj + bproj
        gemm_mma<5><<<dim3(CC / BN, MR / BM), 256>>>(
            y, wproj + (size_t)l * CC * CC, bproj + (size_t)l * CC, x,
            x, MR, CC, CC);

        ln_kernel<<<MR, 256>>>(x, ln2_g + (size_t)l * CC, ln2_b + (size_t)l * CC, lnb);

        // fc = gelu(ln @ wfc + bfc)   [2048 x 3072]
        gemm_mma<3><<<dim3(C4 / BN, MR / BM), 256>>>(
            lnb, wfc + (size_t)l * CC * C4, bfc + (size_t)l * C4, nullptr,
            fc, MR, C4, CC);

        // x = x + fc @ wfc2 + bfc2
        gemm_mma<5><<<dim3(CC / BN, MR / BM), 256>>>(
            fc, wfc2 + (size_t)l * C4 * CC, bfc2 + (size_t)l * CC, x,
            x, MR, CC, C4);
    }

    ln_kernel<<<MR, 256>>>(x, lnf_g, lnf_b, lnb);

    // logits = ln @ lm_w   [2048 x 50257]
    int gn = (VV + BN - 1) / BN;
    gemm_mma<0><<<dim3(gn, MR / BM), 256>>>(
        lnb, lm_w, nullptr, nullptr, out, MR, VV, CC);
}

// round 7
// speedup vs baseline: 2.6985x; 1.3448x over previous
#include <cuda_runtime.h>
#include <cuda_fp16.h>
#include <math.h>
#include <stdint.h>

// ---------------- problem constants ----------------
#define BB   2
#define TT   1024
#define CC   768
#define HH   12
#define DD   64
#define LL   12
#define VV   50257
#define MR   2048
#define C3   2304
#define C4   3072
#define VP   50304   // VV padded to multiple of 128

// ---------------- fp32 buffers ----------------
__device__ float g_x  [MR*CC];   // residual stream
__device__ float g_qkv[MR*C3];   // qkv (attention input)

// ---------------- activation hi/lo pair planes (u32 = half2(k_even, k_odd)) ----------------
__device__ uint32_t g_lnh [MR*(CC/2)], g_lnl [MR*(CC/2)];    // LN outputs
__device__ uint32_t g_acth[MR*(C4/2)], g_actl[MR*(C4/2)];    // y (stride 384) / fc (stride 1536)

// ---------------- weight hi/lo pair planes ----------------
__device__ uint32_t g_wqkvh[LL*(CC/2)*C3], g_wqkvl[LL*(CC/2)*C3];
__device__ uint32_t g_wprjh[LL*(CC/2)*CC], g_wprjl[LL*(CC/2)*CC];
__device__ uint32_t g_wfch [LL*(CC/2)*C4], g_wfcl [LL*(CC/2)*C4];
__device__ uint32_t g_wfc2h[LL*(C4/2)*CC], g_wfc2l[LL*(C4/2)*CC];
__device__ uint32_t g_lmwh [(CC/2)*VP],    g_lmwl [(CC/2)*VP];

// ---------------- helpers ----------------
__device__ __forceinline__ uint32_t smem_u32(const void* p) {
    uint32_t a;
    asm("{ .reg .u64 t; cvta.to.shared.u64 t, %1; cvt.u32.u64 %0, t; }" : "=r"(a) : "l"(p));
    return a;
}

__device__ __forceinline__ void mma_f16(float* c, uint32_t a0, uint32_t a1,
                                        uint32_t a2, uint32_t a3,
                                        uint32_t b0, uint32_t b1) {
    asm volatile(
        "mma.sync.aligned.m16n8k16.row.col.f32.f16.f16.f32 "
        "{%0,%1,%2,%3}, {%4,%5,%6,%7}, {%8,%9}, {%0,%1,%2,%3};"
        : "+f"(c[0]), "+f"(c[1]), "+f"(c[2]), "+f"(c[3])
        : "r"(a0), "r"(a1), "r"(a2), "r"(a3), "r"(b0), "r"(b1));
}

// pack two floats into (hi, lo) half2 words; elem0 (low 16 bits) = first arg
__device__ __forceinline__ void split2(float a, float b, uint32_t& hi, uint32_t& lo) {
    __half ha = __float2half_rn(a), hb = __float2half_rn(b);
    float ra = a - __half2float(ha), rb = b - __half2float(hb);
    __half la = __float2half_rn(ra), lb = __float2half_rn(rb);
    hi = (uint32_t)__half_as_ushort(ha) | ((uint32_t)__half_as_ushort(hb) << 16);
    lo = (uint32_t)__half_as_ushort(la) | ((uint32_t)__half_as_ushort(lb) << 16);
}

__device__ __forceinline__ void cp16(uint32_t s, const void* g) {
    asm volatile("cp.async.cg.shared.global [%0], [%1], 16;" :: "r"(s), "l"(g));
}

__device__ __forceinline__ float gelu_f(float x) {
    float x3 = x * x * x;
    return 0.5f * x * (1.0f + tanhf(0.7978845608028654f * (x + 0.044715f * x3)));
}

// ---------------- weight conversion: [K][N] fp32 -> pair planes [K/2][NP] ----------------
__global__ void convert_w(const float* __restrict__ w, uint32_t* __restrict__ ph,
                          uint32_t* __restrict__ pl, int N, int NP) {
    int kp = blockIdx.y;
    int n0 = (blockIdx.x * 256 + threadIdx.x) * 4;
    if (n0 >= NP) return;
    const float* r0 = w + (size_t)(2 * kp) * N;
    const float* r1 = r0 + N;
    uint32_t h[4], l[4];
#pragma unroll
    for (int j = 0; j < 4; j++) {
        int n = n0 + j;
        float a = (n < N) ? r0[n] : 0.f;
        float b = (n < N) ? r1[n] : 0.f;
        split2(a, b, h[j], l[j]);
    }
    *(uint4*)&ph[(size_t)kp * NP + n0] = make_uint4(h[0], h[1], h[2], h[3]);
    *(uint4*)&pl[(size_t)kp * NP + n0] = make_uint4(l[0], l[1], l[2], l[3]);
}

// ---------------- embedding ----------------
__global__ void embed_kernel(const int* __restrict__ idx,
                             const float* __restrict__ wte,
                             const float* __restrict__ wpe) {
    int row = blockIdx.x;
    int t   = row % TT;
    int tok = idx[row];
    const float* we = wte + (size_t)tok * CC;
    const float* wp = wpe + (size_t)t   * CC;
    float* out = g_x + (size_t)row * CC;
    for (int i = threadIdx.x; i < CC; i += blockDim.x)
        out[i] = we[i] + wp[i];
}

// ---------------- layernorm -> pair planes ----------------
__global__ __launch_bounds__(256)
void ln_kernel(const float* __restrict__ x,
               const float* __restrict__ g,
               const float* __restrict__ b,
               uint32_t* __restrict__ outh, uint32_t* __restrict__ outl) {
    int row = blockIdx.x;
    const float* xr = x + (size_t)row * CC;
    float s = 0.f, s2 = 0.f;
    for (int i = threadIdx.x; i < CC; i += 256) {
        float v = xr[i];
        s += v; s2 += v * v;
    }
    for (int o = 16; o; o >>= 1) {
        s  += __shfl_xor_sync(0xffffffffu, s,  o);
        s2 += __shfl_xor_sync(0xffffffffu, s2, o);
    }
    __shared__ float sh0[8], sh1[8];
    int w = threadIdx.x >> 5, l = threadIdx.x & 31;
    if (l == 0) { sh0[w] = s; sh1[w] = s2; }
    __syncthreads();
    if (w == 0) {
        s  = (l < 8) ? sh0[l] : 0.f;
        s2 = (l < 8) ? sh1[l] : 0.f;
        for (int o = 4; o; o >>= 1) {
            s  += __shfl_xor_sync(0xffffffffu, s,  o);
            s2 += __shfl_xor_sync(0xffffffffu, s2, o);
        }
        if (l == 0) { sh0[0] = s; sh1[0] = s2; }
    }
    __syncthreads();
    float mean = sh0[0] * (1.0f / CC);
    float var  = sh1[0] * (1.0f / CC) - mean * mean;
    float rstd = rsqrtf(var + 1e-5f);
    for (int i = threadIdx.x; i < CC / 2; i += 256) {
        float a = (xr[2 * i]     - mean) * rstd * g[2 * i]     + b[2 * i];
        float c = (xr[2 * i + 1] - mean) * rstd * g[2 * i + 1] + b[2 * i + 1];
        uint32_t ph, pl;
        split2(a, c, ph, pl);
        outh[(size_t)row * (CC / 2) + i] = ph;
        outl[(size_t)row * (CC / 2) + i] = pl;
    }
}

// ---------------- fp16-split mma GEMM with cp.async double-buffer ----------------
// EPI bits: 1=+bias, 2=gelu, 4=+residual.  OUTM: 0 = fp32 C, 1 = pair planes Ch/Cl.
#define PA 20      // u32 row stride of A tile (16 pairs + 4 pad)
#define PB 136     // u32 row stride of B tile (128 + 8 pad, conflict-free)
#define STG 9472   // u32 per stage: 2*128*20 + 2*16*136
#define OFF_AL 2560
#define OFF_BH 5120
#define OFF_BL 7296
#define GSMEM (2 * STG * 4)   // 75776 bytes

template<int EPI, int OUTM>
__global__ __launch_bounds__(256, 2)
void gemm_mma(const uint32_t* __restrict__ Ah, const uint32_t* __restrict__ Al, int KH,
              const uint32_t* __restrict__ Bh, const uint32_t* __restrict__ Bl, int NP,
              const float* __restrict__ bias, const float* __restrict__ res,
              float* __restrict__ C, uint32_t* __restrict__ Ch, uint32_t* __restrict__ Cl,
              int N) {
    extern __shared__ __align__(16) uint32_t sm[];
    const int t = threadIdx.x;
    const int wid = t >> 5, lane = t & 31;
    const int grp = lane >> 2, tig = lane & 3;
    const int warp_m = wid >> 2;          // 0..1
    const int warp_n = wid & 3;           // 0..3
    const int m0 = blockIdx.x * 128;
    const int n0 = blockIdx.y * 128;
    const uint32_t sb = smem_u32(sm);

    float acc[4][4][4];
#pragma unroll
    for (int im = 0; im < 4; im++)
#pragma unroll
        for (int in = 0; in < 4; in++)
#pragma unroll
            for (int r = 0; r < 4; r++) acc[im][in][r] = 0.f;

    const int nch = KH / 16;

    auto prefetch = [&](int c, int st) {
        uint32_t base = sb + (uint32_t)st * STG * 4;
        int k0 = c * 16;
#pragma unroll
        for (int i = 0; i < 2; i++) {
            int idx = t + i * 256;
            int row = idx >> 2, ch = (idx & 3) * 4;
            size_t go = (size_t)(m0 + row) * KH + k0 + ch;
            cp16(base + (row * PA + ch) * 4, Ah + go);
            cp16(base + (OFF_AL + row * PA + ch) * 4, Al + go);
        }
#pragma unroll
        for (int i = 0; i < 2; i++) {
            int idx = t + i * 256;
            int kp = idx >> 5, ch = (idx & 31) * 4;
            size_t go = (size_t)(k0 + kp) * NP + n0 + ch;
            cp16(base + (OFF_BH + kp * PB + ch) * 4, Bh + go);
            cp16(base + (OFF_BL + kp * PB + ch) * 4, Bl + go);
        }
        asm volatile("cp.async.commit_group;" ::: "memory");
    };

    prefetch(0, 0);
    for (int c = 0; c < nch; c++) {
        if (c + 1 < nch) {
            prefetch(c + 1, (c + 1) & 1);
            asm volatile("cp.async.wait_group 1;" ::: "memory");
        } else {
            asm volatile("cp.async.wait_group 0;" ::: "memory");
        }
        __syncthreads();
        const uint32_t* S = sm + (c & 1) * STG;
#pragma unroll
        for (int ks = 0; ks < 2; ks++) {
            const int kb = ks * 8;
            uint32_t ah[4][4], al[4][4];
#pragma unroll
            for (int im = 0; im < 4; im++) {
                int r0 = (warp_m * 64 + im * 16 + grp) * PA;
                int r1 = r0 + 8 * PA;
                ah[im][0] = S[r0 + kb + tig];
                ah[im][1] = S[r1 + kb + tig];
                ah[im][2] = S[r0 + kb + tig + 4];
                ah[im][3] = S[r1 + kb + tig + 4];
                al[im][0] = S[OFF_AL + r0 + kb + tig];
                al[im][1] = S[OFF_AL + r1 + kb + tig];
                al[im][2] = S[OFF_AL + r0 + kb + tig + 4];
                al[im][3] = S[OFF_AL + r1 + kb + tig + 4];
            }
            uint32_t bh[4][2], bl[4][2];
#pragma unroll
            for (int in = 0; in < 4; in++) {
                int nb = warp_n * 32 + in * 8 + grp;
                bh[in][0] = S[OFF_BH + (kb + tig) * PB + nb];
                bh[in][1] = S[OFF_BH + (kb + tig + 4) * PB + nb];
                bl[in][0] = S[OFF_BL + (kb + tig) * PB + nb];
                bl[in][1] = S[OFF_BL + (kb + tig + 4) * PB + nb];
            }
#pragma unroll
            for (int im = 0; im < 4; im++)
#pragma unroll
                for (int in = 0; in < 4; in++) {
                    mma_f16(acc[im][in], ah[im][0], ah[im][1], ah[im][2], ah[im][3],
                            bh[in][0], bh[in][1]);
                    mma_f16(acc[im][in], ah[im][0], ah[im][1], ah[im][2], ah[im][3],
                            bl[in][0], bl[in][1]);
                    mma_f16(acc[im][in], al[im][0], al[im][1], al[im][2], al[im][3],
                            bh[in][0], bh[in][1]);
                }
        }
        __syncthreads();
    }

    // ---- epilogue ----
    const bool n2 = ((N & 1) == 0);   // float2 stores only when every row keeps 8B alignment
#pragma unroll
    for (int im = 0; im < 4; im++) {
        int r0 = m0 + warp_m * 64 + im * 16 + grp;
        int r1 = r0 + 8;
#pragma unroll
        for (int in = 0; in < 4; in++) {
            int nc = n0 + warp_n * 32 + in * 8 + tig * 2;
            float v00 = acc[im][in][0], v01 = acc[im][in][1];
            float v10 = acc[im][in][2], v11 = acc[im][in][3];
            if (EPI & 1) {
                float b0v = (nc < N) ? bias[nc] : 0.f;
                float b1v = (nc + 1 < N) ? bias[nc + 1] : 0.f;
                v00 += b0v; v10 += b0v; v01 += b1v; v11 += b1v;
            }
            if (EPI & 2) {
                v00 = gelu_f(v00); v01 = gelu_f(v01);
                v10 = gelu_f(v10); v11 = gelu_f(v11);
            }
            if (EPI & 4) {
                if (nc < N) { v00 += res[(size_t)r0 * N + nc]; v10 += res[(size_t)r1 * N + nc]; }
                if (nc + 1 < N) { v01 += res[(size_t)r0 * N + nc + 1]; v11 += res[(size_t)r1 * N + nc + 1]; }
            }
            if (OUTM == 1) {
                uint32_t ph, pl;
                split2(v00, v01, ph, pl);
                Ch[(size_t)r0 * (N / 2) + nc / 2] = ph;
                Cl[(size_t)r0 * (N / 2) + nc / 2] = pl;
                split2(v10, v11, ph, pl);
                Ch[(size_t)r1 * (N / 2) + nc / 2] = ph;
                Cl[(size_t)r1 * (N / 2) + nc / 2] = pl;
            } else {
                if (n2 && nc + 1 < N) {
                    *(float2*)(C + (size_t)r0 * N + nc) = make_float2(v00, v01);
                    *(float2*)(C + (size_t)r1 * N + nc) = make_float2(v10, v11);
                } else {
                    if (nc < N)     { C[(size_t)r0 * N + nc]     = v00; C[(size_t)r1 * N + nc]     = v10; }
                    if (nc + 1 < N) { C[(size_t)r0 * N + nc + 1] = v01; C[(size_t)r1 * N + nc + 1] = v11; }
                }
            }
        }
    }
}

// ---------------- tiled attention (fp32, online softmax), writes y pair planes ----------------
#define QT 32
#define JT 32

__global__ __launch_bounds__(256)
void attn_tile_kernel(const float* __restrict__ qkv,
                      uint32_t* __restrict__ yh, uint32_t* __restrict__ yl) {
    __shared__ __align__(16) float4 sQ[QT * 17];
    __shared__ __align__(16) float4 sK[JT * 17];
    __shared__ __align__(16) float4 sV[JT * 17];
    __shared__ float sP[8][144];

    const int t = threadIdx.x;
    const int warp = t >> 5, lane = t & 31;
    const int qi = lane >> 3, jg = lane & 7;
    const int hd = blockIdx.y, b = blockIdx.z;
    const int qblk = gridDim.x - 1 - blockIdx.x;   // long blocks first
    const int qb = qblk * QT;
    const int lq = warp * 4 + qi;
    const int q  = qb + lq;

    {
        const float* Qb = qkv + ((size_t)(b * TT + qb)) * C3 + hd * DD;
#pragma unroll
        for (int i = 0; i < 2; i++) {
            int idx = t + i * 256;
            int row = idx >> 4, c4 = idx & 15;
            float4 v = *(const float4*)(Qb + (size_t)row * C3 + c4 * 4);
            v.x *= 0.125f; v.y *= 0.125f; v.z *= 0.125f; v.w *= 0.125f;
            sQ[row * 17 + c4] = v;
        }
    }

    const float* Kb = qkv + (size_t)b * TT * C3 + CC     + hd * DD;
    const float* Vb = qkv + (size_t)b * TT * C3 + 2 * CC + hd * DD;

    float yacc[8];
#pragma unroll
    for (int i = 0; i < 8; i++) yacc[i] = 0.f;
    float mrow = -1e30f, lrow = 0.f;

    const int ntiles = qblk + 1;
    for (int jt = 0; jt < ntiles; jt++) {
        const int j0 = jt * JT;
        __syncthreads();
#pragma unroll
        for (int i = 0; i < 2; i++) {
            int idx = t + i * 256;
            int row = idx >> 4, c4 = idx & 15;
            int slot = row * 17 + (c4 ^ ((row >> 2) & 7));
            sK[slot] = *(const float4*)(Kb + (size_t)(j0 + row) * C3 + c4 * 4);
            sV[slot] = *(const float4*)(Vb + (size_t)(j0 + row) * C3 + c4 * 4);
        }
        __syncthreads();

        float s[4] = {0.f, 0.f, 0.f, 0.f};
#pragma unroll
        for (int dc = 0; dc < 16; dc++) {
            float4 qv = sQ[lq * 17 + dc];
#pragma unroll
            for (int ji = 0; ji < 4; ji++) {
                int jr = jg * 4 + ji;
                float4 kv = sK[jr * 17 + (dc ^ ((jr >> 2) & 7))];
                s[ji] += qv.x * kv.x + qv.y * kv.y + qv.z * kv.z + qv.w * kv.w;
            }
        }
#pragma unroll
        for (int ji = 0; ji < 4; ji++) {
            int j = j0 + jg * 4 + ji;
            if (j > q) s[ji] = -1e30f;
        }
        float tm = fmaxf(fmaxf(s[0], s[1]), fmaxf(s[2], s[3]));
#pragma unroll
        for (int o = 1; o < 8; o <<= 1) tm = fmaxf(tm, __shfl_xor_sync(0xffffffffu, tm, o));
        float mnew = fmaxf(mrow, tm);
        float cscale = __expf(mrow - mnew);
        float p[4], ts = 0.f;
#pragma unroll
        for (int ji = 0; ji < 4; ji++) { p[ji] = __expf(s[ji] - mnew); ts += p[ji]; }
#pragma unroll
        for (int o = 1; o < 8; o <<= 1) ts += __shfl_xor_sync(0xffffffffu, ts, o);
        lrow = lrow * cscale + ts;
        mrow = mnew;
#pragma unroll
        for (int i = 0; i < 8; i++) yacc[i] *= cscale;
        *(float4*)&sP[warp][qi * 36 + jg * 4] = make_float4(p[0], p[1], p[2], p[3]);
        __syncwarp();
#pragma unroll 4
        for (int j = 0; j < JT; j++) {
            float pj = sP[warp][qi * 36 + j];
            int sw = (j >> 2) & 7;
            float4 v0 = sV[j * 17 + (jg ^ sw)];
            float4 v1 = sV[j * 17 + ((jg + 8) ^ sw)];
            yacc[0] += pj * v0.x; yacc[1] += pj * v0.y;
            yacc[2] += pj * v0.z; yacc[3] += pj * v0.w;
            yacc[4] += pj * v1.x; yacc[5] += pj * v1.y;
            yacc[6] += pj * v1.z; yacc[7] += pj * v1.w;
        }
    }

    float inv = 1.f / lrow;
    size_t r = (size_t)(b * TT + q) * (CC / 2);
    int pc = hd * 32 + jg * 2;
    uint32_t ph, pl;
    split2(yacc[0] * inv, yacc[1] * inv, ph, pl);
    yh[r + pc] = ph; yl[r + pc] = pl;
    split2(yacc[2] * inv, yacc[3] * inv, ph, pl);
    yh[r + pc + 1] = ph; yl[r + pc + 1] = pl;
    split2(yacc[4] * inv, yacc[5] * inv, ph, pl);
    yh[r + pc + 16] = ph; yl[r + pc + 16] = pl;
    split2(yacc[6] * inv, yacc[7] * inv, ph, pl);
    yh[r + pc + 17] = ph; yl[r + pc + 17] = pl;
}

// ---------------- host orchestration ----------------
extern "C" void kernel_launch(void* const* d_in, const int* in_sizes, int n_in,
                              void* d_out, int out_size) {
    const int*   idx   = (const int*)  d_in[0];
    const float* wte   = (const float*)d_in[1];
    const float* wpe   = (const float*)d_in[2];
    const float* ln1_g = (const float*)d_in[3];
    const float* ln1_b = (const float*)d_in[4];
    const float* wqkv  = (const float*)d_in[5];
    const float* bqkv  = (const float*)d_in[6];
    const float* wproj = (const float*)d_in[7];
    const float* bproj = (const float*)d_in[8];
    const float* ln2_g = (const float*)d_in[9];
    const float* ln2_b = (const float*)d_in[10];
    const float* wfc   = (const float*)d_in[11];
    const float* bfc   = (const float*)d_in[12];
    const float* wfc2  = (const float*)d_in[13];
    const float* bfc2  = (const float*)d_in[14];
    const float* lnf_g = (const float*)d_in[15];
    const float* lnf_b = (const float*)d_in[16];
    const float* lm_w  = (const float*)d_in[17];
    float* out = (float*)d_out;

    float *x, *qkv;
    uint32_t *lnh, *lnl, *acth, *actl;
    uint32_t *wqh, *wql, *wph, *wpl, *wfh, *wfl, *w2h, *w2l, *lmh, *lml;
    cudaGetSymbolAddress((void**)&x,    g_x);
    cudaGetSymbolAddress((void**)&qkv,  g_qkv);
    cudaGetSymbolAddress((void**)&lnh,  g_lnh);
    cudaGetSymbolAddress((void**)&lnl,  g_lnl);
    cudaGetSymbolAddress((void**)&acth, g_acth);
    cudaGetSymbolAddress((void**)&actl, g_actl);
    cudaGetSymbolAddress((void**)&wqh,  g_wqkvh);
    cudaGetSymbolAddress((void**)&wql,  g_wqkvl);
    cudaGetSymbolAddress((void**)&wph,  g_wprjh);
    cudaGetSymbolAddress((void**)&wpl,  g_wprjl);
    cudaGetSymbolAddress((void**)&wfh,  g_wfch);
    cudaGetSymbolAddress((void**)&wfl,  g_wfcl);
    cudaGetSymbolAddress((void**)&w2h,  g_wfc2h);
    cudaGetSymbolAddress((void**)&w2l,  g_wfc2l);
    cudaGetSymbolAddress((void**)&lmh,  g_lmwh);
    cudaGetSymbolAddress((void**)&lml,  g_lmwl);

    cudaFuncSetAttribute(gemm_mma<1, 0>, cudaFuncAttributeMaxDynamicSharedMemorySize, GSMEM);
    cudaFuncSetAttribute(gemm_mma<5, 0>, cudaFuncAttributeMaxDynamicSharedMemorySize, GSMEM);
    cudaFuncSetAttribute(gemm_mma<3, 1>, cudaFuncAttributeMaxDynamicSharedMemorySize, GSMEM);
    cudaFuncSetAttribute(gemm_mma<0, 0>, cudaFuncAttributeMaxDynamicSharedMemorySize, GSMEM);

    // ---- weight conversions (once per call) ----
    convert_w<<<dim3((C3 + 1023) / 1024, LL * CC / 2), 256>>>(wqkv,  wqh, wql, C3, C3);
    convert_w<<<dim3((CC + 1023) / 1024, LL * CC / 2), 256>>>(wproj, wph, wpl, CC, CC);
    convert_w<<<dim3((C4 + 1023) / 1024, LL * CC / 2), 256>>>(wfc,   wfh, wfl, C4, C4);
    convert_w<<<dim3((CC + 1023) / 1024, LL * C4 / 2), 256>>>(wfc2,  w2h, w2l, CC, CC);
    convert_w<<<dim3((VP + 1023) / 1024, CC / 2),      256>>>(lm_w,  lmh, lml, VV, VP);

    embed_kernel<<<MR, 256>>>(idx, wte, wpe);

    for (int l = 0; l < LL; l++) {
        ln_kernel<<<MR, 256>>>(x, ln1_g + (size_t)l * CC, ln1_b + (size_t)l * CC, lnh, lnl);

        // qkv = ln @ wqkv + bqkv  [2048 x 2304], fp32 out
        gemm_mma<1, 0><<<dim3(16, C3 / 128), 256, GSMEM>>>(
            lnh, lnl, CC / 2,
            wqh + (size_t)l * (CC / 2) * C3, wql + (size_t)l * (CC / 2) * C3, C3,
            bqkv + (size_t)l * C3, nullptr, qkv, nullptr, nullptr, C3);

        attn_tile_kernel<<<dim3(TT / QT, HH, BB), 256>>>(qkv, acth, actl);

        // x = x + y @ wproj + bproj  (A = y planes, stride 384)
        gemm_mma<5, 0><<<dim3(16, CC / 128), 256, GSMEM>>>(
            acth, actl, CC / 2,
            wph + (size_t)l * (CC / 2) * CC, wpl + (size_t)l * (CC / 2) * CC, CC,
            bproj + (size_t)l * CC, x, x, nullptr, nullptr, CC);

        ln_kernel<<<MR, 256>>>(x, ln2_g + (size_t)l * CC, ln2_b + (size_t)l * CC, lnh, lnl);

        // fc = gelu(ln @ wfc + bfc), pair-plane out (stride 1536)
        gemm_mma<3, 1><<<dim3(16, C4 / 128), 256, GSMEM>>>(
            lnh, lnl, CC / 2,
            wfh + (size_t)l * (CC / 2) * C4, wfl + (size_t)l * (CC / 2) * C4, C4,
            bfc + (size_t)l * C4, nullptr, nullptr, acth, actl, C4);

        // x = x + fc @ wfc2 + bfc2  (A = fc planes, stride 1536)
        gemm_mma<5, 0><<<dim3(16, CC / 128), 256, GSMEM>>>(
            acth, actl, C4 / 2,
            w2h + (size_t)l * (C4 / 2) * CC, w2l + (size_t)l * (C4 / 2) * CC, CC,
            bfc2 + (size_t)l * CC, x, x, nullptr, nullptr, CC);
    }

    ln_kernel<<<MR, 256>>>(x, lnf_g, lnf_b, lnh, lnl);

    // logits = ln @ lm_w  [2048 x 50257]
    gemm_mma<0, 0><<<dim3(16, VP / 128), 256, GSMEM>>>(
        lnh, lnl, CC / 2, lmh, lml, VP,
        nullptr, nullptr, out, nullptr, nullptr, VV);
}

// round 10
// speedup vs baseline: 3.7530x; 1.3908x over previous
#include <cuda_runtime.h>
#include <cuda_fp16.h>
#include <math.h>
#include <stdint.h>

// ---------------- problem constants ----------------
#define BB   2
#define TT   1024
#define CC   768
#define HH   12
#define DD   64
#define LL   12
#define VV   50257
#define MR   2048
#define C3   2304
#define C4   3072
#define VP   50304   // VV padded to multiple of 128

// ---------------- fp32 buffers ----------------
__device__ float g_x  [MR*CC];   // residual stream
__device__ float g_qkv[MR*C3];   // qkv (attention input)

// ---------------- activation hi/lo pair planes (u32 = half2(k_even, k_odd)) ----------------
__device__ uint32_t g_lnh [MR*(CC/2)], g_lnl [MR*(CC/2)];    // LN outputs
__device__ uint32_t g_acth[MR*(C4/2)], g_actl[MR*(C4/2)];    // y (stride 384) / fc (stride 1536)

// ---------------- weight hi/lo pair planes ----------------
__device__ uint32_t g_wqkvh[LL*(CC/2)*C3], g_wqkvl[LL*(CC/2)*C3];
__device__ uint32_t g_wprjh[LL*(CC/2)*CC], g_wprjl[LL*(CC/2)*CC];
__device__ uint32_t g_wfch [LL*(CC/2)*C4], g_wfcl [LL*(CC/2)*C4];
__device__ uint32_t g_wfc2h[LL*(C4/2)*CC], g_wfc2l[LL*(C4/2)*CC];
__device__ uint32_t g_lmwh [(CC/2)*VP],    g_lmwl [(CC/2)*VP];

// ---------------- helpers ----------------
__device__ __forceinline__ uint32_t smem_u32(const void* p) {
    uint32_t a;
    asm("{ .reg .u64 t; cvta.to.shared.u64 t, %1; cvt.u32.u64 %0, t; }" : "=r"(a) : "l"(p));
    return a;
}

__device__ __forceinline__ void mma_f16(float* c, uint32_t a0, uint32_t a1,
                                        uint32_t a2, uint32_t a3,
                                        uint32_t b0, uint32_t b1) {
    asm volatile(
        "mma.sync.aligned.m16n8k16.row.col.f32.f16.f16.f32 "
        "{%0,%1,%2,%3}, {%4,%5,%6,%7}, {%8,%9}, {%0,%1,%2,%3};"
        : "+f"(c[0]), "+f"(c[1]), "+f"(c[2]), "+f"(c[3])
        : "r"(a0), "r"(a1), "r"(a2), "r"(a3), "r"(b0), "r"(b1));
}

// pack two floats into (hi, lo) half2 words; elem0 (low 16 bits) = first arg
__device__ __forceinline__ void split2(float a, float b, uint32_t& hi, uint32_t& lo) {
    __half ha = __float2half_rn(a), hb = __float2half_rn(b);
    float ra = a - __half2float(ha), rb = b - __half2float(hb);
    __half la = __float2half_rn(ra), lb = __float2half_rn(rb);
    hi = (uint32_t)__half_as_ushort(ha) | ((uint32_t)__half_as_ushort(hb) << 16);
    lo = (uint32_t)__half_as_ushort(la) | ((uint32_t)__half_as_ushort(lb) << 16);
}

__device__ __forceinline__ void cp16(uint32_t s, const void* g) {
    asm volatile("cp.async.cg.shared.global [%0], [%1], 16;" :: "r"(s), "l"(g));
}

__device__ __forceinline__ float gelu_f(float x) {
    float x3 = x * x * x;
    return 0.5f * x * (1.0f + tanhf(0.7978845608028654f * (x + 0.044715f * x3)));
}

// ---------------- weight conversion: [K][N] fp32 -> pair planes [K/2][NP] ----------------
__global__ void convert_w(const float* __restrict__ w, uint32_t* __restrict__ ph,
                          uint32_t* __restrict__ pl, int N, int NP) {
    int kp = blockIdx.y;
    int n0 = (blockIdx.x * 256 + threadIdx.x) * 4;
    if (n0 >= NP) return;
    const float* r0 = w + (size_t)(2 * kp) * N;
    const float* r1 = r0 + N;
    uint32_t h[4], l[4];
#pragma unroll
    for (int j = 0; j < 4; j++) {
        int n = n0 + j;
        float a = (n < N) ? r0[n] : 0.f;
        float b = (n < N) ? r1[n] : 0.f;
        split2(a, b, h[j], l[j]);
    }
    *(uint4*)&ph[(size_t)kp * NP + n0] = make_uint4(h[0], h[1], h[2], h[3]);
    *(uint4*)&pl[(size_t)kp * NP + n0] = make_uint4(l[0], l[1], l[2], l[3]);
}

// ---------------- embedding ----------------
__global__ void embed_kernel(const int* __restrict__ idx,
                             const float* __restrict__ wte,
                             const float* __restrict__ wpe) {
    int row = blockIdx.x;
    int t   = row % TT;
    int tok = idx[row];
    const float* we = wte + (size_t)tok * CC;
    const float* wp = wpe + (size_t)t   * CC;
    float* out = g_x + (size_t)row * CC;
    for (int i = threadIdx.x; i < CC; i += blockDim.x)
        out[i] = we[i] + wp[i];
}

// ---------------- layernorm -> pair planes ----------------
__global__ __launch_bounds__(256)
void ln_kernel(const float* __restrict__ x,
               const float* __restrict__ g,
               const float* __restrict__ b,
               uint32_t* __restrict__ outh, uint32_t* __restrict__ outl) {
    int row = blockIdx.x;
    const float* xr = x + (size_t)row * CC;
    float s = 0.f, s2 = 0.f;
    for (int i = threadIdx.x; i < CC; i += 256) {
        float v = xr[i];
        s += v; s2 += v * v;
    }
    for (int o = 16; o; o >>= 1) {
        s  += __shfl_xor_sync(0xffffffffu, s,  o);
        s2 += __shfl_xor_sync(0xffffffffu, s2, o);
    }
    __shared__ float sh0[8], sh1[8];
    int w = threadIdx.x >> 5, l = threadIdx.x & 31;
    if (l == 0) { sh0[w] = s; sh1[w] = s2; }
    __syncthreads();
    if (w == 0) {
        s  = (l < 8) ? sh0[l] : 0.f;
        s2 = (l < 8) ? sh1[l] : 0.f;
        for (int o = 4; o; o >>= 1) {
            s  += __shfl_xor_sync(0xffffffffu, s,  o);
            s2 += __shfl_xor_sync(0xffffffffu, s2, o);
        }
        if (l == 0) { sh0[0] = s; sh1[0] = s2; }
    }
    __syncthreads();
    float mean = sh0[0] * (1.0f / CC);
    float var  = sh1[0] * (1.0f / CC) - mean * mean;
    float rstd = rsqrtf(var + 1e-5f);
    for (int i = threadIdx.x; i < CC / 2; i += 256) {
        float a = (xr[2 * i]     - mean) * rstd * g[2 * i]     + b[2 * i];
        float c = (xr[2 * i + 1] - mean) * rstd * g[2 * i + 1] + b[2 * i + 1];
        uint32_t ph, pl;
        split2(a, c, ph, pl);
        outh[(size_t)row * (CC / 2) + i] = ph;
        outl[(size_t)row * (CC / 2) + i] = pl;
    }
}

// ---------------- fp16-split mma GEMM with cp.async double-buffer ----------------
// EPI bits: 1=+bias, 2=gelu, 4=+residual.  OUTM: 0 = fp32 C, 1 = pair planes Ch/Cl.
#define PA 20      // u32 row stride of A tile (16 pairs + 4 pad)
#define PB 136     // u32 row stride of B tile (128 + 8 pad, conflict-free)
#define STG 9472   // u32 per stage: 2*128*20 + 2*16*136
#define OFF_AL 2560
#define OFF_BH 5120
#define OFF_BL 7296
#define GSMEM (2 * STG * 4)   // 75776 bytes

template<int EPI, int OUTM>
__global__ __launch_bounds__(256, 2)
void gemm_mma(const uint32_t* __restrict__ Ah, const uint32_t* __restrict__ Al, int KH,
              const uint32_t* __restrict__ Bh, const uint32_t* __restrict__ Bl, int NP,
              const float* __restrict__ bias, const float* __restrict__ res,
              float* __restrict__ C, uint32_t* __restrict__ Ch, uint32_t* __restrict__ Cl,
              int N) {
    extern __shared__ __align__(16) uint32_t sm[];
    const int t = threadIdx.x;
    const int wid = t >> 5, lane = t & 31;
    const int grp = lane >> 2, tig = lane & 3;
    const int warp_m = wid >> 2;          // 0..1
    const int warp_n = wid & 3;           // 0..3
    const int m0 = blockIdx.x * 128;
    const int n0 = blockIdx.y * 128;
    const uint32_t sb = smem_u32(sm);

    float acc[4][4][4];
#pragma unroll
    for (int im = 0; im < 4; im++)
#pragma unroll
        for (int in = 0; in < 4; in++)
#pragma unroll
            for (int r = 0; r < 4; r++) acc[im][in][r] = 0.f;

    const int nch = KH / 16;

    auto prefetch = [&](int c, int st) {
        uint32_t base = sb + (uint32_t)st * STG * 4;
        int k0 = c * 16;
#pragma unroll
        for (int i = 0; i < 2; i++) {
            int idx = t + i * 256;
            int row = idx >> 2, ch = (idx & 3) * 4;
            size_t go = (size_t)(m0 + row) * KH + k0 + ch;
            cp16(base + (row * PA + ch) * 4, Ah + go);
            cp16(base + (OFF_AL + row * PA + ch) * 4, Al + go);
        }
#pragma unroll
        for (int i = 0; i < 2; i++) {
            int idx = t + i * 256;
            int kp = idx >> 5, ch = (idx & 31) * 4;
            size_t go = (size_t)(k0 + kp) * NP + n0 + ch;
            cp16(base + (OFF_BH + kp * PB + ch) * 4, Bh + go);
            cp16(base + (OFF_BL + kp * PB + ch) * 4, Bl + go);
        }
        asm volatile("cp.async.commit_group;" ::: "memory");
    };

    prefetch(0, 0);
    for (int c = 0; c < nch; c++) {
        if (c + 1 < nch) {
            prefetch(c + 1, (c + 1) & 1);
            asm volatile("cp.async.wait_group 1;" ::: "memory");
        } else {
            asm volatile("cp.async.wait_group 0;" ::: "memory");
        }
        __syncthreads();
        const uint32_t* S = sm + (c & 1) * STG;
#pragma unroll
        for (int ks = 0; ks < 2; ks++) {
            const int kb = ks * 8;
            uint32_t ah[4][4], al[4][4];
#pragma unroll
            for (int im = 0; im < 4; im++) {
                int r0 = (warp_m * 64 + im * 16 + grp) * PA;
                int r1 = r0 + 8 * PA;
                ah[im][0] = S[r0 + kb + tig];
                ah[im][1] = S[r1 + kb + tig];
                ah[im][2] = S[r0 + kb + tig + 4];
                ah[im][3] = S[r1 + kb + tig + 4];
                al[im][0] = S[OFF_AL + r0 + kb + tig];
                al[im][1] = S[OFF_AL + r1 + kb + tig];
                al[im][2] = S[OFF_AL + r0 + kb + tig + 4];
                al[im][3] = S[OFF_AL + r1 + kb + tig + 4];
            }
            uint32_t bh[4][2], bl[4][2];
#pragma unroll
            for (int in = 0; in < 4; in++) {
                int nb = warp_n * 32 + in * 8 + grp;
                bh[in][0] = S[OFF_BH + (kb + tig) * PB + nb];
                bh[in][1] = S[OFF_BH + (kb + tig + 4) * PB + nb];
                bl[in][0] = S[OFF_BL + (kb + tig) * PB + nb];
                bl[in][1] = S[OFF_BL + (kb + tig + 4) * PB + nb];
            }
#pragma unroll
            for (int im = 0; im < 4; im++)
#pragma unroll
                for (int in = 0; in < 4; in++) {
                    mma_f16(acc[im][in], ah[im][0], ah[im][1], ah[im][2], ah[im][3],
                            bh[in][0], bh[in][1]);
                    mma_f16(acc[im][in], ah[im][0], ah[im][1], ah[im][2], ah[im][3],
                            bl[in][0], bl[in][1]);
                    mma_f16(acc[im][in], al[im][0], al[im][1], al[im][2], al[im][3],
                            bh[in][0], bh[in][1]);
                }
        }
        __syncthreads();
    }

    // ---- epilogue ----
    const bool n2 = ((N & 1) == 0);   // float2 stores only when every row keeps 8B alignment
#pragma unroll
    for (int im = 0; im < 4; im++) {
        int r0 = m0 + warp_m * 64 + im * 16 + grp;
        int r1 = r0 + 8;
#pragma unroll
        for (int in = 0; in < 4; in++) {
            int nc = n0 + warp_n * 32 + in * 8 + tig * 2;
            float v00 = acc[im][in][0], v01 = acc[im][in][1];
            float v10 = acc[im][in][2], v11 = acc[im][in][3];
            if (EPI & 1) {
                float b0v = (nc < N) ? bias[nc] : 0.f;
                float b1v = (nc + 1 < N) ? bias[nc + 1] : 0.f;
                v00 += b0v; v10 += b0v; v01 += b1v; v11 += b1v;
            }
            if (EPI & 2) {
                v00 = gelu_f(v00); v01 = gelu_f(v01);
                v10 = gelu_f(v10); v11 = gelu_f(v11);
            }
            if (EPI & 4) {
                if (nc < N) { v00 += res[(size_t)r0 * N + nc]; v10 += res[(size_t)r1 * N + nc]; }
                if (nc + 1 < N) { v01 += res[(size_t)r0 * N + nc + 1]; v11 += res[(size_t)r1 * N + nc + 1]; }
            }
            if (OUTM == 1) {
                uint32_t ph, pl;
                split2(v00, v01, ph, pl);
                Ch[(size_t)r0 * (N / 2) + nc / 2] = ph;
                Cl[(size_t)r0 * (N / 2) + nc / 2] = pl;
                split2(v10, v11, ph, pl);
                Ch[(size_t)r1 * (N / 2) + nc / 2] = ph;
                Cl[(size_t)r1 * (N / 2) + nc / 2] = pl;
            } else {
                if (n2 && nc + 1 < N) {
                    *(float2*)(C + (size_t)r0 * N + nc) = make_float2(v00, v01);
                    *(float2*)(C + (size_t)r1 * N + nc) = make_float2(v10, v11);
                } else {
                    if (nc < N)     { C[(size_t)r0 * N + nc]     = v00; C[(size_t)r1 * N + nc]     = v10; }
                    if (nc + 1 < N) { C[(size_t)r0 * N + nc + 1] = v01; C[(size_t)r1 * N + nc + 1] = v11; }
                }
            }
        }
    }
}

// ---------------- MMA flash-attention (fp16 split, online softmax) ----------------
// block: 128 threads / 4 warps; q-tile 64 (warp owns 16 rows x full 64-wide j strip)
// smem planes (u32, row stride 36): Qh Ql Kh Kl [row][dpair]; Vh Vl transposed [d][jpair]
#define APD 36
#define APLANE (64 * APD)                // 2304 u32
#define ASMEM (6 * APLANE * 4)           // 55296 bytes

__global__ __launch_bounds__(128, 3)
void attn_mma_kernel(const float* __restrict__ qkv,
                     uint32_t* __restrict__ yh, uint32_t* __restrict__ yl) {
    extern __shared__ __align__(16) uint32_t as[];
    uint32_t* sQh = as;
    uint32_t* sQl = as + APLANE;
    uint32_t* sKh = as + 2 * APLANE;
    uint32_t* sKl = as + 3 * APLANE;
    uint32_t* sVh = as + 4 * APLANE;     // [d][jpair]
    uint32_t* sVl = as + 5 * APLANE;

    const int t = threadIdx.x;
    const int warp = t >> 5, lane = t & 31;
    const int grp = lane >> 2, tig = lane & 3;
    const int hd = blockIdx.y, b = blockIdx.z;
    const int qblk = gridDim.x - 1 - blockIdx.x;   // long blocks first
    const int qb = qblk * 64;
    const int m0 = warp * 16;

    // ---- stage Q (scaled) ----
    {
        const float* Qb = qkv + ((size_t)(b * TT + qb)) * C3 + hd * DD;
#pragma unroll
        for (int i = 0; i < 8; i++) {
            int idx = t + i * 128;         // 0..1023 float4s
            int row = idx >> 4, c4 = idx & 15;
            float4 v = *(const float4*)(Qb + (size_t)row * C3 + c4 * 4);
            uint32_t h0, l0, h1, l1;
            split2(v.x * 0.125f, v.y * 0.125f, h0, l0);
            split2(v.z * 0.125f, v.w * 0.125f, h1, l1);
            sQh[row * APD + 2 * c4]     = h0;
            sQh[row * APD + 2 * c4 + 1] = h1;
            sQl[row * APD + 2 * c4]     = l0;
            sQl[row * APD + 2 * c4 + 1] = l1;
        }
    }

    const float* Kb = qkv + (size_t)b * TT * C3 + CC     + hd * DD;
    const float* Vb = qkv + (size_t)b * TT * C3 + 2 * CC + hd * DD;

    float oacc[8][4];
#pragma unroll
    for (int nf = 0; nf < 8; nf++)
#pragma unroll
        for (int e = 0; e < 4; e++) oacc[nf][e] = 0.f;
    float mr1 = -1e30f, mr2 = -1e30f, lr1 = 0.f, lr2 = 0.f;

    for (int jt = 0; jt <= qblk; jt++) {
        const int j0 = jt * 64;
        __syncthreads();
        // ---- stage K [j][dpair] ----
#pragma unroll
        for (int i = 0; i < 8; i++) {
            int idx = t + i * 128;
            int row = idx >> 4, c4 = idx & 15;
            float4 v = *(const float4*)(Kb + (size_t)(j0 + row) * C3 + c4 * 4);
            uint32_t h0, l0, h1, l1;
            split2(v.x, v.y, h0, l0);
            split2(v.z, v.w, h1, l1);
            sKh[row * APD + 2 * c4]     = h0;
            sKh[row * APD + 2 * c4 + 1] = h1;
            sKl[row * APD + 2 * c4]     = l0;
            sKl[row * APD + 2 * c4 + 1] = l1;
        }
        // ---- stage V transposed [d][jpair] ----
#pragma unroll
        for (int i = 0; i < 16; i++) {
            int w = t + i * 128;           // 0..2047
            int d = w & 63, jp = w >> 6;
            float v0 = Vb[(size_t)(j0 + 2 * jp)     * C3 + d];
            float v1 = Vb[(size_t)(j0 + 2 * jp + 1) * C3 + d];
            uint32_t h, l;
            split2(v0, v1, h, l);
            sVh[d * APD + jp] = h;
            sVl[d * APD + jp] = l;
        }
        __syncthreads();

        // ---- S = Q K^T (3-pass fp16 split) ----
        float s[8][4];
#pragma unroll
        for (int nf = 0; nf < 8; nf++)
#pragma unroll
            for (int e = 0; e < 4; e++) s[nf][e] = 0.f;

#pragma unroll
        for (int ks = 0; ks < 4; ks++) {
            const int kb = ks * 8;
            uint32_t qh0 = sQh[(m0 + grp)     * APD + kb + tig];
            uint32_t qh1 = sQh[(m0 + grp + 8) * APD + kb + tig];
            uint32_t qh2 = sQh[(m0 + grp)     * APD + kb + tig + 4];
            uint32_t qh3 = sQh[(m0 + grp + 8) * APD + kb + tig + 4];
            uint32_t ql0 = sQl[(m0 + grp)     * APD + kb + tig];
            uint32_t ql1 = sQl[(m0 + grp + 8) * APD + kb + tig];
            uint32_t ql2 = sQl[(m0 + grp)     * APD + kb + tig + 4];
            uint32_t ql3 = sQl[(m0 + grp + 8) * APD + kb + tig + 4];
#pragma unroll
            for (int nf = 0; nf < 8; nf++) {
                uint32_t bh0 = sKh[(nf * 8 + grp) * APD + kb + tig];
                uint32_t bh1 = sKh[(nf * 8 + grp) * APD + kb + tig + 4];
                uint32_t bl0 = sKl[(nf * 8 + grp) * APD + kb + tig];
                uint32_t bl1 = sKl[(nf * 8 + grp) * APD + kb + tig + 4];
                mma_f16(s[nf], qh0, qh1, qh2, qh3, bh0, bh1);
                mma_f16(s[nf], qh0, qh1, qh2, qh3, bl0, bl1);
                mma_f16(s[nf], ql0, ql1, ql2, ql3, bh0, bh1);
            }
        }

        // ---- causal mask (diagonal tile only) ----
        if (jt == qblk) {
#pragma unroll
            for (int nf = 0; nf < 8; nf++) {
                int jc = nf * 8 + 2 * tig;
                int r1 = m0 + grp, r2 = r1 + 8;
                if (jc     > r1) s[nf][0] = -1e30f;
                if (jc + 1 > r1) s[nf][1] = -1e30f;
                if (jc     > r2) s[nf][2] = -1e30f;
                if (jc + 1 > r2) s[nf][3] = -1e30f;
            }
        }

        // ---- online softmax (rows grp / grp+8; reduce over 4 tig lanes) ----
        float tm1 = -1e30f, tm2 = -1e30f;
#pragma unroll
        for (int nf = 0; nf < 8; nf++) {
            tm1 = fmaxf(tm1, fmaxf(s[nf][0], s[nf][1]));
            tm2 = fmaxf(tm2, fmaxf(s[nf][2], s[nf][3]));
        }
        tm1 = fmaxf(tm1, __shfl_xor_sync(0xffffffffu, tm1, 1));
        tm1 = fmaxf(tm1, __shfl_xor_sync(0xffffffffu, tm1, 2));
        tm2 = fmaxf(tm2, __shfl_xor_sync(0xffffffffu, tm2, 1));
        tm2 = fmaxf(tm2, __shfl_xor_sync(0xffffffffu, tm2, 2));
        float mn1 = fmaxf(mr1, tm1), mn2 = fmaxf(mr2, tm2);
        float c1 = __expf(mr1 - mn1), c2 = __expf(mr2 - mn2);
        float ts1 = 0.f, ts2 = 0.f;
#pragma unroll
        for (int nf = 0; nf < 8; nf++) {
            s[nf][0] = __expf(s[nf][0] - mn1);
            s[nf][1] = __expf(s[nf][1] - mn1);
            s[nf][2] = __expf(s[nf][2] - mn2);
            s[nf][3] = __expf(s[nf][3] - mn2);
            ts1 += s[nf][0] + s[nf][1];
            ts2 += s[nf][2] + s[nf][3];
        }
        ts1 += __shfl_xor_sync(0xffffffffu, ts1, 1);
        ts1 += __shfl_xor_sync(0xffffffffu, ts1, 2);
        ts2 += __shfl_xor_sync(0xffffffffu, ts2, 1);
        ts2 += __shfl_xor_sync(0xffffffffu, ts2, 2);
        lr1 = lr1 * c1 + ts1;
        lr2 = lr2 * c2 + ts2;
        mr1 = mn1; mr2 = mn2;
#pragma unroll
        for (int nf = 0; nf < 8; nf++) {
            oacc[nf][0] *= c1; oacc[nf][1] *= c1;
            oacc[nf][2] *= c2; oacc[nf][3] *= c2;
        }

        // ---- O += P V (P frags straight from registers, 3-pass) ----
#pragma unroll
        for (int ks = 0; ks < 4; ks++) {
            uint32_t ph0, pl0, ph1, pl1, ph2, pl2, ph3, pl3;
            split2(s[2 * ks][0],     s[2 * ks][1],     ph0, pl0);
            split2(s[2 * ks][2],     s[2 * ks][3],     ph1, pl1);
            split2(s[2 * ks + 1][0], s[2 * ks + 1][1], ph2, pl2);
            split2(s[2 * ks + 1][2], s[2 * ks + 1][3], ph3, pl3);
#pragma unroll
            for (int nf = 0; nf < 8; nf++) {
                uint32_t bh0 = sVh[(nf * 8 + grp) * APD + ks * 8 + tig];
                uint32_t bh1 = sVh[(nf * 8 + grp) * APD + ks * 8 + tig + 4];
                uint32_t bl0 = sVl[(nf * 8 + grp) * APD + ks * 8 + tig];
                uint32_t bl1 = sVl[(nf * 8 + grp) * APD + ks * 8 + tig + 4];
                mma_f16(oacc[nf], ph0, ph1, ph2, ph3, bh0, bh1);
                mma_f16(oacc[nf], ph0, ph1, ph2, ph3, bl0, bl1);
                mma_f16(oacc[nf], pl0, pl1, pl2, pl3, bh0, bh1);
            }
        }
    }

    // ---- epilogue: normalize + write y pair planes ----
    float inv1 = 1.f / lr1, inv2 = 1.f / lr2;
    size_t r1 = (size_t)(b * TT + qb + m0 + grp) * (CC / 2) + hd * 32;
    size_t r2 = r1 + 8 * (CC / 2);
#pragma unroll
    for (int nf = 0; nf < 8; nf++) {
        uint32_t h, l;
        split2(oacc[nf][0] * inv1, oacc[nf][1] * inv1, h, l);
        yh[r1 + nf * 4 + tig] = h; yl[r1 + nf * 4 + tig] = l;
        split2(oacc[nf][2] * inv2, oacc[nf][3] * inv2, h, l);
        yh[r2 + nf * 4 + tig] = h; yl[r2 + nf * 4 + tig] = l;
    }
}

// ---------------- host orchestration ----------------
extern "C" void kernel_launch(void* const* d_in, const int* in_sizes, int n_in,
                              void* d_out, int out_size) {
    const int*   idx   = (const int*)  d_in[0];
    const float* wte   = (const float*)d_in[1];
    const float* wpe   = (const float*)d_in[2];
    const float* ln1_g = (const float*)d_in[3];
    const float* ln1_b = (const float*)d_in[4];
    const float* wqkv  = (const float*)d_in[5];
    const float* bqkv  = (const float*)d_in[6];
    const float* wproj = (const float*)d_in[7];
    const float* bproj = (const float*)d_in[8];
    const float* ln2_g = (const float*)d_in[9];
    const float* ln2_b = (const float*)d_in[10];
    const float* wfc   = (const float*)d_in[11];
    const float* bfc   = (const float*)d_in[12];
    const float* wfc2  = (const float*)d_in[13];
    const float* bfc2  = (const float*)d_in[14];
    const float* lnf_g = (const float*)d_in[15];
    const float* lnf_b = (const float*)d_in[16];
    const float* lm_w  = (const float*)d_in[17];
    float* out = (float*)d_out;

    float *x, *qkv;
    uint32_t *lnh, *lnl, *acth, *actl;
    uint32_t *wqh, *wql, *wph, *wpl, *wfh, *wfl, *w2h, *w2l, *lmh, *lml;
    cudaGetSymbolAddress((void**)&x,    g_x);
    cudaGetSymbolAddress((void**)&qkv,  g_qkv);
    cudaGetSymbolAddress((void**)&lnh,  g_lnh);
    cudaGetSymbolAddress((void**)&lnl,  g_lnl);
    cudaGetSymbolAddress((void**)&acth, g_acth);
    cudaGetSymbolAddress((void**)&actl, g_actl);
    cudaGetSymbolAddress((void**)&wqh,  g_wqkvh);
    cudaGetSymbolAddress((void**)&wql,  g_wqkvl);
    cudaGetSymbolAddress((void**)&wph,  g_wprjh);
    cudaGetSymbolAddress((void**)&wpl,  g_wprjl);
    cudaGetSymbolAddress((void**)&wfh,  g_wfch);
    cudaGetSymbolAddress((void**)&wfl,  g_wfcl);
    cudaGetSymbolAddress((void**)&w2h,  g_wfc2h);
    cudaGetSymbolAddress((void**)&w2l,  g_wfc2l);
    cudaGetSymbolAddress((void**)&lmh,  g_lmwh);
    cudaGetSymbolAddress((void**)&lml,  g_lmwl);

    cudaFuncSetAttribute(gemm_mma<1, 0>, cudaFuncAttributeMaxDynamicSharedMemorySize, GSMEM);
    cudaFuncSetAttribute(gemm_mma<5, 0>, cudaFuncAttributeMaxDynamicSharedMemorySize, GSMEM);
    cudaFuncSetAttribute(gemm_mma<3, 1>, cudaFuncAttributeMaxDynamicSharedMemorySize, GSMEM);
    cudaFuncSetAttribute(gemm_mma<0, 0>, cudaFuncAttributeMaxDynamicSharedMemorySize, GSMEM);
    cudaFuncSetAttribute(attn_mma_kernel, cudaFuncAttributeMaxDynamicSharedMemorySize, ASMEM);

    // ---- weight conversions (once per call) ----
    convert_w<<<dim3((C3 + 1023) / 1024, LL * CC / 2), 256>>>(wqkv,  wqh, wql, C3, C3);
    convert_w<<<dim3((CC + 1023) / 1024, LL * CC / 2), 256>>>(wproj, wph, wpl, CC, CC);
    convert_w<<<dim3((C4 + 1023) / 1024, LL * CC / 2), 256>>>(wfc,   wfh, wfl, C4, C4);
    convert_w<<<dim3((CC + 1023) / 1024, LL * C4 / 2), 256>>>(wfc2,  w2h, w2l, CC, CC);
    convert_w<<<dim3((VP + 1023) / 1024, CC / 2),      256>>>(lm_w,  lmh, lml, VV, VP);

    embed_kernel<<<MR, 256>>>(idx, wte, wpe);

    for (int l = 0; l < LL; l++) {
        ln_kernel<<<MR, 256>>>(x, ln1_g + (size_t)l * CC, ln1_b + (size_t)l * CC, lnh, lnl);

        // qkv = ln @ wqkv + bqkv  [2048 x 2304], fp32 out
        gemm_mma<1, 0><<<dim3(16, C3 / 128), 256, GSMEM>>>(
            lnh, lnl, CC / 2,
            wqh + (size_t)l * (CC / 2) * C3, wql + (size_t)l * (CC / 2) * C3, C3,
            bqkv + (size_t)l * C3, nullptr, qkv, nullptr, nullptr, C3);

        attn_mma_kernel<<<dim3(TT / 64, HH, BB), 128, ASMEM>>>(qkv, acth, actl);

        // x = x + y @ wproj + bproj  (A = y planes, stride 384)
        gemm_mma<5, 0><<<dim3(16, CC / 128), 256, GSMEM>>>(
            acth, actl, CC / 2,
            wph + (size_t)l * (CC / 2) * CC, wpl + (size_t)l * (CC / 2) * CC, CC,
            bproj + (size_t)l * CC, x, x, nullptr, nullptr, CC);

        ln_kernel<<<MR, 256>>>(x, ln2_g + (size_t)l * CC, ln2_b + (size_t)l * CC, lnh, lnl);

        // fc = gelu(ln @ wfc + bfc), pair-plane out (stride 1536)
        gemm_mma<3, 1><<<dim3(16, C4 / 128), 256, GSMEM>>>(
            lnh, lnl, CC / 2,
            wfh + (size_t)l * (CC / 2) * C4, wfl + (size_t)l * (CC / 2) * C4, C4,
            bfc + (size_t)l * C4, nullptr, nullptr, acth, actl, C4);

        // x = x + fc @ wfc2 + bfc2  (A = fc planes, stride 1536)
        gemm_mma<5, 0><<<dim3(16, CC / 128), 256, GSMEM>>>(
            acth, actl, C4 / 2,
            w2h + (size_t)l * (C4 / 2) * CC, w2l + (size_t)l * (C4 / 2) * CC, CC,
            bfc2 + (size_t)l * CC, x, x, nullptr, nullptr, CC);
    }

    ln_kernel<<<MR, 256>>>(x, lnf_g, lnf_b, lnh, lnl);

    // logits = ln @ lm_w  [2048 x 50257]
    gemm_mma<0, 0><<<dim3(16, VP / 128), 256, GSMEM>>>(
        lnh, lnl, CC / 2, lmh, lml, VP,
        nullptr, nullptr, out, nullptr, nullptr, VV);
}

// round 11
// speedup vs baseline: 4.0725x; 1.0851x over previous
#include <cuda_runtime.h>
#include <cuda_fp16.h>
#include <math.h>
#include <stdint.h>

// ---------------- problem constants ----------------
#define BB   2
#define TT   1024
#define CC   768
#define HH   12
#define DD   64
#define LL   12
#define VV   50257
#define MR   2048
#define C3   2304
#define C4   3072
#define VP   50304   // VV padded to multiple of 128

// ---------------- fp32 buffers ----------------
__device__ float g_x  [MR*CC];   // residual stream
__device__ float g_qkv[MR*C3];   // qkv (attention input)

// ---------------- activation hi/lo pair planes (u32 = half2(k_even, k_odd)) ----------------
__device__ uint32_t g_lnh [MR*(CC/2)], g_lnl [MR*(CC/2)];    // LN outputs
__device__ uint32_t g_acth[MR*(C4/2)], g_actl[MR*(C4/2)];    // y (stride 384) / fc (stride 1536)

// ---------------- weight hi/lo pair planes ----------------
__device__ uint32_t g_wqkvh[LL*(CC/2)*C3], g_wqkvl[LL*(CC/2)*C3];
__device__ uint32_t g_wprjh[LL*(CC/2)*CC], g_wprjl[LL*(CC/2)*CC];
__device__ uint32_t g_wfch [LL*(CC/2)*C4], g_wfcl [LL*(CC/2)*C4];
__device__ uint32_t g_wfc2h[LL*(C4/2)*CC], g_wfc2l[LL*(C4/2)*CC];
__device__ uint32_t g_lmwh [(CC/2)*VP],    g_lmwl [(CC/2)*VP];

// ---------------- helpers ----------------
__device__ __forceinline__ uint32_t smem_u32(const void* p) {
    uint32_t a;
    asm("{ .reg .u64 t; cvta.to.shared.u64 t, %1; cvt.u32.u64 %0, t; }" : "=r"(a) : "l"(p));
    return a;
}

__device__ __forceinline__ void mma_f16(float* c, uint32_t a0, uint32_t a1,
                                        uint32_t a2, uint32_t a3,
                                        uint32_t b0, uint32_t b1) {
    asm volatile(
        "mma.sync.aligned.m16n8k16.row.col.f32.f16.f16.f32 "
        "{%0,%1,%2,%3}, {%4,%5,%6,%7}, {%8,%9}, {%0,%1,%2,%3};"
        : "+f"(c[0]), "+f"(c[1]), "+f"(c[2]), "+f"(c[3])
        : "r"(a0), "r"(a1), "r"(a2), "r"(a3), "r"(b0), "r"(b1));
}

// pack two floats into (hi, lo) half2 words; elem0 (low 16 bits) = first arg
__device__ __forceinline__ void split2(float a, float b, uint32_t& hi, uint32_t& lo) {
    __half ha = __float2half_rn(a), hb = __float2half_rn(b);
    float ra = a - __half2float(ha), rb = b - __half2float(hb);
    __half la = __float2half_rn(ra), lb = __float2half_rn(rb);
    hi = (uint32_t)__half_as_ushort(ha) | ((uint32_t)__half_as_ushort(hb) << 16);
    lo = (uint32_t)__half_as_ushort(la) | ((uint32_t)__half_as_ushort(lb) << 16);
}

__device__ __forceinline__ void cp16(uint32_t s, const void* g) {
    asm volatile("cp.async.cg.shared.global [%0], [%1], 16;" :: "r"(s), "l"(g));
}

__device__ __forceinline__ float gelu_f(float x) {
    float x3 = x * x * x;
    return 0.5f * x * (1.0f + tanhf(0.7978845608028654f * (x + 0.044715f * x3)));
}

// ---------------- weight conversion: [K][N] fp32 -> pair planes [K/2][NP] ----------------
__global__ void convert_w(const float* __restrict__ w, uint32_t* __restrict__ ph,
                          uint32_t* __restrict__ pl, int N, int NP) {
    int kp = blockIdx.y;
    int n0 = (blockIdx.x * 256 + threadIdx.x) * 4;
    if (n0 >= NP) return;
    const float* r0 = w + (size_t)(2 * kp) * N;
    const float* r1 = r0 + N;
    uint32_t h[4], l[4];
#pragma unroll
    for (int j = 0; j < 4; j++) {
        int n = n0 + j;
        float a = (n < N) ? r0[n] : 0.f;
        float b = (n < N) ? r1[n] : 0.f;
        split2(a, b, h[j], l[j]);
    }
    *(uint4*)&ph[(size_t)kp * NP + n0] = make_uint4(h[0], h[1], h[2], h[3]);
    *(uint4*)&pl[(size_t)kp * NP + n0] = make_uint4(l[0], l[1], l[2], l[3]);
}

// ---------------- embedding ----------------
__global__ void embed_kernel(const int* __restrict__ idx,
                             const float* __restrict__ wte,
                             const float* __restrict__ wpe) {
    int row = blockIdx.x;
    int t   = row % TT;
    int tok = idx[row];
    const float* we = wte + (size_t)tok * CC;
    const float* wp = wpe + (size_t)t   * CC;
    float* out = g_x + (size_t)row * CC;
    for (int i = threadIdx.x; i < CC; i += blockDim.x)
        out[i] = we[i] + wp[i];
}

// ---------------- layernorm -> pair planes ----------------
__global__ __launch_bounds__(256)
void ln_kernel(const float* __restrict__ x,
               const float* __restrict__ g,
               const float* __restrict__ b,
               uint32_t* __restrict__ outh, uint32_t* __restrict__ outl) {
    int row = blockIdx.x;
    const float* xr = x + (size_t)row * CC;
    float s = 0.f, s2 = 0.f;
    for (int i = threadIdx.x; i < CC; i += 256) {
        float v = xr[i];
        s += v; s2 += v * v;
    }
    for (int o = 16; o; o >>= 1) {
        s  += __shfl_xor_sync(0xffffffffu, s,  o);
        s2 += __shfl_xor_sync(0xffffffffu, s2, o);
    }
    __shared__ float sh0[8], sh1[8];
    int w = threadIdx.x >> 5, l = threadIdx.x & 31;
    if (l == 0) { sh0[w] = s; sh1[w] = s2; }
    __syncthreads();
    if (w == 0) {
        s  = (l < 8) ? sh0[l] : 0.f;
        s2 = (l < 8) ? sh1[l] : 0.f;
        for (int o = 4; o; o >>= 1) {
            s  += __shfl_xor_sync(0xffffffffu, s,  o);
            s2 += __shfl_xor_sync(0xffffffffu, s2, o);
        }
        if (l == 0) { sh0[0] = s; sh1[0] = s2; }
    }
    __syncthreads();
    float mean = sh0[0] * (1.0f / CC);
    float var  = sh1[0] * (1.0f / CC) - mean * mean;
    float rstd = rsqrtf(var + 1e-5f);
    for (int i = threadIdx.x; i < CC / 2; i += 256) {
        float a = (xr[2 * i]     - mean) * rstd * g[2 * i]     + b[2 * i];
        float c = (xr[2 * i + 1] - mean) * rstd * g[2 * i + 1] + b[2 * i + 1];
        uint32_t ph, pl;
        split2(a, c, ph, pl);
        outh[(size_t)row * (CC / 2) + i] = ph;
        outl[(size_t)row * (CC / 2) + i] = pl;
    }
}

// ---------------- fp16-split mma GEMM, 128x128 tile, cp.async double-buffer ----------------
// EPI bits: 1=+bias, 2=gelu, 4=+residual.  OUTM: 0 = fp32 C, 1 = pair planes.
// PASSES: 3 = hi/lo split (exact), 1 = fp16 hi-only (LM head leaf).
#define PA 20      // u32 row stride of A tile (16 pairs + 4 pad)
#define PB 136     // u32 row stride of B tile (128 + 8 pad, conflict-free)
#define STG 9472   // u32 per stage: 2*128*20 + 2*16*136
#define OFF_AL 2560
#define OFF_BH 5120
#define OFF_BL 7296
#define GSMEM (2 * STG * 4)   // 75776 bytes

template<int EPI, int OUTM, int PASSES>
__global__ __launch_bounds__(256, 2)
void gemm_mma(const uint32_t* __restrict__ Ah, const uint32_t* __restrict__ Al, int KH,
              const uint32_t* __restrict__ Bh, const uint32_t* __restrict__ Bl, int NP,
              const float* __restrict__ bias, const float* __restrict__ res,
              float* __restrict__ C, uint32_t* __restrict__ Ch, uint32_t* __restrict__ Cl,
              int N) {
    extern __shared__ __align__(16) uint32_t sm[];
    const int t = threadIdx.x;
    const int wid = t >> 5, lane = t & 31;
    const int grp = lane >> 2, tig = lane & 3;
    const int warp_m = wid >> 2;          // 0..1
    const int warp_n = wid & 3;           // 0..3
    const int m0 = blockIdx.x * 128;
    const int n0 = blockIdx.y * 128;
    const uint32_t sb = smem_u32(sm);

    float acc[4][4][4];
#pragma unroll
    for (int im = 0; im < 4; im++)
#pragma unroll
        for (int in = 0; in < 4; in++)
#pragma unroll
            for (int r = 0; r < 4; r++) acc[im][in][r] = 0.f;

    const int nch = KH / 16;

    auto prefetch = [&](int c, int st) {
        uint32_t base = sb + (uint32_t)st * STG * 4;
        int k0 = c * 16;
#pragma unroll
        for (int i = 0; i < 2; i++) {
            int idx = t + i * 256;
            int row = idx >> 2, ch = (idx & 3) * 4;
            size_t go = (size_t)(m0 + row) * KH + k0 + ch;
            cp16(base + (row * PA + ch) * 4, Ah + go);
            if (PASSES == 3) cp16(base + (OFF_AL + row * PA + ch) * 4, Al + go);
        }
#pragma unroll
        for (int i = 0; i < 2; i++) {
            int idx = t + i * 256;
            int kp = idx >> 5, ch = (idx & 31) * 4;
            size_t go = (size_t)(k0 + kp) * NP + n0 + ch;
            cp16(base + (OFF_BH + kp * PB + ch) * 4, Bh + go);
            if (PASSES == 3) cp16(base + (OFF_BL + kp * PB + ch) * 4, Bl + go);
        }
        asm volatile("cp.async.commit_group;" ::: "memory");
    };

    prefetch(0, 0);
    for (int c = 0; c < nch; c++) {
        if (c + 1 < nch) {
            prefetch(c + 1, (c + 1) & 1);
            asm volatile("cp.async.wait_group 1;" ::: "memory");
        } else {
            asm volatile("cp.async.wait_group 0;" ::: "memory");
        }
        __syncthreads();
        const uint32_t* S = sm + (c & 1) * STG;
#pragma unroll
        for (int ks = 0; ks < 2; ks++) {
            const int kb = ks * 8;
            uint32_t ah[4][4], al[4][4];
#pragma unroll
            for (int im = 0; im < 4; im++) {
                int r0 = (warp_m * 64 + im * 16 + grp) * PA;
                int r1 = r0 + 8 * PA;
                ah[im][0] = S[r0 + kb + tig];
                ah[im][1] = S[r1 + kb + tig];
                ah[im][2] = S[r0 + kb + tig + 4];
                ah[im][3] = S[r1 + kb + tig + 4];
                if (PASSES == 3) {
                    al[im][0] = S[OFF_AL + r0 + kb + tig];
                    al[im][1] = S[OFF_AL + r1 + kb + tig];
                    al[im][2] = S[OFF_AL + r0 + kb + tig + 4];
                    al[im][3] = S[OFF_AL + r1 + kb + tig + 4];
                }
            }
            uint32_t bh[4][2], bl[4][2];
#pragma unroll
            for (int in = 0; in < 4; in++) {
                int nb = warp_n * 32 + in * 8 + grp;
                bh[in][0] = S[OFF_BH + (kb + tig) * PB + nb];
                bh[in][1] = S[OFF_BH + (kb + tig + 4) * PB + nb];
                if (PASSES == 3) {
                    bl[in][0] = S[OFF_BL + (kb + tig) * PB + nb];
                    bl[in][1] = S[OFF_BL + (kb + tig + 4) * PB + nb];
                }
            }
#pragma unroll
            for (int im = 0; im < 4; im++)
#pragma unroll
                for (int in = 0; in < 4; in++) {
                    mma_f16(acc[im][in], ah[im][0], ah[im][1], ah[im][2], ah[im][3],
                            bh[in][0], bh[in][1]);
                    if (PASSES == 3) {
                        mma_f16(acc[im][in], ah[im][0], ah[im][1], ah[im][2], ah[im][3],
                                bl[in][0], bl[in][1]);
                        mma_f16(acc[im][in], al[im][0], al[im][1], al[im][2], al[im][3],
                                bh[in][0], bh[in][1]);
                    }
                }
        }
        __syncthreads();
    }

    // ---- epilogue ----
    const bool n2 = ((N & 1) == 0);
#pragma unroll
    for (int im = 0; im < 4; im++) {
        int r0 = m0 + warp_m * 64 + im * 16 + grp;
        int r1 = r0 + 8;
#pragma unroll
        for (int in = 0; in < 4; in++) {
            int nc = n0 + warp_n * 32 + in * 8 + tig * 2;
            float v00 = acc[im][in][0], v01 = acc[im][in][1];
            float v10 = acc[im][in][2], v11 = acc[im][in][3];
            if (EPI & 1) {
                float b0v = (nc < N) ? bias[nc] : 0.f;
                float b1v = (nc + 1 < N) ? bias[nc + 1] : 0.f;
                v00 += b0v; v10 += b0v; v01 += b1v; v11 += b1v;
            }
            if (EPI & 2) {
                v00 = gelu_f(v00); v01 = gelu_f(v01);
                v10 = gelu_f(v10); v11 = gelu_f(v11);
            }
            if (EPI & 4) {
                if (nc < N) { v00 += res[(size_t)r0 * N + nc]; v10 += res[(size_t)r1 * N + nc]; }
                if (nc + 1 < N) { v01 += res[(size_t)r0 * N + nc + 1]; v11 += res[(size_t)r1 * N + nc + 1]; }
            }
            if (OUTM == 1) {
                uint32_t ph, pl;
                split2(v00, v01, ph, pl);
                Ch[(size_t)r0 * (N / 2) + nc / 2] = ph;
                Cl[(size_t)r0 * (N / 2) + nc / 2] = pl;
                split2(v10, v11, ph, pl);
                Ch[(size_t)r1 * (N / 2) + nc / 2] = ph;
                Cl[(size_t)r1 * (N / 2) + nc / 2] = pl;
            } else {
                if (n2 && nc + 1 < N) {
                    *(float2*)(C + (size_t)r0 * N + nc) = make_float2(v00, v01);
                    *(float2*)(C + (size_t)r1 * N + nc) = make_float2(v10, v11);
                } else {
                    if (nc < N)     { C[(size_t)r0 * N + nc]     = v00; C[(size_t)r1 * N + nc]     = v10; }
                    if (nc + 1 < N) { C[(size_t)r0 * N + nc + 1] = v01; C[(size_t)r1 * N + nc + 1] = v11; }
                }
            }
        }
    }
}

// ---------------- 64x64-tile variant (wave-fill for proj / fc / fc2) ----------------
// 8 warps 2x4; warp tile 32x16; 3-pass split.
#define PB64 72
#define STG64 4864            // 2*64*20 + 2*16*72
#define OFF_AL64 1280
#define OFF_BH64 2560
#define OFF_BL64 3712
#define GSMEM64 (2 * STG64 * 4)   // 38912 bytes

template<int EPI, int OUTM>
__global__ __launch_bounds__(256, 3)
void gemm_mma64(const uint32_t* __restrict__ Ah, const uint32_t* __restrict__ Al, int KH,
                const uint32_t* __restrict__ Bh, const uint32_t* __restrict__ Bl, int NP,
                const float* __restrict__ bias, const float* __restrict__ res,
                float* __restrict__ C, uint32_t* __restrict__ Ch, uint32_t* __restrict__ Cl,
                int N) {
    extern __shared__ __align__(16) uint32_t sm[];
    const int t = threadIdx.x;
    const int wid = t >> 5, lane = t & 31;
    const int grp = lane >> 2, tig = lane & 3;
    const int warp_m = wid >> 2;          // 0..1  (32-row strips)
    const int warp_n = wid & 3;           // 0..3  (16-col strips)
    const int m0 = blockIdx.x * 64;
    const int n0 = blockIdx.y * 64;
    const uint32_t sb = smem_u32(sm);

    float acc[2][2][4];
#pragma unroll
    for (int im = 0; im < 2; im++)
#pragma unroll
        for (int in = 0; in < 2; in++)
#pragma unroll
            for (int r = 0; r < 4; r++) acc[im][in][r] = 0.f;

    const int nch = KH / 16;

    auto prefetch = [&](int c, int st) {
        uint32_t base = sb + (uint32_t)st * STG64 * 4;
        int k0 = c * 16;
        {   // A: 64 rows x 16 pairs per plane
            int row = t >> 2, ch = (t & 3) * 4;
            size_t go = (size_t)(m0 + row) * KH + k0 + ch;
            cp16(base + (row * PA + ch) * 4, Ah + go);
            cp16(base + (OFF_AL64 + row * PA + ch) * 4, Al + go);
        }
        {   // B: 16 kp rows x 64 n per plane
            int kp = t >> 4, ch = (t & 15) * 4;
            size_t go = (size_t)(k0 + kp) * NP + n0 + ch;
            cp16(base + (OFF_BH64 + kp * PB64 + ch) * 4, Bh + go);
            cp16(base + (OFF_BL64 + kp * PB64 + ch) * 4, Bl + go);
        }
        asm volatile("cp.async.commit_group;" ::: "memory");
    };

    prefetch(0, 0);
    for (int c = 0; c < nch; c++) {
        if (c + 1 < nch) {
            prefetch(c + 1, (c + 1) & 1);
            asm volatile("cp.async.wait_group 1;" ::: "memory");
        } else {
            asm volatile("cp.async.wait_group 0;" ::: "memory");
        }
        __syncthreads();
        const uint32_t* S = sm + (c & 1) * STG64;
#pragma unroll
        for (int ks = 0; ks < 2; ks++) {
            const int kb = ks * 8;
            uint32_t ah[2][4], al[2][4];
#pragma unroll
            for (int im = 0; im < 2; im++) {
                int r0 = (warp_m * 32 + im * 16 + grp) * PA;
                int r1 = r0 + 8 * PA;
                ah[im][0] = S[r0 + kb + tig];
                ah[im][1] = S[r1 + kb + tig];
                ah[im][2] = S[r0 + kb + tig + 4];
                ah[im][3] = S[r1 + kb + tig + 4];
                al[im][0] = S[OFF_AL64 + r0 + kb + tig];
                al[im][1] = S[OFF_AL64 + r1 + kb + tig];
                al[im][2] = S[OFF_AL64 + r0 + kb + tig + 4];
                al[im][3] = S[OFF_AL64 + r1 + kb + tig + 4];
            }
            uint32_t bh[2][2], bl[2][2];
#pragma unroll
            for (int in = 0; in < 2; in++) {
                int nb = warp_n * 16 + in * 8 + grp;
                bh[in][0] = S[OFF_BH64 + (kb + tig) * PB64 + nb];
                bh[in][1] = S[OFF_BH64 + (kb + tig + 4) * PB64 + nb];
                bl[in][0] = S[OFF_BL64 + (kb + tig) * PB64 + nb];
                bl[in][1] = S[OFF_BL64 + (kb + tig + 4) * PB64 + nb];
            }
#pragma unroll
            for (int im = 0; im < 2; im++)
#pragma unroll
                for (int in = 0; in < 2; in++) {
                    mma_f16(acc[im][in], ah[im][0], ah[im][1], ah[im][2], ah[im][3],
                            bh[in][0], bh[in][1]);
                    mma_f16(acc[im][in], ah[im][0], ah[im][1], ah[im][2], ah[im][3],
                            bl[in][0], bl[in][1]);
                    mma_f16(acc[im][in], al[im][0], al[im][1], al[im][2], al[im][3],
                            bh[in][0], bh[in][1]);
                }
        }
        __syncthreads();
    }

    // ---- epilogue ----
#pragma unroll
    for (int im = 0; im < 2; im++) {
        int r0 = m0 + warp_m * 32 + im * 16 + grp;
        int r1 = r0 + 8;
#pragma unroll
        for (int in = 0; in < 2; in++) {
            int nc = n0 + warp_n * 16 + in * 8 + tig * 2;
            float v00 = acc[im][in][0], v01 = acc[im][in][1];
            float v10 = acc[im][in][2], v11 = acc[im][in][3];
            if (EPI & 1) {
                float b0v = bias[nc], b1v = bias[nc + 1];
                v00 += b0v; v10 += b0v; v01 += b1v; v11 += b1v;
            }
            if (EPI & 2) {
                v00 = gelu_f(v00); v01 = gelu_f(v01);
                v10 = gelu_f(v10); v11 = gelu_f(v11);
            }
            if (EPI & 4) {
                v00 += res[(size_t)r0 * N + nc];
                v01 += res[(size_t)r0 * N + nc + 1];
                v10 += res[(size_t)r1 * N + nc];
                v11 += res[(size_t)r1 * N + nc + 1];
            }
            if (OUTM == 1) {
                uint32_t ph, pl;
                split2(v00, v01, ph, pl);
                Ch[(size_t)r0 * (N / 2) + nc / 2] = ph;
                Cl[(size_t)r0 * (N / 2) + nc / 2] = pl;
                split2(v10, v11, ph, pl);
                Ch[(size_t)r1 * (N / 2) + nc / 2] = ph;
                Cl[(size_t)r1 * (N / 2) + nc / 2] = pl;
            } else {
                *(float2*)(C + (size_t)r0 * N + nc) = make_float2(v00, v01);
                *(float2*)(C + (size_t)r1 * N + nc) = make_float2(v10, v11);
            }
        }
    }
}

// ---------------- MMA flash-attention (fp16 split, online softmax) ----------------
#define APD 36
#define APLANE (64 * APD)                // 2304 u32
#define ASMEM (6 * APLANE * 4)           // 55296 bytes

__global__ __launch_bounds__(128, 3)
void attn_mma_kernel(const float* __restrict__ qkv,
                     uint32_t* __restrict__ yh, uint32_t* __restrict__ yl) {
    extern __shared__ __align__(16) uint32_t as[];
    uint32_t* sQh = as;
    uint32_t* sQl = as + APLANE;
    uint32_t* sKh = as + 2 * APLANE;
    uint32_t* sKl = as + 3 * APLANE;
    uint32_t* sVh = as + 4 * APLANE;     // [d][jpair]
    uint32_t* sVl = as + 5 * APLANE;

    const int t = threadIdx.x;
    const int warp = t >> 5, lane = t & 31;
    const int grp = lane >> 2, tig = lane & 3;
    const int hd = blockIdx.y, b = blockIdx.z;
    const int qblk = gridDim.x - 1 - blockIdx.x;   // long blocks first
    const int qb = qblk * 64;
    const int m0 = warp * 16;

    {
        const float* Qb = qkv + ((size_t)(b * TT + qb)) * C3 + hd * DD;
#pragma unroll
        for (int i = 0; i < 8; i++) {
            int idx = t + i * 128;
            int row = idx >> 4, c4 = idx & 15;
            float4 v = *(const float4*)(Qb + (size_t)row * C3 + c4 * 4);
            uint32_t h0, l0, h1, l1;
            split2(v.x * 0.125f, v.y * 0.125f, h0, l0);
            split2(v.z * 0.125f, v.w * 0.125f, h1, l1);
            sQh[row * APD + 2 * c4]     = h0;
            sQh[row * APD + 2 * c4 + 1] = h1;
            sQl[row * APD + 2 * c4]     = l0;
            sQl[row * APD + 2 * c4 + 1] = l1;
        }
    }

    const float* Kb = qkv + (size_t)b * TT * C3 + CC     + hd * DD;
    const float* Vb = qkv + (size_t)b * TT * C3 + 2 * CC + hd * DD;

    float oacc[8][4];
#pragma unroll
    for (int nf = 0; nf < 8; nf++)
#pragma unroll
        for (int e = 0; e < 4; e++) oacc[nf][e] = 0.f;
    float mr1 = -1e30f, mr2 = -1e30f, lr1 = 0.f, lr2 = 0.f;

    for (int jt = 0; jt <= qblk; jt++) {
        const int j0 = jt * 64;
        __syncthreads();
#pragma unroll
        for (int i = 0; i < 8; i++) {
            int idx = t + i * 128;
            int row = idx >> 4, c4 = idx & 15;
            float4 v = *(const float4*)(Kb + (size_t)(j0 + row) * C3 + c4 * 4);
            uint32_t h0, l0, h1, l1;
            split2(v.x, v.y, h0, l0);
            split2(v.z, v.w, h1, l1);
            sKh[row * APD + 2 * c4]     = h0;
            sKh[row * APD + 2 * c4 + 1] = h1;
            sKl[row * APD + 2 * c4]     = l0;
            sKl[row * APD + 2 * c4 + 1] = l1;
        }
#pragma unroll
        for (int i = 0; i < 16; i++) {
            int w = t + i * 128;
            int d = w & 63, jp = w >> 6;
            float v0 = Vb[(size_t)(j0 + 2 * jp)     * C3 + d];
            float v1 = Vb[(size_t)(j0 + 2 * jp + 1) * C3 + d];
            uint32_t h, l;
            split2(v0, v1, h, l);
            sVh[d * APD + jp] = h;
            sVl[d * APD + jp] = l;
        }
        __syncthreads();

        float s[8][4];
#pragma unroll
        for (int nf = 0; nf < 8; nf++)
#pragma unroll
            for (int e = 0; e < 4; e++) s[nf][e] = 0.f;

#pragma unroll
        for (int ks = 0; ks < 4; ks++) {
            const int kb = ks * 8;
            uint32_t qh0 = sQh[(m0 + grp)     * APD + kb + tig];
            uint32_t qh1 = sQh[(m0 + grp + 8) * APD + kb + tig];
            uint32_t qh2 = sQh[(m0 + grp)     * APD + kb + tig + 4];
            uint32_t qh3 = sQh[(m0 + grp + 8) * APD + kb + tig + 4];
            uint32_t ql0 = sQl[(m0 + grp)     * APD + kb + tig];
            uint32_t ql1 = sQl[(m0 + grp + 8) * APD + kb + tig];
            uint32_t ql2 = sQl[(m0 + grp)     * APD + kb + tig + 4];
            uint32_t ql3 = sQl[(m0 + grp + 8) * APD + kb + tig + 4];
#pragma unroll
            for (int nf = 0; nf < 8; nf++) {
                uint32_t bh0 = sKh[(nf * 8 + grp) * APD + kb + tig];
                uint32_t bh1 = sKh[(nf * 8 + grp) * APD + kb + tig + 4];
                uint32_t bl0 = sKl[(nf * 8 + grp) * APD + kb + tig];
                uint32_t bl1 = sKl[(nf * 8 + grp) * APD + kb + tig + 4];
                mma_f16(s[nf], qh0, qh1, qh2, qh3, bh0, bh1);
                mma_f16(s[nf], qh0, qh1, qh2, qh3, bl0, bl1);
                mma_f16(s[nf], ql0, ql1, ql2, ql3, bh0, bh1);
            }
        }

        if (jt == qblk) {
#pragma unroll
            for (int nf = 0; nf < 8; nf++) {
                int jc = nf * 8 + 2 * tig;
                int r1 = m0 + grp, r2 = r1 + 8;
                if (jc     > r1) s[nf][0] = -1e30f;
                if (jc + 1 > r1) s[nf][1] = -1e30f;
                if (jc     > r2) s[nf][2] = -1e30f;
                if (jc + 1 > r2) s[nf][3] = -1e30f;
            }
        }

        float tm1 = -1e30f, tm2 = -1e30f;
#pragma unroll
        for (int nf = 0; nf < 8; nf++) {
            tm1 = fmaxf(tm1, fmaxf(s[nf][0], s[nf][1]));
            tm2 = fmaxf(tm2, fmaxf(s[nf][2], s[nf][3]));
        }
        tm1 = fmaxf(tm1, __shfl_xor_sync(0xffffffffu, tm1, 1));
        tm1 = fmaxf(tm1, __shfl_xor_sync(0xffffffffu, tm1, 2));
        tm2 = fmaxf(tm2, __shfl_xor_sync(0xffffffffu, tm2, 1));
        tm2 = fmaxf(tm2, __shfl_xor_sync(0xffffffffu, tm2, 2));
        float mn1 = fmaxf(mr1, tm1), mn2 = fmaxf(mr2, tm2);
        float c1 = __expf(mr1 - mn1), c2 = __expf(mr2 - mn2);
        float ts1 = 0.f, ts2 = 0.f;
#pragma unroll
        for (int nf = 0; nf < 8; nf++) {
            s[nf][0] = __expf(s[nf][0] - mn1);
            s[nf][1] = __expf(s[nf][1] - mn1);
            s[nf][2] = __expf(s[nf][2] - mn2);
            s[nf][3] = __expf(s[nf][3] - mn2);
            ts1 += s[nf][0] + s[nf][1];
            ts2 += s[nf][2] + s[nf][3];
        }
        ts1 += __shfl_xor_sync(0xffffffffu, ts1, 1);
        ts1 += __shfl_xor_sync(0xffffffffu, ts1, 2);
        ts2 += __shfl_xor_sync(0xffffffffu, ts2, 1);
        ts2 += __shfl_xor_sync(0xffffffffu, ts2, 2);
        lr1 = lr1 * c1 + ts1;
        lr2 = lr2 * c2 + ts2;
        mr1 = mn1; mr2 = mn2;
#pragma unroll
        for (int nf = 0; nf < 8; nf++) {
            oacc[nf][0] *= c1; oacc[nf][1] *= c1;
            oacc[nf][2] *= c2; oacc[nf][3] *= c2;
        }

#pragma unroll
        for (int ks = 0; ks < 4; ks++) {
            uint32_t ph0, pl0, ph1, pl1, ph2, pl2, ph3, pl3;
            split2(s[2 * ks][0],     s[2 * ks][1],     ph0, pl0);
            split2(s[2 * ks][2],     s[2 * ks][3],     ph1, pl1);
            split2(s[2 * ks + 1][0], s[2 * ks + 1][1], ph2, pl2);
            split2(s[2 * ks + 1][2], s[2 * ks + 1][3], ph3, pl3);
#pragma unroll
            for (int nf = 0; nf < 8; nf++) {
                uint32_t bh0 = sVh[(nf * 8 + grp) * APD + ks * 8 + tig];
                uint32_t bh1 = sVh[(nf * 8 + grp) * APD + ks * 8 + tig + 4];
                uint32_t bl0 = sVl[(nf * 8 + grp) * APD + ks * 8 + tig];
                uint32_t bl1 = sVl[(nf * 8 + grp) * APD + ks * 8 + tig + 4];
                mma_f16(oacc[nf], ph0, ph1, ph2, ph3, bh0, bh1);
                mma_f16(oacc[nf], ph0, ph1, ph2, ph3, bl0, bl1);
                mma_f16(oacc[nf], pl0, pl1, pl2, pl3, bh0, bh1);
            }
        }
    }

    float inv1 = 1.f / lr1, inv2 = 1.f / lr2;
    size_t r1 = (size_t)(b * TT + qb + m0 + grp) * (CC / 2) + hd * 32;
    size_t r2 = r1 + 8 * (CC / 2);
#pragma unroll
    for (int nf = 0; nf < 8; nf++) {
        uint32_t h, l;
        split2(oacc[nf][0] * inv1, oacc[nf][1] * inv1, h, l);
        yh[r1 + nf * 4 + tig] = h; yl[r1 + nf * 4 + tig] = l;
        split2(oacc[nf][2] * inv2, oacc[nf][3] * inv2, h, l);
        yh[r2 + nf * 4 + tig] = h; yl[r2 + nf * 4 + tig] = l;
    }
}

// ---------------- host orchestration ----------------
extern "C" void kernel_launch(void* const* d_in, const int* in_sizes, int n_in,
                              void* d_out, int out_size) {
    const int*   idx   = (const int*)  d_in[0];
    const float* wte   = (const float*)d_in[1];
    const float* wpe   = (const float*)d_in[2];
    const float* ln1_g = (const float*)d_in[3];
    const float* ln1_b = (const float*)d_in[4];
    const float* wqkv  = (const float*)d_in[5];
    const float* bqkv  = (const float*)d_in[6];
    const float* wproj = (const float*)d_in[7];
    const float* bproj = (const float*)d_in[8];
    const float* ln2_g = (const float*)d_in[9];
    const float* ln2_b = (const float*)d_in[10];
    const float* wfc   = (const float*)d_in[11];
    const float* bfc   = (const float*)d_in[12];
    const float* wfc2  = (const float*)d_in[13];
    const float* bfc2  = (const float*)d_in[14];
    const float* lnf_g = (const float*)d_in[15];
    const float* lnf_b = (const float*)d_in[16];
    const float* lm_w  = (const float*)d_in[17];
    float* out = (float*)d_out;

    float *x, *qkv;
    uint32_t *lnh, *lnl, *acth, *actl;
    uint32_t *wqh, *wql, *wph, *wpl, *wfh, *wfl, *w2h, *w2l, *lmh, *lml;
    cudaGetSymbolAddress((void**)&x,    g_x);
    cudaGetSymbolAddress((void**)&qkv,  g_qkv);
    cudaGetSymbolAddress((void**)&lnh,  g_lnh);
    cudaGetSymbolAddress((void**)&lnl,  g_lnl);
    cudaGetSymbolAddress((void**)&acth, g_acth);
    cudaGetSymbolAddress((void**)&actl, g_actl);
    cudaGetSymbolAddress((void**)&wqh,  g_wqkvh);
    cudaGetSymbolAddress((void**)&wql,  g_wqkvl);
    cudaGetSymbolAddress((void**)&wph,  g_wprjh);
    cudaGetSymbolAddress((void**)&wpl,  g_wprjl);
    cudaGetSymbolAddress((void**)&wfh,  g_wfch);
    cudaGetSymbolAddress((void**)&wfl,  g_wfcl);
    cudaGetSymbolAddress((void**)&w2h,  g_wfc2h);
    cudaGetSymbolAddress((void**)&w2l,  g_wfc2l);
    cudaGetSymbolAddress((void**)&lmh,  g_lmwh);
    cudaGetSymbolAddress((void**)&lml,  g_lmwl);

    cudaFuncSetAttribute(gemm_mma<1, 0, 3>, cudaFuncAttributeMaxDynamicSharedMemorySize, GSMEM);
    cudaFuncSetAttribute(gemm_mma<0, 0, 1>, cudaFuncAttributeMaxDynamicSharedMemorySize, GSMEM);
    cudaFuncSetAttribute(gemm_mma64<5, 0>, cudaFuncAttributeMaxDynamicSharedMemorySize, GSMEM64);
    cudaFuncSetAttribute(gemm_mma64<3, 1>, cudaFuncAttributeMaxDynamicSharedMemorySize, GSMEM64);
    cudaFuncSetAttribute(attn_mma_kernel, cudaFuncAttributeMaxDynamicSharedMemorySize, ASMEM);

    // ---- weight conversions (once per call) ----
    convert_w<<<dim3((C3 + 1023) / 1024, LL * CC / 2), 256>>>(wqkv,  wqh, wql, C3, C3);
    convert_w<<<dim3((CC + 1023) / 1024, LL * CC / 2), 256>>>(wproj, wph, wpl, CC, CC);
    convert_w<<<dim3((C4 + 1023) / 1024, LL * CC / 2), 256>>>(wfc,   wfh, wfl, C4, C4);
    convert_w<<<dim3((CC + 1023) / 1024, LL * C4 / 2), 256>>>(wfc2,  w2h, w2l, CC, CC);
    convert_w<<<dim3((VP + 1023) / 1024, CC / 2),      256>>>(lm_w,  lmh, lml, VV, VP);

    embed_kernel<<<MR, 256>>>(idx, wte, wpe);

    for (int l = 0; l < LL; l++) {
        ln_kernel<<<MR, 256>>>(x, ln1_g + (size_t)l * CC, ln1_b + (size_t)l * CC, lnh, lnl);

        // qkv = ln @ wqkv + bqkv  [2048 x 2304], fp32 out (128-tile, 288 CTAs = full wave)
        gemm_mma<1, 0, 3><<<dim3(16, C3 / 128), 256, GSMEM>>>(
            lnh, lnl, CC / 2,
            wqh + (size_t)l * (CC / 2) * C3, wql + (size_t)l * (CC / 2) * C3, C3,
            bqkv + (size_t)l * C3, nullptr, qkv, nullptr, nullptr, C3);

        attn_mma_kernel<<<dim3(TT / 64, HH, BB), 128, ASMEM>>>(qkv, acth, actl);

        // x = x + y @ wproj + bproj  (64x64 tiles: 32x12 = 384 CTAs, all SMs busy)
        gemm_mma64<5, 0><<<dim3(32, 12), 256, GSMEM64>>>(
            acth, actl, CC / 2,
            wph + (size_t)l * (CC / 2) * CC, wpl + (size_t)l * (CC / 2) * CC, CC,
            bproj + (size_t)l * CC, x, x, nullptr, nullptr, CC);

        ln_kernel<<<MR, 256>>>(x, ln2_g + (size_t)l * CC, ln2_b + (size_t)l * CC, lnh, lnl);

        // fc = gelu(ln @ wfc + bfc), pair-plane out  (64x64: 32x48 CTAs)
        gemm_mma64<3, 1><<<dim3(32, C4 / 64), 256, GSMEM64>>>(
            lnh, lnl, CC / 2,
            wfh + (size_t)l * (CC / 2) * C4, wfl + (size_t)l * (CC / 2) * C4, C4,
            bfc + (size_t)l * C4, nullptr, nullptr, acth, actl, C4);

        // x = x + fc @ wfc2 + bfc2  (64x64: 32x12 CTAs)
        gemm_mma64<5, 0><<<dim3(32, 12), 256, GSMEM64>>>(
            acth, actl, C4 / 2,
            w2h + (size_t)l * (C4 / 2) * CC, w2l + (size_t)l * (C4 / 2) * CC, CC,
            bfc2 + (size_t)l * CC, x, x, nullptr, nullptr, CC);
    }

    ln_kernel<<<MR, 256>>>(x, lnf_g, lnf_b, lnh, lnl);

    // logits = ln @ lm_w  [2048 x 50257] — single-pass fp16 (error leaf)
    gemm_mma<0, 0, 1><<<dim3(16, VP / 128), 256, GSMEM>>>(
        lnh, lnl, CC / 2, lmh, lml, VP,
        nullptr, nullptr, out, nullptr, nullptr, VV);
}

// round 14
// speedup vs baseline: 4.2921x; 1.0539x over previous
#include <cuda_runtime.h>
#include <cuda_fp16.h>
#include <math.h>
#include <stdint.h>

// ---------------- problem constants ----------------
#define BB   2
#define TT   1024
#define CC   768
#define HH   12
#define DD   64
#define LL   12
#define VV   50257
#define MR   2048
#define C3   2304
#define C4   3072
#define VP   50304   // VV padded to multiple of 128

// ---------------- fp32 buffers ----------------
__device__ float g_x  [MR*CC];   // residual stream
__device__ float g_qkv[MR*C3];   // qkv (attention input)

// ---------------- activation hi/lo pair planes (u32 = half2(k_even, k_odd)) ----------------
__device__ uint32_t g_lnh [MR*(CC/2)], g_lnl [MR*(CC/2)];    // LN outputs
__device__ uint32_t g_acth[MR*(C4/2)], g_actl[MR*(C4/2)];    // y (stride 384) / fc (stride 1536)

// ---------------- weight hi/lo pair planes ----------------
__device__ uint32_t g_wqkvh[LL*(CC/2)*C3], g_wqkvl[LL*(CC/2)*C3];
__device__ uint32_t g_wprjh[LL*(CC/2)*CC], g_wprjl[LL*(CC/2)*CC];
__device__ uint32_t g_wfch [LL*(CC/2)*C4], g_wfcl [LL*(CC/2)*C4];
__device__ uint32_t g_wfc2h[LL*(C4/2)*CC], g_wfc2l[LL*(C4/2)*CC];
__device__ uint32_t g_lmwh [(CC/2)*VP];

// ---------------- helpers ----------------
__device__ __forceinline__ uint32_t smem_u32(const void* p) {
    uint32_t a;
    asm("{ .reg .u64 t; cvta.to.shared.u64 t, %1; cvt.u32.u64 %0, t; }" : "=r"(a) : "l"(p));
    return a;
}

__device__ __forceinline__ void mma_f16(float* c, uint32_t a0, uint32_t a1,
                                        uint32_t a2, uint32_t a3,
                                        uint32_t b0, uint32_t b1) {
    asm volatile(
        "mma.sync.aligned.m16n8k16.row.col.f32.f16.f16.f32 "
        "{%0,%1,%2,%3}, {%4,%5,%6,%7}, {%8,%9}, {%0,%1,%2,%3};"
        : "+f"(c[0]), "+f"(c[1]), "+f"(c[2]), "+f"(c[3])
        : "r"(a0), "r"(a1), "r"(a2), "r"(a3), "r"(b0), "r"(b1));
}

// pack two floats into (hi, lo) half2 words; elem0 (low 16 bits) = first arg
__device__ __forceinline__ void split2(float a, float b, uint32_t& hi, uint32_t& lo) {
    __half ha = __float2half_rn(a), hb = __float2half_rn(b);
    float ra = a - __half2float(ha), rb = b - __half2float(hb);
    __half la = __float2half_rn(ra), lb = __float2half_rn(rb);
    hi = (uint32_t)__half_as_ushort(ha) | ((uint32_t)__half_as_ushort(hb) << 16);
    lo = (uint32_t)__half_as_ushort(la) | ((uint32_t)__half_as_ushort(lb) << 16);
}

__device__ __forceinline__ void cp16(uint32_t s, const void* g) {
    asm volatile("cp.async.cg.shared.global [%0], [%1], 16;" :: "r"(s), "l"(g));
}

__device__ __forceinline__ float gelu_f(float x) {
    float x3 = x * x * x;
    return 0.5f * x * (1.0f + tanhf(0.7978845608028654f * (x + 0.044715f * x3)));
}

// ---------------- weight conversion: [K][N] fp32 -> pair planes [K/2][NP] ----------------
__global__ void convert_w(const float* __restrict__ w, uint32_t* __restrict__ ph,
                          uint32_t* __restrict__ pl, int N, int NP) {
    int kp = blockIdx.y;
    int n0 = (blockIdx.x * 256 + threadIdx.x) * 4;
    if (n0 >= NP) return;
    const float* r0 = w + (size_t)(2 * kp) * N;
    const float* r1 = r0 + N;
    uint32_t h[4], l[4];
#pragma unroll
    for (int j = 0; j < 4; j++) {
        int n = n0 + j;
        float a = (n < N) ? r0[n] : 0.f;
        float b = (n < N) ? r1[n] : 0.f;
        split2(a, b, h[j], l[j]);
    }
    *(uint4*)&ph[(size_t)kp * NP + n0] = make_uint4(h[0], h[1], h[2], h[3]);
    if (pl) *(uint4*)&pl[(size_t)kp * NP + n0] = make_uint4(l[0], l[1], l[2], l[3]);
}

// ---------------- embedding ----------------
__global__ void embed_kernel(const int* __restrict__ idx,
                             const float* __restrict__ wte,
                             const float* __restrict__ wpe) {
    int row = blockIdx.x;
    int t   = row % TT;
    int tok = idx[row];
    const float* we = wte + (size_t)tok * CC;
    const float* wp = wpe + (size_t)t   * CC;
    float* out = g_x + (size_t)row * CC;
    for (int i = threadIdx.x; i < CC; i += blockDim.x)
        out[i] = we[i] + wp[i];
}

// ---------------- layernorm: warp-per-row, shuffle-only reduce ----------------
__global__ __launch_bounds__(256)
void ln_kernel(const float* __restrict__ x,
               const float* __restrict__ g,
               const float* __restrict__ b,
               uint32_t* __restrict__ outh, uint32_t* __restrict__ outl) {
    int warp = threadIdx.x >> 5, lane = threadIdx.x & 31;
    int row = blockIdx.x * 8 + warp;
    const float* xr = x + (size_t)row * CC;

    float4 v[6];
    float s = 0.f, s2 = 0.f;
#pragma unroll
    for (int j = 0; j < 6; j++) {
        v[j] = *(const float4*)(xr + (lane + 32 * j) * 4);
        s  += v[j].x + v[j].y + v[j].z + v[j].w;
        s2 += v[j].x * v[j].x + v[j].y * v[j].y + v[j].z * v[j].z + v[j].w * v[j].w;
    }
#pragma unroll
    for (int o = 16; o; o >>= 1) {
        s  += __shfl_xor_sync(0xffffffffu, s,  o);
        s2 += __shfl_xor_sync(0xffffffffu, s2, o);
    }
    float mean = s * (1.0f / CC);
    float var  = s2 * (1.0f / CC) - mean * mean;
    float rstd = rsqrtf(var + 1e-5f);

    size_t ro = (size_t)row * (CC / 2);
#pragma unroll
    for (int j = 0; j < 6; j++) {
        int f = lane + 32 * j;          // float4 index; covers floats 4f..4f+3
        float4 gv = *(const float4*)(g + 4 * f);
        float4 bv = *(const float4*)(b + 4 * f);
        float a0 = (v[j].x - mean) * rstd * gv.x + bv.x;
        float a1 = (v[j].y - mean) * rstd * gv.y + bv.y;
        float a2 = (v[j].z - mean) * rstd * gv.z + bv.z;
        float a3 = (v[j].w - mean) * rstd * gv.w + bv.w;
        uint32_t h0, l0, h1, l1;
        split2(a0, a1, h0, l0);
        split2(a2, a3, h1, l1);
        *(uint2*)&outh[ro + 2 * f] = make_uint2(h0, h1);
        *(uint2*)&outl[ro + 2 * f] = make_uint2(l0, l1);
    }
}

// ---------------- fp16-split mma GEMM, 128x128 tile, cp.async double-buffer ----------------
// EPI bits: 1=+bias, 2=gelu, 4=+residual.  OUTM: 0 = fp32 C, 1 = pair planes.
// PASSES: 3 = hi/lo split (exact), 1 = fp16 hi-only (LM head leaf).
#define PA 20      // u32 row stride of A tile (16 pairs + 4 pad)
#define PB 136     // u32 row stride of B tile (128 + 8 pad, conflict-free)
#define STG 9472   // u32 per stage: 2*128*20 + 2*16*136
#define OFF_AL 2560
#define OFF_BH 5120
#define OFF_BL 7296
#define GSMEM (2 * STG * 4)   // 75776 bytes

template<int EPI, int OUTM, int PASSES>
__global__ __launch_bounds__(256, 2)
void gemm_mma(const uint32_t* __restrict__ Ah, const uint32_t* __restrict__ Al, int KH,
              const uint32_t* __restrict__ Bh, const uint32_t* __restrict__ Bl, int NP,
              const float* __restrict__ bias, const float* __restrict__ res,
              float* __restrict__ C, uint32_t* __restrict__ Ch, uint32_t* __restrict__ Cl,
              int N) {
    extern __shared__ __align__(16) uint32_t sm[];
    const int t = threadIdx.x;
    const int wid = t >> 5, lane = t & 31;
    const int grp = lane >> 2, tig = lane & 3;
    const int warp_m = wid >> 2;          // 0..1
    const int warp_n = wid & 3;           // 0..3
    const int m0 = blockIdx.x * 128;
    const int n0 = blockIdx.y * 128;
    const uint32_t sb = smem_u32(sm);

    float acc[4][4][4];
#pragma unroll
    for (int im = 0; im < 4; im++)
#pragma unroll
        for (int in = 0; in < 4; in++)
#pragma unroll
            for (int r = 0; r < 4; r++) acc[im][in][r] = 0.f;

    const int nch = KH / 16;

    auto prefetch = [&](int c, int st) {
        uint32_t base = sb + (uint32_t)st * STG * 4;
        int k0 = c * 16;
#pragma unroll
        for (int i = 0; i < 2; i++) {
            int idx = t + i * 256;
            int row = idx >> 2, ch = (idx & 3) * 4;
            size_t go = (size_t)(m0 + row) * KH + k0 + ch;
            cp16(base + (row * PA + ch) * 4, Ah + go);
            if (PASSES == 3) cp16(base + (OFF_AL + row * PA + ch) * 4, Al + go);
        }
#pragma unroll
        for (int i = 0; i < 2; i++) {
            int idx = t + i * 256;
            int kp = idx >> 5, ch = (idx & 31) * 4;
            size_t go = (size_t)(k0 + kp) * NP + n0 + ch;
            cp16(base + (OFF_BH + kp * PB + ch) * 4, Bh + go);
            if (PASSES == 3) cp16(base + (OFF_BL + kp * PB + ch) * 4, Bl + go);
        }
        asm volatile("cp.async.commit_group;" ::: "memory");
    };

    prefetch(0, 0);
    for (int c = 0; c < nch; c++) {
        if (c + 1 < nch) {
            prefetch(c + 1, (c + 1) & 1);
            asm volatile("cp.async.wait_group 1;" ::: "memory");
        } else {
            asm volatile("cp.async.wait_group 0;" ::: "memory");
        }
        __syncthreads();
        const uint32_t* S = sm + (c & 1) * STG;
#pragma unroll
        for (int ks = 0; ks < 2; ks++) {
            const int kb = ks * 8;
            uint32_t ah[4][4], al[4][4];
#pragma unroll
            for (int im = 0; im < 4; im++) {
                int r0 = (warp_m * 64 + im * 16 + grp) * PA;
                int r1 = r0 + 8 * PA;
                ah[im][0] = S[r0 + kb + tig];
                ah[im][1] = S[r1 + kb + tig];
                ah[im][2] = S[r0 + kb + tig + 4];
                ah[im][3] = S[r1 + kb + tig + 4];
                if (PASSES == 3) {
                    al[im][0] = S[OFF_AL + r0 + kb + tig];
                    al[im][1] = S[OFF_AL + r1 + kb + tig];
                    al[im][2] = S[OFF_AL + r0 + kb + tig + 4];
                    al[im][3] = S[OFF_AL + r1 + kb + tig + 4];
                }
            }
            uint32_t bh[4][2], bl[4][2];
#pragma unroll
            for (int in = 0; in < 4; in++) {
                int nb = warp_n * 32 + in * 8 + grp;
                bh[in][0] = S[OFF_BH + (kb + tig) * PB + nb];
                bh[in][1] = S[OFF_BH + (kb + tig + 4) * PB + nb];
                if (PASSES == 3) {
                    bl[in][0] = S[OFF_BL + (kb + tig) * PB + nb];
                    bl[in][1] = S[OFF_BL + (kb + tig + 4) * PB + nb];
                }
            }
#pragma unroll
            for (int im = 0; im < 4; im++)
#pragma unroll
                for (int in = 0; in < 4; in++) {
                    mma_f16(acc[im][in], ah[im][0], ah[im][1], ah[im][2], ah[im][3],
                            bh[in][0], bh[in][1]);
                    if (PASSES == 3) {
                        mma_f16(acc[im][in], ah[im][0], ah[im][1], ah[im][2], ah[im][3],
                                bl[in][0], bl[in][1]);
                        mma_f16(acc[im][in], al[im][0], al[im][1], al[im][2], al[im][3],
                                bh[in][0], bh[in][1]);
                    }
                }
        }
        __syncthreads();
    }

    // ---- epilogue ----
    const bool n2 = ((N & 1) == 0);
#pragma unroll
    for (int im = 0; im < 4; im++) {
        int r0 = m0 + warp_m * 64 + im * 16 + grp;
        int r1 = r0 + 8;
#pragma unroll
        for (int in = 0; in < 4; in++) {
            int nc = n0 + warp_n * 32 + in * 8 + tig * 2;
            float v00 = acc[im][in][0], v01 = acc[im][in][1];
            float v10 = acc[im][in][2], v11 = acc[im][in][3];
            if (EPI & 1) {
                float b0v = (nc < N) ? bias[nc] : 0.f;
                float b1v = (nc + 1 < N) ? bias[nc + 1] : 0.f;
                v00 += b0v; v10 += b0v; v01 += b1v; v11 += b1v;
            }
            if (EPI & 2) {
                v00 = gelu_f(v00); v01 = gelu_f(v01);
                v10 = gelu_f(v10); v11 = gelu_f(v11);
            }
            if (EPI & 4) {
                if (nc < N) { v00 += res[(size_t)r0 * N + nc]; v10 += res[(size_t)r1 * N + nc]; }
                if (nc + 1 < N) { v01 += res[(size_t)r0 * N + nc + 1]; v11 += res[(size_t)r1 * N + nc + 1]; }
            }
            if (OUTM == 1) {
                uint32_t ph, pl;
                split2(v00, v01, ph, pl);
                Ch[(size_t)r0 * (N / 2) + nc / 2] = ph;
                Cl[(size_t)r0 * (N / 2) + nc / 2] = pl;
                split2(v10, v11, ph, pl);
                Ch[(size_t)r1 * (N / 2) + nc / 2] = ph;
                Cl[(size_t)r1 * (N / 2) + nc / 2] = pl;
            } else {
                if (n2 && nc + 1 < N) {
                    *(float2*)(C + (size_t)r0 * N + nc) = make_float2(v00, v01);
                    *(float2*)(C + (size_t)r1 * N + nc) = make_float2(v10, v11);
                } else {
                    if (nc < N)     { C[(size_t)r0 * N + nc]     = v00; C[(size_t)r1 * N + nc]     = v10; }
                    if (nc + 1 < N) { C[(size_t)r0 * N + nc + 1] = v01; C[(size_t)r1 * N + nc + 1] = v11; }
                }
            }
        }
    }
}

// ---------------- 64x128-tile variant (M-split wave-fill for proj / fc2) ----------------
// 8 warps 2x4; warp tile 32x32; 3-pass split. 11 B smem traffic / output.
#define STGM 6912             // 64*20*2 + 16*136*2
#define OFF_ALM 1280
#define OFF_BHM 2560
#define OFF_BLM 4736
#define GSMEMM (2 * STGM * 4) // 55296 bytes

template<int EPI, int OUTM>
__global__ __launch_bounds__(256, 2)
void gemm_mmaM64(const uint32_t* __restrict__ Ah, const uint32_t* __restrict__ Al, int KH,
                 const uint32_t* __restrict__ Bh, const uint32_t* __restrict__ Bl, int NP,
                 const float* __restrict__ bias, const float* __restrict__ res,
                 float* __restrict__ C, uint32_t* __restrict__ Ch, uint32_t* __restrict__ Cl,
                 int N) {
    extern __shared__ __align__(16) uint32_t sm[];
    const int t = threadIdx.x;
    const int wid = t >> 5, lane = t & 31;
    const int grp = lane >> 2, tig = lane & 3;
    const int warp_m = wid >> 2;          // 0..1  (32-row strips)
    const int warp_n = wid & 3;           // 0..3  (32-col strips)
    const int m0 = blockIdx.x * 64;
    const int n0 = blockIdx.y * 128;
    const uint32_t sb = smem_u32(sm);

    float acc[2][4][4];
#pragma unroll
    for (int im = 0; im < 2; im++)
#pragma unroll
        for (int in = 0; in < 4; in++)
#pragma unroll
            for (int r = 0; r < 4; r++) acc[im][in][r] = 0.f;

    const int nch = KH / 16;

    auto prefetch = [&](int c, int st) {
        uint32_t base = sb + (uint32_t)st * STGM * 4;
        int k0 = c * 16;
        {   // A: 64 rows x 16 pairs, hi+lo
            int row = t >> 2, ch = (t & 3) * 4;
            size_t go = (size_t)(m0 + row) * KH + k0 + ch;
            cp16(base + (row * PA + ch) * 4, Ah + go);
            cp16(base + (OFF_ALM + row * PA + ch) * 4, Al + go);
        }
#pragma unroll
        for (int i = 0; i < 2; i++) {   // B: 16 kp x 128 n, hi+lo
            int idx = t + i * 256;
            int kp = idx >> 5, ch = (idx & 31) * 4;
            size_t go = (size_t)(k0 + kp) * NP + n0 + ch;
            cp16(base + (OFF_BHM + kp * PB + ch) * 4, Bh + go);
            cp16(base + (OFF_BLM + kp * PB + ch) * 4, Bl + go);
        }
        asm volatile("cp.async.commit_group;" ::: "memory");
    };

    prefetch(0, 0);
    for (int c = 0; c < nch; c++) {
        if (c + 1 < nch) {
            prefetch(c + 1, (c + 1) & 1);
            asm volatile("cp.async.wait_group 1;" ::: "memory");
        } else {
            asm volatile("cp.async.wait_group 0;" ::: "memory");
        }
        __syncthreads();
        const uint32_t* S = sm + (c & 1) * STGM;
#pragma unroll
        for (int ks = 0; ks < 2; ks++) {
            const int kb = ks * 8;
            uint32_t ah[2][4], al[2][4];
#pragma unroll
            for (int im = 0; im < 2; im++) {
                int r0 = (warp_m * 32 + im * 16 + grp) * PA;
                int r1 = r0 + 8 * PA;
                ah[im][0] = S[r0 + kb + tig];
                ah[im][1] = S[r1 + kb + tig];
                ah[im][2] = S[r0 + kb + tig + 4];
                ah[im][3] = S[r1 + kb + tig + 4];
                al[im][0] = S[OFF_ALM + r0 + kb + tig];
                al[im][1] = S[OFF_ALM + r1 + kb + tig];
                al[im][2] = S[OFF_ALM + r0 + kb + tig + 4];
                al[im][3] = S[OFF_ALM + r1 + kb + tig + 4];
            }
            uint32_t bh[4][2], bl[4][2];
#pragma unroll
            for (int in = 0; in < 4; in++) {
                int nb = warp_n * 32 + in * 8 + grp;
                bh[in][0] = S[OFF_BHM + (kb + tig) * PB + nb];
                bh[in][1] = S[OFF_BHM + (kb + tig + 4) * PB + nb];
                bl[in][0] = S[OFF_BLM + (kb + tig) * PB + nb];
                bl[in][1] = S[OFF_BLM + (kb + tig + 4) * PB + nb];
            }
#pragma unroll
            for (int im = 0; im < 2; im++)
#pragma unroll
                for (int in = 0; in < 4; in++) {
                    mma_f16(acc[im][in], ah[im][0], ah[im][1], ah[im][2], ah[im][3],
                            bh[in][0], bh[in][1]);
                    mma_f16(acc[im][in], ah[im][0], ah[im][1], ah[im][2], ah[im][3],
                            bl[in][0], bl[in][1]);
                    mma_f16(acc[im][in], al[im][0], al[im][1], al[im][2], al[im][3],
                            bh[in][0], bh[in][1]);
                }
        }
        __syncthreads();
    }

    // ---- epilogue ----
#pragma unroll
    for (int im = 0; im < 2; im++) {
        int r0 = m0 + warp_m * 32 + im * 16 + grp;
        int r1 = r0 + 8;
#pragma unroll
        for (int in = 0; in < 4; in++) {
            int nc = n0 + warp_n * 32 + in * 8 + tig * 2;
            float v00 = acc[im][in][0], v01 = acc[im][in][1];
            float v10 = acc[im][in][2], v11 = acc[im][in][3];
            if (EPI & 1) {
                float b0v = bias[nc], b1v = bias[nc + 1];
                v00 += b0v; v10 += b0v; v01 += b1v; v11 += b1v;
            }
            if (EPI & 2) {
                v00 = gelu_f(v00); v01 = gelu_f(v01);
                v10 = gelu_f(v10); v11 = gelu_f(v11);
            }
            if (EPI & 4) {
                v00 += res[(size_t)r0 * N + nc];
                v01 += res[(size_t)r0 * N + nc + 1];
                v10 += res[(size_t)r1 * N + nc];
                v11 += res[(size_t)r1 * N + nc + 1];
            }
            if (OUTM == 1) {
                uint32_t ph, pl;
                split2(v00, v01, ph, pl);
                Ch[(size_t)r0 * (N / 2) + nc / 2] = ph;
                Cl[(size_t)r0 * (N / 2) + nc / 2] = pl;
                split2(v10, v11, ph, pl);
                Ch[(size_t)r1 * (N / 2) + nc / 2] = ph;
                Cl[(size_t)r1 * (N / 2) + nc / 2] = pl;
            } else {
                *(float2*)(C + (size_t)r0 * N + nc) = make_float2(v00, v01);
                *(float2*)(C + (size_t)r1 * N + nc) = make_float2(v10, v11);
            }
        }
    }
}

// ---------------- MMA flash-attention (fp16 split, online softmax) ----------------
#define APD 36
#define APLANE (64 * APD)                // 2304 u32
#define ASMEM (6 * APLANE * 4)           // 55296 bytes

__global__ __launch_bounds__(128, 3)
void attn_mma_kernel(const float* __restrict__ qkv,
                     uint32_t* __restrict__ yh, uint32_t* __restrict__ yl) {
    extern __shared__ __align__(16) uint32_t as[];
    uint32_t* sQh = as;
    uint32_t* sQl = as + APLANE;
    uint32_t* sKh = as + 2 * APLANE;
    uint32_t* sKl = as + 3 * APLANE;
    uint32_t* sVh = as + 4 * APLANE;     // [d][jpair]
    uint32_t* sVl = as + 5 * APLANE;

    const int t = threadIdx.x;
    const int warp = t >> 5, lane = t & 31;
    const int grp = lane >> 2, tig = lane & 3;
    const int hd = blockIdx.y, b = blockIdx.z;
    const int qblk = gridDim.x - 1 - blockIdx.x;   // long blocks first
    const int qb = qblk * 64;
    const int m0 = warp * 16;

    {
        const float* Qb = qkv + ((size_t)(b * TT + qb)) * C3 + hd * DD;
#pragma unroll
        for (int i = 0; i < 8; i++) {
            int idx = t + i * 128;
            int row = idx >> 4, c4 = idx & 15;
            float4 v = *(const float4*)(Qb + (size_t)row * C3 + c4 * 4);
            uint32_t h0, l0, h1, l1;
            split2(v.x * 0.125f, v.y * 0.125f, h0, l0);
            split2(v.z * 0.125f, v.w * 0.125f, h1, l1);
            sQh[row * APD + 2 * c4]     = h0;
            sQh[row * APD + 2 * c4 + 1] = h1;
            sQl[row * APD + 2 * c4]     = l0;
            sQl[row * APD + 2 * c4 + 1] = l1;
        }
    }

    const float* Kb = qkv + (size_t)b * TT * C3 + CC     + hd * DD;
    const float* Vb = qkv + (size_t)b * TT * C3 + 2 * CC + hd * DD;

    float oacc[8][4];
#pragma unroll
    for (int nf = 0; nf < 8; nf++)
#pragma unroll
        for (int e = 0; e < 4; e++) oacc[nf][e] = 0.f;
    float mr1 = -1e30f, mr2 = -1e30f, lr1 = 0.f, lr2 = 0.f;

    for (int jt = 0; jt <= qblk; jt++) {
        const int j0 = jt * 64;
        __syncthreads();
#pragma unroll
        for (int i = 0; i < 8; i++) {
            int idx = t + i * 128;
            int row = idx >> 4, c4 = idx & 15;
            float4 v = *(const float4*)(Kb + (size_t)(j0 + row) * C3 + c4 * 4);
            uint32_t h0, l0, h1, l1;
            split2(v.x, v.y, h0, l0);
            split2(v.z, v.w, h1, l1);
            sKh[row * APD + 2 * c4]     = h0;
            sKh[row * APD + 2 * c4 + 1] = h1;
            sKl[row * APD + 2 * c4]     = l0;
            sKl[row * APD + 2 * c4 + 1] = l1;
        }
#pragma unroll
        for (int i = 0; i < 16; i++) {
            int w = t + i * 128;
            int d = w & 63, jp = w >> 6;
            float v0 = Vb[(size_t)(j0 + 2 * jp)     * C3 + d];
            float v1 = Vb[(size_t)(j0 + 2 * jp + 1) * C3 + d];
            uint32_t h, l;
            split2(v0, v1, h, l);
            sVh[d * APD + jp] = h;
            sVl[d * APD + jp] = l;
        }
        __syncthreads();

        float s[8][4];
#pragma unroll
        for (int nf = 0; nf < 8; nf++)
#pragma unroll
            for (int e = 0; e < 4; e++) s[nf][e] = 0.f;

#pragma unroll
        for (int ks = 0; ks < 4; ks++) {
            const int kb = ks * 8;
            uint32_t qh0 = sQh[(m0 + grp)     * APD + kb + tig];
            uint32_t qh1 = sQh[(m0 + grp + 8) * APD + kb + tig];
            uint32_t qh2 = sQh[(m0 + grp)     * APD + kb + tig + 4];
            uint32_t qh3 = sQh[(m0 + grp + 8) * APD + kb + tig + 4];
            uint32_t ql0 = sQl[(m0 + grp)     * APD + kb + tig];
            uint32_t ql1 = sQl[(m0 + grp + 8) * APD + kb + tig];
            uint32_t ql2 = sQl[(m0 + grp)     * APD + kb + tig + 4];
            uint32_t ql3 = sQl[(m0 + grp + 8) * APD + kb + tig + 4];
#pragma unroll
            for (int nf = 0; nf < 8; nf++) {
                uint32_t bh0 = sKh[(nf * 8 + grp) * APD + kb + tig];
                uint32_t bh1 = sKh[(nf * 8 + grp) * APD + kb + tig + 4];
                uint32_t bl0 = sKl[(nf * 8 + grp) * APD + kb + tig];
                uint32_t bl1 = sKl[(nf * 8 + grp) * APD + kb + tig + 4];
                mma_f16(s[nf], qh0, qh1, qh2, qh3, bh0, bh1);
                mma_f16(s[nf], qh0, qh1, qh2, qh3, bl0, bl1);
                mma_f16(s[nf], ql0, ql1, ql2, ql3, bh0, bh1);
            }
        }

        if (jt == qblk) {
#pragma unroll
            for (int nf = 0; nf < 8; nf++) {
                int jc = nf * 8 + 2 * tig;
                int r1 = m0 + grp, r2 = r1 + 8;
                if (jc     > r1) s[nf][0] = -1e30f;
                if (jc + 1 > r1) s[nf][1] = -1e30f;
                if (jc     > r2) s[nf][2] = -1e30f;
                if (jc + 1 > r2) s[nf][3] = -1e30f;
            }
        }

        float tm1 = -1e30f, tm2 = -1e30f;
#pragma unroll
        for (int nf = 0; nf < 8; nf++) {
            tm1 = fmaxf(tm1, fmaxf(s[nf][0], s[nf][1]));
            tm2 = fmaxf(tm2, fmaxf(s[nf][2], s[nf][3]));
        }
        tm1 = fmaxf(tm1, __shfl_xor_sync(0xffffffffu, tm1, 1));
        tm1 = fmaxf(tm1, __shfl_xor_sync(0xffffffffu, tm1, 2));
        tm2 = fmaxf(tm2, __shfl_xor_sync(0xffffffffu, tm2, 1));
        tm2 = fmaxf(tm2, __shfl_xor_sync(0xffffffffu, tm2, 2));
        float mn1 = fmaxf(mr1, tm1), mn2 = fmaxf(mr2, tm2);
        float c1 = __expf(mr1 - mn1), c2 = __expf(mr2 - mn2);
        float ts1 = 0.f, ts2 = 0.f;
#pragma unroll
        for (int nf = 0; nf < 8; nf++) {
            s[nf][0] = __expf(s[nf][0] - mn1);
            s[nf][1] = __expf(s[nf][1] - mn1);
            s[nf][2] = __expf(s[nf][2] - mn2);
            s[nf][3] = __expf(s[nf][3] - mn2);
            ts1 += s[nf][0] + s[nf][1];
            ts2 += s[nf][2] + s[nf][3];
        }
        ts1 += __shfl_xor_sync(0xffffffffu, ts1, 1);
        ts1 += __shfl_xor_sync(0xffffffffu, ts1, 2);
        ts2 += __shfl_xor_sync(0xffffffffu, ts2, 1);
        ts2 += __shfl_xor_sync(0xffffffffu, ts2, 2);
        lr1 = lr1 * c1 + ts1;
        lr2 = lr2 * c2 + ts2;
        mr1 = mn1; mr2 = mn2;
#pragma unroll
        for (int nf = 0; nf < 8; nf++) {
            oacc[nf][0] *= c1; oacc[nf][1] *= c1;
            oacc[nf][2] *= c2; oacc[nf][3] *= c2;
        }

#pragma unroll
        for (int ks = 0; ks < 4; ks++) {
            uint32_t ph0, pl0, ph1, pl1, ph2, pl2, ph3, pl3;
            split2(s[2 * ks][0],     s[2 * ks][1],     ph0, pl0);
            split2(s[2 * ks][2],     s[2 * ks][3],     ph1, pl1);
            split2(s[2 * ks + 1][0], s[2 * ks + 1][1], ph2, pl2);
            split2(s[2 * ks + 1][2], s[2 * ks + 1][3], ph3, pl3);
#pragma unroll
            for (int nf = 0; nf < 8; nf++) {
                uint32_t bh0 = sVh[(nf * 8 + grp) * APD + ks * 8 + tig];
                uint32_t bh1 = sVh[(nf * 8 + grp) * APD + ks * 8 + tig + 4];
                uint32_t bl0 = sVl[(nf * 8 + grp) * APD + ks * 8 + tig];
                uint32_t bl1 = sVl[(nf * 8 + grp) * APD + ks * 8 + tig + 4];
                mma_f16(oacc[nf], ph0, ph1, ph2, ph3, bh0, bh1);
                mma_f16(oacc[nf], ph0, ph1, ph2, ph3, bl0, bl1);
                mma_f16(oacc[nf], pl0, pl1, pl2, pl3, bh0, bh1);
            }
        }
    }

    float inv1 = 1.f / lr1, inv2 = 1.f / lr2;
    size_t r1 = (size_t)(b * TT + qb + m0 + grp) * (CC / 2) + hd * 32;
    size_t r2 = r1 + 8 * (CC / 2);
#pragma unroll
    for (int nf = 0; nf < 8; nf++) {
        uint32_t h, l;
        split2(oacc[nf][0] * inv1, oacc[nf][1] * inv1, h, l);
        yh[r1 + nf * 4 + tig] = h; yl[r1 + nf * 4 + tig] = l;
        split2(oacc[nf][2] * inv2, oacc[nf][3] * inv2, h, l);
        yh[r2 + nf * 4 + tig] = h; yl[r2 + nf * 4 + tig] = l;
    }
}

// ---------------- host orchestration ----------------
extern "C" void kernel_launch(void* const* d_in, const int* in_sizes, int n_in,
                              void* d_out, int out_size) {
    const int*   idx   = (const int*)  d_in[0];
    const float* wte   = (const float*)d_in[1];
    const float* wpe   = (const float*)d_in[2];
    const float* ln1_g = (const float*)d_in[3];
    const float* ln1_b = (const float*)d_in[4];
    const float* wqkv  = (const float*)d_in[5];
    const float* bqkv  = (const float*)d_in[6];
    const float* wproj = (const float*)d_in[7];
    const float* bproj = (const float*)d_in[8];
    const float* ln2_g = (const float*)d_in[9];
    const float* ln2_b = (const float*)d_in[10];
    const float* wfc   = (const float*)d_in[11];
    const float* bfc   = (const float*)d_in[12];
    const float* wfc2  = (const float*)d_in[13];
    const float* bfc2  = (const float*)d_in[14];
    const float* lnf_g = (const float*)d_in[15];
    const float* lnf_b = (const float*)d_in[16];
    const float* lm_w  = (const float*)d_in[17];
    float* out = (float*)d_out;

    float *x, *qkv;
    uint32_t *lnh, *lnl, *acth, *actl;
    uint32_t *wqh, *wql, *wph, *wpl, *wfh, *wfl, *w2h, *w2l, *lmh;
    cudaGetSymbolAddress((void**)&x,    g_x);
    cudaGetSymbolAddress((void**)&qkv,  g_qkv);
    cudaGetSymbolAddress((void**)&lnh,  g_lnh);
    cudaGetSymbolAddress((void**)&lnl,  g_lnl);
    cudaGetSymbolAddress((void**)&acth, g_acth);
    cudaGetSymbolAddress((void**)&actl, g_actl);
    cudaGetSymbolAddress((void**)&wqh,  g_wqkvh);
    cudaGetSymbolAddress((void**)&wql,  g_wqkvl);
    cudaGetSymbolAddress((void**)&wph,  g_wprjh);
    cudaGetSymbolAddress((void**)&wpl,  g_wprjl);
    cudaGetSymbolAddress((void**)&wfh,  g_wfch);
    cudaGetSymbolAddress((void**)&wfl,  g_wfcl);
    cudaGetSymbolAddress((void**)&w2h,  g_wfc2h);
    cudaGetSymbolAddress((void**)&w2l,  g_wfc2l);
    cudaGetSymbolAddress((void**)&lmh,  g_lmwh);

    cudaFuncSetAttribute(gemm_mma<1, 0, 3>, cudaFuncAttributeMaxDynamicSharedMemorySize, GSMEM);
    cudaFuncSetAttribute(gemm_mma<3, 1, 3>, cudaFuncAttributeMaxDynamicSharedMemorySize, GSMEM);
    cudaFuncSetAttribute(gemm_mma<0, 0, 1>, cudaFuncAttributeMaxDynamicSharedMemorySize, GSMEM);
    cudaFuncSetAttribute(gemm_mmaM64<5, 0>, cudaFuncAttributeMaxDynamicSharedMemorySize, GSMEMM);
    cudaFuncSetAttribute(attn_mma_kernel, cudaFuncAttributeMaxDynamicSharedMemorySize, ASMEM);

    // ---- weight conversions (once per call) ----
    convert_w<<<dim3((C3 + 1023) / 1024, LL * CC / 2), 256>>>(wqkv,  wqh, wql, C3, C3);
    convert_w<<<dim3((CC + 1023) / 1024, LL * CC / 2), 256>>>(wproj, wph, wpl, CC, CC);
    convert_w<<<dim3((C4 + 1023) / 1024, LL * CC / 2), 256>>>(wfc,   wfh, wfl, C4, C4);
    convert_w<<<dim3((CC + 1023) / 1024, LL * C4 / 2), 256>>>(wfc2,  w2h, w2l, CC, CC);
    convert_w<<<dim3((VP + 1023) / 1024, CC / 2),      256>>>(lm_w,  lmh, nullptr, VV, VP);

    embed_kernel<<<MR, 256>>>(idx, wte, wpe);

    for (int l = 0; l < LL; l++) {
        ln_kernel<<<MR / 8, 256>>>(x, ln1_g + (size_t)l * CC, ln1_b + (size_t)l * CC, lnh, lnl);

        // qkv = ln @ wqkv + bqkv  [2048 x 2304], fp32 out (128-tile, 288 CTAs)
        gemm_mma<1, 0, 3><<<dim3(16, C3 / 128), 256, GSMEM>>>(
            lnh, lnl, CC / 2,
            wqh + (size_t)l * (CC / 2) * C3, wql + (size_t)l * (CC / 2) * C3, C3,
            bqkv + (size_t)l * C3, nullptr, qkv, nullptr, nullptr, C3);

        attn_mma_kernel<<<dim3(TT / 64, HH, BB), 128, ASMEM>>>(qkv, acth, actl);

        // x = x + y @ wproj + bproj  (64x128 tiles: 32x6 = 192 CTAs)
        gemm_mmaM64<5, 0><<<dim3(32, 6), 256, GSMEMM>>>(
            acth, actl, CC / 2,
            wph + (size_t)l * (CC / 2) * CC, wpl + (size_t)l * (CC / 2) * CC, CC,
            bproj + (size_t)l * CC, x, x, nullptr, nullptr, CC);

        ln_kernel<<<MR / 8, 256>>>(x, ln2_g + (size_t)l * CC, ln2_b + (size_t)l * CC, lnh, lnl);

        // fc = gelu(ln @ wfc + bfc), pair-plane out  (128-tile: 16x24 = 384 CTAs)
        gemm_mma<3, 1, 3><<<dim3(16, C4 / 128), 256, GSMEM>>>(
            lnh, lnl, CC / 2,
            wfh + (size_t)l * (CC / 2) * C4, wfl + (size_t)l * (CC / 2) * C4, C4,
            bfc + (size_t)l * C4, nullptr, nullptr, acth, actl, C4);

        // x = x + fc @ wfc2 + bfc2  (64x128 tiles: 32x6 = 192 CTAs, K=3072 deep)
        gemm_mmaM64<5, 0><<<dim3(32, 6), 256, GSMEMM>>>(
            acth, actl, C4 / 2,
            w2h + (size_t)l * (C4 / 2) * CC, w2l + (size_t)l * (C4 / 2) * CC, CC,
            bfc2 + (size_t)l * CC, x, x, nullptr, nullptr, CC);
    }

    ln_kernel<<<MR / 8, 256>>>(x, lnf_g, lnf_b, lnh, lnl);

    // logits = ln @ lm_w  [2048 x 50257] — single-pass fp16 (error leaf)
    gemm_mma<0, 0, 1><<<dim3(16, VP / 128), 256, GSMEM>>>(
        lnh, lnl, CC / 2, lmh, nullptr, VP,
        nullptr, nullptr, out, nullptr, nullptr, VV);
}

// round 16
// speedup vs baseline: 4.3165x; 1.0057x over previous
#include <cuda_runtime.h>
#include <cuda_fp16.h>
#include <math.h>
#include <stdint.h>

// ---------------- problem constants ----------------
#define BB   2
#define TT   1024
#define CC   768
#define HH   12
#define DD   64
#define LL   12
#define VV   50257
#define MR   2048
#define C3   2304
#define C4   3072
#define VP   50304   // VV padded to multiple of 128

// ---------------- fp32 buffers ----------------
__device__ float g_x  [MR*CC];   // residual stream
__device__ float g_qkv[MR*C3];   // qkv fp32 (V columns used by attention)

// ---------------- activation hi/lo pair planes (u32 = half2(k_even, k_odd)) ----------------
__device__ uint32_t g_lnh [MR*(CC/2)], g_lnl [MR*(CC/2)];    // LN outputs
__device__ uint32_t g_acth[MR*(C4/2)], g_actl[MR*(C4/2)];    // y (stride 384) / fc (stride 1536)
__device__ uint32_t g_qkh [MR*768],    g_qkl [MR*768];       // Q,K pair planes (qkv cols 0..1535)

// ---------------- weight hi/lo pair planes ----------------
__device__ uint32_t g_wqkvh[LL*(CC/2)*C3], g_wqkvl[LL*(CC/2)*C3];
__device__ uint32_t g_wprjh[LL*(CC/2)*CC], g_wprjl[LL*(CC/2)*CC];
__device__ uint32_t g_wfch [LL*(CC/2)*C4], g_wfcl [LL*(CC/2)*C4];
__device__ uint32_t g_wfc2h[LL*(C4/2)*CC], g_wfc2l[LL*(C4/2)*CC];
__device__ uint32_t g_lmwh [(CC/2)*VP];

// ---------------- helpers ----------------
__device__ __forceinline__ uint32_t smem_u32(const void* p) {
    uint32_t a;
    asm("{ .reg .u64 t; cvta.to.shared.u64 t, %1; cvt.u32.u64 %0, t; }" : "=r"(a) : "l"(p));
    return a;
}

__device__ __forceinline__ void mma_f16(float* c, uint32_t a0, uint32_t a1,
                                        uint32_t a2, uint32_t a3,
                                        uint32_t b0, uint32_t b1) {
    asm volatile(
        "mma.sync.aligned.m16n8k16.row.col.f32.f16.f16.f32 "
        "{%0,%1,%2,%3}, {%4,%5,%6,%7}, {%8,%9}, {%0,%1,%2,%3};"
        : "+f"(c[0]), "+f"(c[1]), "+f"(c[2]), "+f"(c[3])
        : "r"(a0), "r"(a1), "r"(a2), "r"(a3), "r"(b0), "r"(b1));
}

// pack two floats into (hi, lo) half2 words; elem0 (low 16 bits) = first arg
__device__ __forceinline__ void split2(float a, float b, uint32_t& hi, uint32_t& lo) {
    __half ha = __float2half_rn(a), hb = __float2half_rn(b);
    float ra = a - __half2float(ha), rb = b - __half2float(hb);
    __half la = __float2half_rn(ra), lb = __float2half_rn(rb);
    hi = (uint32_t)__half_as_ushort(ha) | ((uint32_t)__half_as_ushort(hb) << 16);
    lo = (uint32_t)__half_as_ushort(la) | ((uint32_t)__half_as_ushort(lb) << 16);
}

__device__ __forceinline__ void cp16(uint32_t s, const void* g) {
    asm volatile("cp.async.cg.shared.global [%0], [%1], 16;" :: "r"(s), "l"(g));
}

__device__ __forceinline__ float gelu_f(float x) {
    float x3 = x * x * x;
    return 0.5f * x * (1.0f + tanhf(0.7978845608028654f * (x + 0.044715f * x3)));
}

// ---------------- weight conversion: [K][N] fp32 -> pair planes [K/2][NP] ----------------
__global__ void convert_w(const float* __restrict__ w, uint32_t* __restrict__ ph,
                          uint32_t* __restrict__ pl, int N, int NP) {
    int kp = blockIdx.y;
    int n0 = (blockIdx.x * 256 + threadIdx.x) * 4;
    if (n0 >= NP) return;
    const float* r0 = w + (size_t)(2 * kp) * N;
    const float* r1 = r0 + N;
    uint32_t h[4], l[4];
#pragma unroll
    for (int j = 0; j < 4; j++) {
        int n = n0 + j;
        float a = (n < N) ? r0[n] : 0.f;
        float b = (n < N) ? r1[n] : 0.f;
        split2(a, b, h[j], l[j]);
    }
    *(uint4*)&ph[(size_t)kp * NP + n0] = make_uint4(h[0], h[1], h[2], h[3]);
    if (pl) *(uint4*)&pl[(size_t)kp * NP + n0] = make_uint4(l[0], l[1], l[2], l[3]);
}

// ---------------- embedding ----------------
__global__ void embed_kernel(const int* __restrict__ idx,
                             const float* __restrict__ wte,
                             const float* __restrict__ wpe) {
    int row = blockIdx.x;
    int t   = row % TT;
    int tok = idx[row];
    const float* we = wte + (size_t)tok * CC;
    const float* wp = wpe + (size_t)t   * CC;
    float* out = g_x + (size_t)row * CC;
    for (int i = threadIdx.x; i < CC; i += blockDim.x)
        out[i] = we[i] + wp[i];
}

// ---------------- layernorm: warp-per-row, shuffle-only reduce ----------------
__global__ __launch_bounds__(256)
void ln_kernel(const float* __restrict__ x,
               const float* __restrict__ g,
               const float* __restrict__ b,
               uint32_t* __restrict__ outh, uint32_t* __restrict__ outl) {
    int warp = threadIdx.x >> 5, lane = threadIdx.x & 31;
    int row = blockIdx.x * 8 + warp;
    const float* xr = x + (size_t)row * CC;

    float4 v[6];
    float s = 0.f, s2 = 0.f;
#pragma unroll
    for (int j = 0; j < 6; j++) {
        v[j] = *(const float4*)(xr + (lane + 32 * j) * 4);
        s  += v[j].x + v[j].y + v[j].z + v[j].w;
        s2 += v[j].x * v[j].x + v[j].y * v[j].y + v[j].z * v[j].z + v[j].w * v[j].w;
    }
#pragma unroll
    for (int o = 16; o; o >>= 1) {
        s  += __shfl_xor_sync(0xffffffffu, s,  o);
        s2 += __shfl_xor_sync(0xffffffffu, s2, o);
    }
    float mean = s * (1.0f / CC);
    float var  = s2 * (1.0f / CC) - mean * mean;
    float rstd = rsqrtf(var + 1e-5f);

    size_t ro = (size_t)row * (CC / 2);
#pragma unroll
    for (int j = 0; j < 6; j++) {
        int f = lane + 32 * j;
        float4 gv = *(const float4*)(g + 4 * f);
        float4 bv = *(const float4*)(b + 4 * f);
        float a0 = (v[j].x - mean) * rstd * gv.x + bv.x;
        float a1 = (v[j].y - mean) * rstd * gv.y + bv.y;
        float a2 = (v[j].z - mean) * rstd * gv.z + bv.z;
        float a3 = (v[j].w - mean) * rstd * gv.w + bv.w;
        uint32_t h0, l0, h1, l1;
        split2(a0, a1, h0, l0);
        split2(a2, a3, h1, l1);
        *(uint2*)&outh[ro + 2 * f] = make_uint2(h0, h1);
        *(uint2*)&outl[ro + 2 * f] = make_uint2(l0, l1);
    }
}

// ---------------- fp16-split mma GEMM, 128x128 tile, 3-stage cp.async pipeline ----------------
// EPI bits: 1=+bias, 2=gelu, 4=+residual.
// OUTM: 0 = fp32 C, 1 = pair planes, 2 = qkv hybrid (planes for n<1536, fp32 V for n>=1536).
// PASSES: 3 = hi/lo split (exact), 1 = fp16 hi-only (LM head leaf).
#define PA 20      // u32 row stride of A tile (16 pairs + 4 pad)
#define PB 136     // u32 row stride of B tile (128 + 8 pad, conflict-free)
#define STG 9472   // u32 per stage: 2*128*20 + 2*16*136
#define OFF_AL 2560
#define OFF_BH 5120
#define OFF_BL 7296
#define GSMEM (3 * STG * 4)   // 113664 bytes (3 stages)

template<int EPI, int OUTM, int PASSES>
__global__ __launch_bounds__(256, 2)
void gemm_mma(const uint32_t* __restrict__ Ah, const uint32_t* __restrict__ Al, int KH,
              const uint32_t* __restrict__ Bh, const uint32_t* __restrict__ Bl, int NP,
              const float* __restrict__ bias, const float* __restrict__ res,
              float* __restrict__ C, uint32_t* __restrict__ Ch, uint32_t* __restrict__ Cl,
              int N) {
    extern __shared__ __align__(16) uint32_t sm[];
    const int t = threadIdx.x;
    const int wid = t >> 5, lane = t & 31;
    const int grp = lane >> 2, tig = lane & 3;
    const int warp_m = wid >> 2;
    const int warp_n = wid & 3;
    const int m0 = blockIdx.x * 128;
    const int n0 = blockIdx.y * 128;
    const uint32_t sb = smem_u32(sm);

    float acc[4][4][4];
#pragma unroll
    for (int im = 0; im < 4; im++)
#pragma unroll
        for (int in = 0; in < 4; in++)
#pragma unroll
            for (int r = 0; r < 4; r++) acc[im][in][r] = 0.f;

    const int nch = KH / 16;

    auto prefetch = [&](int c, int st) {
        uint32_t base = sb + (uint32_t)st * STG * 4;
        int k0 = c * 16;
#pragma unroll
        for (int i = 0; i < 2; i++) {
            int idx = t + i * 256;
            int row = idx >> 2, ch = (idx & 3) * 4;
            size_t go = (size_t)(m0 + row) * KH + k0 + ch;
            cp16(base + (row * PA + ch) * 4, Ah + go);
            if (PASSES == 3) cp16(base + (OFF_AL + row * PA + ch) * 4, Al + go);
        }
#pragma unroll
        for (int i = 0; i < 2; i++) {
            int idx = t + i * 256;
            int kp = idx >> 5, ch = (idx & 31) * 4;
            size_t go = (size_t)(k0 + kp) * NP + n0 + ch;
            cp16(base + (OFF_BH + kp * PB + ch) * 4, Bh + go);
            if (PASSES == 3) cp16(base + (OFF_BL + kp * PB + ch) * 4, Bl + go);
        }
        asm volatile("cp.async.commit_group;" ::: "memory");
    };

    prefetch(0, 0);
    if (nch > 1) prefetch(1, 1);
    for (int c = 0; c < nch; c++) {
        if (c + 2 < nch) {
            prefetch(c + 2, (c + 2) % 3);
            asm volatile("cp.async.wait_group 2;" ::: "memory");
        } else if (c + 1 < nch) {
            asm volatile("cp.async.wait_group 1;" ::: "memory");
        } else {
            asm volatile("cp.async.wait_group 0;" ::: "memory");
        }
        __syncthreads();
        const uint32_t* S = sm + (c % 3) * STG;
#pragma unroll
        for (int ks = 0; ks < 2; ks++) {
            const int kb = ks * 8;
            uint32_t ah[4][4], al[4][4];
#pragma unroll
            for (int im = 0; im < 4; im++) {
                int r0 = (warp_m * 64 + im * 16 + grp) * PA;
                int r1 = r0 + 8 * PA;
                ah[im][0] = S[r0 + kb + tig];
                ah[im][1] = S[r1 + kb + tig];
                ah[im][2] = S[r0 + kb + tig + 4];
                ah[im][3] = S[r1 + kb + tig + 4];
                if (PASSES == 3) {
                    al[im][0] = S[OFF_AL + r0 + kb + tig];
                    al[im][1] = S[OFF_AL + r1 + kb + tig];
                    al[im][2] = S[OFF_AL + r0 + kb + tig + 4];
                    al[im][3] = S[OFF_AL + r1 + kb + tig + 4];
                }
            }
            uint32_t bh[4][2], bl[4][2];
#pragma unroll
            for (int in = 0; in < 4; in++) {
                int nb = warp_n * 32 + in * 8 + grp;
                bh[in][0] = S[OFF_BH + (kb + tig) * PB + nb];
                bh[in][1] = S[OFF_BH + (kb + tig + 4) * PB + nb];
                if (PASSES == 3) {
                    bl[in][0] = S[OFF_BL + (kb + tig) * PB + nb];
                    bl[in][1] = S[OFF_BL + (kb + tig + 4) * PB + nb];
                }
            }
#pragma unroll
            for (int im = 0; im < 4; im++)
#pragma unroll
                for (int in = 0; in < 4; in++) {
                    mma_f16(acc[im][in], ah[im][0], ah[im][1], ah[im][2], ah[im][3],
                            bh[in][0], bh[in][1]);
                    if (PASSES == 3) {
                        mma_f16(acc[im][in], ah[im][0], ah[im][1], ah[im][2], ah[im][3],
                                bl[in][0], bl[in][1]);
                        mma_f16(acc[im][in], al[im][0], al[im][1], al[im][2], al[im][3],
                                bh[in][0], bh[in][1]);
                    }
                }
        }
        __syncthreads();
    }

    // ---- epilogue ----
    const bool n2 = ((N & 1) == 0);
#pragma unroll
    for (int im = 0; im < 4; im++) {
        int r0 = m0 + warp_m * 64 + im * 16 + grp;
        int r1 = r0 + 8;
#pragma unroll
        for (int in = 0; in < 4; in++) {
            int nc = n0 + warp_n * 32 + in * 8 + tig * 2;
            float v00 = acc[im][in][0], v01 = acc[im][in][1];
            float v10 = acc[im][in][2], v11 = acc[im][in][3];
            if (EPI & 1) {
                float b0v = (nc < N) ? bias[nc] : 0.f;
                float b1v = (nc + 1 < N) ? bias[nc + 1] : 0.f;
                v00 += b0v; v10 += b0v; v01 += b1v; v11 += b1v;
            }
            if (EPI & 2) {
                v00 = gelu_f(v00); v01 = gelu_f(v01);
                v10 = gelu_f(v10); v11 = gelu_f(v11);
            }
            if (EPI & 4) {
                if (nc < N) { v00 += res[(size_t)r0 * N + nc]; v10 += res[(size_t)r1 * N + nc]; }
                if (nc + 1 < N) { v01 += res[(size_t)r0 * N + nc + 1]; v11 += res[(size_t)r1 * N + nc + 1]; }
            }
            if (OUTM == 1) {
                uint32_t ph, pl;
                split2(v00, v01, ph, pl);
                Ch[(size_t)r0 * (N / 2) + nc / 2] = ph;
                Cl[(size_t)r0 * (N / 2) + nc / 2] = pl;
                split2(v10, v11, ph, pl);
                Ch[(size_t)r1 * (N / 2) + nc / 2] = ph;
                Cl[(size_t)r1 * (N / 2) + nc / 2] = pl;
            } else if (OUTM == 2) {
                if (n0 < 2 * CC) {   // Q,K columns -> pair planes (row stride 768)
                    uint32_t ph, pl;
                    split2(v00, v01, ph, pl);
                    Ch[(size_t)r0 * 768 + nc / 2] = ph;
                    Cl[(size_t)r0 * 768 + nc / 2] = pl;
                    split2(v10, v11, ph, pl);
                    Ch[(size_t)r1 * 768 + nc / 2] = ph;
                    Cl[(size_t)r1 * 768 + nc / 2] = pl;
                } else {             // V columns -> fp32 qkv
                    *(float2*)(C + (size_t)r0 * N + nc) = make_float2(v00, v01);
                    *(float2*)(C + (size_t)r1 * N + nc) = make_float2(v10, v11);
                }
            } else {
                if (n2 && nc + 1 < N) {
                    *(float2*)(C + (size_t)r0 * N + nc) = make_float2(v00, v01);
                    *(float2*)(C + (size_t)r1 * N + nc) = make_float2(v10, v11);
                } else {
                    if (nc < N)     { C[(size_t)r0 * N + nc]     = v00; C[(size_t)r1 * N + nc]     = v10; }
                    if (nc + 1 < N) { C[(size_t)r0 * N + nc + 1] = v01; C[(size_t)r1 * N + nc + 1] = v11; }
                }
            }
        }
    }
}

// ---------------- 64x128-tile variant (proj / fc2), 3-stage pipeline ----------------
#define STGM 6912             // 64*20*2 + 16*136*2
#define OFF_ALM 1280
#define OFF_BHM 2560
#define OFF_BLM 4736
#define GSMEMM (3 * STGM * 4) // 82944 bytes

template<int EPI, int OUTM>
__global__ __launch_bounds__(256, 2)
void gemm_mmaM64(const uint32_t* __restrict__ Ah, const uint32_t* __restrict__ Al, int KH,
                 const uint32_t* __restrict__ Bh, const uint32_t* __restrict__ Bl, int NP,
                 const float* __restrict__ bias, const float* __restrict__ res,
                 float* __restrict__ C, uint32_t* __restrict__ Ch, uint32_t* __restrict__ Cl,
                 int N) {
    extern __shared__ __align__(16) uint32_t sm[];
    const int t = threadIdx.x;
    const int wid = t >> 5, lane = t & 31;
    const int grp = lane >> 2, tig = lane & 3;
    const int warp_m = wid >> 2;
    const int warp_n = wid & 3;
    const int m0 = blockIdx.x * 64;
    const int n0 = blockIdx.y * 128;
    const uint32_t sb = smem_u32(sm);

    float acc[2][4][4];
#pragma unroll
    for (int im = 0; im < 2; im++)
#pragma unroll
        for (int in = 0; in < 4; in++)
#pragma unroll
            for (int r = 0; r < 4; r++) acc[im][in][r] = 0.f;

    const int nch = KH / 16;

    auto prefetch = [&](int c, int st) {
        uint32_t base = sb + (uint32_t)st * STGM * 4;
        int k0 = c * 16;
        {
            int row = t >> 2, ch = (t & 3) * 4;
            size_t go = (size_t)(m0 + row) * KH + k0 + ch;
            cp16(base + (row * PA + ch) * 4, Ah + go);
            cp16(base + (OFF_ALM + row * PA + ch) * 4, Al + go);
        }
#pragma unroll
        for (int i = 0; i < 2; i++) {
            int idx = t + i * 256;
            int kp = idx >> 5, ch = (idx & 31) * 4;
            size_t go = (size_t)(k0 + kp) * NP + n0 + ch;
            cp16(base + (OFF_BHM + kp * PB + ch) * 4, Bh + go);
            cp16(base + (OFF_BLM + kp * PB + ch) * 4, Bl + go);
        }
        asm volatile("cp.async.commit_group;" ::: "memory");
    };

    prefetch(0, 0);
    if (nch > 1) prefetch(1, 1);
    for (int c = 0; c < nch; c++) {
        if (c + 2 < nch) {
            prefetch(c + 2, (c + 2) % 3);
            asm volatile("cp.async.wait_group 2;" ::: "memory");
        } else if (c + 1 < nch) {
            asm volatile("cp.async.wait_group 1;" ::: "memory");
        } else {
            asm volatile("cp.async.wait_group 0;" ::: "memory");
        }
        __syncthreads();
        const uint32_t* S = sm + (c % 3) * STGM;
#pragma unroll
        for (int ks = 0; ks < 2; ks++) {
            const int kb = ks * 8;
            uint32_t ah[2][4], al[2][4];
#pragma unroll
            for (int im = 0; im < 2; im++) {
                int r0 = (warp_m * 32 + im * 16 + grp) * PA;
                int r1 = r0 + 8 * PA;
                ah[im][0] = S[r0 + kb + tig];
                ah[im][1] = S[r1 + kb + tig];
                ah[im][2] = S[r0 + kb + tig + 4];
                ah[im][3] = S[r1 + kb + tig + 4];
                al[im][0] = S[OFF_ALM + r0 + kb + tig];
                al[im][1] = S[OFF_ALM + r1 + kb + tig];
                al[im][2] = S[OFF_ALM + r0 + kb + tig + 4];
                al[im][3] = S[OFF_ALM + r1 + kb + tig + 4];
            }
            uint32_t bh[4][2], bl[4][2];
#pragma unroll
            for (int in = 0; in < 4; in++) {
                int nb = warp_n * 32 + in * 8 + grp;
                bh[in][0] = S[OFF_BHM + (kb + tig) * PB + nb];
                bh[in][1] = S[OFF_BHM + (kb + tig + 4) * PB + nb];
                bl[in][0] = S[OFF_BLM + (kb + tig) * PB + nb];
                bl[in][1] = S[OFF_BLM + (kb + tig + 4) * PB + nb];
            }
#pragma unroll
            for (int im = 0; im < 2; im++)
#pragma unroll
                for (int in = 0; in < 4; in++) {
                    mma_f16(acc[im][in], ah[im][0], ah[im][1], ah[im][2], ah[im][3],
                            bh[in][0], bh[in][1]);
                    mma_f16(acc[im][in], ah[im][0], ah[im][1], ah[im][2], ah[im][3],
                            bl[in][0], bl[in][1]);
                    mma_f16(acc[im][in], al[im][0], al[im][1], al[im][2], al[im][3],
                            bh[in][0], bh[in][1]);
                }
        }
        __syncthreads();
    }

    // ---- epilogue ----
#pragma unroll
    for (int im = 0; im < 2; im++) {
        int r0 = m0 + warp_m * 32 + im * 16 + grp;
        int r1 = r0 + 8;
#pragma unroll
        for (int in = 0; in < 4; in++) {
            int nc = n0 + warp_n * 32 + in * 8 + tig * 2;
            float v00 = acc[im][in][0], v01 = acc[im][in][1];
            float v10 = acc[im][in][2], v11 = acc[im][in][3];
            if (EPI & 1) {
                float b0v = bias[nc], b1v = bias[nc + 1];
                v00 += b0v; v10 += b0v; v01 += b1v; v11 += b1v;
            }
            if (EPI & 2) {
                v00 = gelu_f(v00); v01 = gelu_f(v01);
                v10 = gelu_f(v10); v11 = gelu_f(v11);
            }
            if (EPI & 4) {
                v00 += res[(size_t)r0 * N + nc];
                v01 += res[(size_t)r0 * N + nc + 1];
                v10 += res[(size_t)r1 * N + nc];
                v11 += res[(size_t)r1 * N + nc + 1];
            }
            if (OUTM == 1) {
                uint32_t ph, pl;
                split2(v00, v01, ph, pl);
                Ch[(size_t)r0 * (N / 2) + nc / 2] = ph;
                Cl[(size_t)r0 * (N / 2) + nc / 2] = pl;
                split2(v10, v11, ph, pl);
                Ch[(size_t)r1 * (N / 2) + nc / 2] = ph;
                Cl[(size_t)r1 * (N / 2) + nc / 2] = pl;
            } else {
                *(float2*)(C + (size_t)r0 * N + nc) = make_float2(v00, v01);
                *(float2*)(C + (size_t)r1 * N + nc) = make_float2(v10, v11);
            }
        }
    }
}

// ---------------- MMA flash-attention (Q/K planes via cp.async, online softmax) ----------------
#define APD 36
#define APLANE (64 * APD)                // 2304 u32
#define ASMEM (6 * APLANE * 4)           // 55296 bytes

__global__ __launch_bounds__(128, 3)
void attn_mma_kernel(const uint32_t* __restrict__ qkh, const uint32_t* __restrict__ qkl,
                     const float* __restrict__ qkv,
                     uint32_t* __restrict__ yh, uint32_t* __restrict__ yl) {
    extern __shared__ __align__(16) uint32_t as[];
    uint32_t* sQh = as;
    uint32_t* sQl = as + APLANE;
    uint32_t* sKh = as + 2 * APLANE;
    uint32_t* sKl = as + 3 * APLANE;
    uint32_t* sVh = as + 4 * APLANE;     // [d][jpair]
    uint32_t* sVl = as + 5 * APLANE;

    const int t = threadIdx.x;
    const int warp = t >> 5, lane = t & 31;
    const int grp = lane >> 2, tig = lane & 3;
    const int hd = blockIdx.y, b = blockIdx.z;
    const int qblk = gridDim.x - 1 - blockIdx.x;   // long blocks first
    const int qb = qblk * 64;
    const int m0 = warp * 16;

    const uint32_t aQh = smem_u32(sQh), aQl = smem_u32(sQl);
    const uint32_t aKh = smem_u32(sKh), aKl = smem_u32(sKl);

    // ---- stage Q planes via cp.async: 64 rows x 32 u32 per plane (8 x 16B per row) ----
#pragma unroll
    for (int i = 0; i < 8; i++) {
        int idx = t + i * 128;             // 0..1023
        int plane = idx >> 9;              // 0 hi, 1 lo
        int rem = idx & 511;
        int row = rem >> 3, ch = (rem & 7) * 4;   // ch 0..28
        const uint32_t* src = (plane ? qkl : qkh)
            + (size_t)(b * TT + qb + row) * 768 + hd * 32 + ch;
        uint32_t dst = (plane ? aQl : aQh) + (uint32_t)(row * APD + ch) * 4;
        cp16(dst, src);
    }
    asm volatile("cp.async.commit_group;" ::: "memory");

    const float* Vb = qkv + (size_t)b * TT * C3 + 2 * CC + hd * DD;
    const int kcol = 384 + hd * 32;        // K plane column base

    float oacc[8][4];
#pragma unroll
    for (int nf = 0; nf < 8; nf++)
#pragma unroll
        for (int e = 0; e < 4; e++) oacc[nf][e] = 0.f;
    float mr1 = -1e30f, mr2 = -1e30f, lr1 = 0.f, lr2 = 0.f;

    for (int jt = 0; jt <= qblk; jt++) {
        const int j0 = jt * 64;
        __syncthreads();
        // ---- stage K planes via cp.async: 64 rows x 32 u32 per plane ----
#pragma unroll
        for (int i = 0; i < 8; i++) {
            int idx = t + i * 128;
            int plane = idx >> 9;
            int rem = idx & 511;
            int row = rem >> 3, ch = (rem & 7) * 4;
            const uint32_t* src = (plane ? qkl : qkh)
                + (size_t)(b * TT + j0 + row) * 768 + kcol + ch;
            uint32_t dst = (plane ? aKl : aKh) + (uint32_t)(row * APD + ch) * 4;
            cp16(dst, src);
        }
        asm volatile("cp.async.commit_group;" ::: "memory");
        // ---- stage V transposed [d][jpair] from fp32 ----
#pragma unroll
        for (int i = 0; i < 16; i++) {
            int w = t + i * 128;
            int d = w & 63, jp = w >> 6;
            float v0 = Vb[(size_t)(j0 + 2 * jp)     * C3 + d];
            float v1 = Vb[(size_t)(j0 + 2 * jp + 1) * C3 + d];
            uint32_t h, l;
            split2(v0, v1, h, l);
            sVh[d * APD + jp] = h;
            sVl[d * APD + jp] = l;
        }
        asm volatile("cp.async.wait_group 0;" ::: "memory");
        __syncthreads();

        float s[8][4];
#pragma unroll
        for (int nf = 0; nf < 8; nf++)
#pragma unroll
            for (int e = 0; e < 4; e++) s[nf][e] = 0.f;

#pragma unroll
        for (int ks = 0; ks < 4; ks++) {
            const int kb = ks * 8;
            uint32_t qh0 = sQh[(m0 + grp)     * APD + kb + tig];
            uint32_t qh1 = sQh[(m0 + grp + 8) * APD + kb + tig];
            uint32_t qh2 = sQh[(m0 + grp)     * APD + kb + tig + 4];
            uint32_t qh3 = sQh[(m0 + grp + 8) * APD + kb + tig + 4];
            uint32_t ql0 = sQl[(m0 + grp)     * APD + kb + tig];
            uint32_t ql1 = sQl[(m0 + grp + 8) * APD + kb + tig];
            uint32_t ql2 = sQl[(m0 + grp)     * APD + kb + tig + 4];
            uint32_t ql3 = sQl[(m0 + grp + 8) * APD + kb + tig + 4];
#pragma unroll
            for (int nf = 0; nf < 8; nf++) {
                uint32_t bh0 = sKh[(nf * 8 + grp) * APD + kb + tig];
                uint32_t bh1 = sKh[(nf * 8 + grp) * APD + kb + tig + 4];
                uint32_t bl0 = sKl[(nf * 8 + grp) * APD + kb + tig];
                uint32_t bl1 = sKl[(nf * 8 + grp) * APD + kb + tig + 4];
                mma_f16(s[nf], qh0, qh1, qh2, qh3, bh0, bh1);
                mma_f16(s[nf], qh0, qh1, qh2, qh3, bl0, bl1);
                mma_f16(s[nf], ql0, ql1, ql2, ql3, bh0, bh1);
            }
        }

        // softmax scale (Q not pre-scaled)
#pragma unroll
        for (int nf = 0; nf < 8; nf++) {
            s[nf][0] *= 0.125f; s[nf][1] *= 0.125f;
            s[nf][2] *= 0.125f; s[nf][3] *= 0.125f;
        }

        if (jt == qblk) {
#pragma unroll
            for (int nf = 0; nf < 8; nf++) {
                int jc = nf * 8 + 2 * tig;
                int r1 = m0 + grp, r2 = r1 + 8;
                if (jc     > r1) s[nf][0] = -1e30f;
                if (jc + 1 > r1) s[nf][1] = -1e30f;
                if (jc     > r2) s[nf][2] = -1e30f;
                if (jc + 1 > r2) s[nf][3] = -1e30f;
            }
        }

        float tm1 = -1e30f, tm2 = -1e30f;
#pragma unroll
        for (int nf = 0; nf < 8; nf++) {
            tm1 = fmaxf(tm1, fmaxf(s[nf][0], s[nf][1]));
            tm2 = fmaxf(tm2, fmaxf(s[nf][2], s[nf][3]));
        }
        tm1 = fmaxf(tm1, __shfl_xor_sync(0xffffffffu, tm1, 1));
        tm1 = fmaxf(tm1, __shfl_xor_sync(0xffffffffu, tm1, 2));
        tm2 = fmaxf(tm2, __shfl_xor_sync(0xffffffffu, tm2, 1));
        tm2 = fmaxf(tm2, __shfl_xor_sync(0xffffffffu, tm2, 2));
        float mn1 = fmaxf(mr1, tm1), mn2 = fmaxf(mr2, tm2);
        float c1 = __expf(mr1 - mn1), c2 = __expf(mr2 - mn2);
        float ts1 = 0.f, ts2 = 0.f;
#pragma unroll
        for (int nf = 0; nf < 8; nf++) {
            s[nf][0] = __expf(s[nf][0] - mn1);
            s[nf][1] = __expf(s[nf][1] - mn1);
            s[nf][2] = __expf(s[nf][2] - mn2);
            s[nf][3] = __expf(s[nf][3] - mn2);
            ts1 += s[nf][0] + s[nf][1];
            ts2 += s[nf][2] + s[nf][3];
        }
        ts1 += __shfl_xor_sync(0xffffffffu, ts1, 1);
        ts1 += __shfl_xor_sync(0xffffffffu, ts1, 2);
        ts2 += __shfl_xor_sync(0xffffffffu, ts2, 1);
        ts2 += __shfl_xor_sync(0xffffffffu, ts2, 2);
        lr1 = lr1 * c1 + ts1;
        lr2 = lr2 * c2 + ts2;
        mr1 = mn1; mr2 = mn2;
#pragma unroll
        for (int nf = 0; nf < 8; nf++) {
            oacc[nf][0] *= c1; oacc[nf][1] *= c1;
            oacc[nf][2] *= c2; oacc[nf][3] *= c2;
        }

#pragma unroll
        for (int ks = 0; ks < 4; ks++) {
            uint32_t ph0, pl0, ph1, pl1, ph2, pl2, ph3, pl3;
            split2(s[2 * ks][0],     s[2 * ks][1],     ph0, pl0);
            split2(s[2 * ks][2],     s[2 * ks][3],     ph1, pl1);
            split2(s[2 * ks + 1][0], s[2 * ks + 1][1], ph2, pl2);
            split2(s[2 * ks + 1][2], s[2 * ks + 1][3], ph3, pl3);
#pragma unroll
            for (int nf = 0; nf < 8; nf++) {
                uint32_t bh0 = sVh[(nf * 8 + grp) * APD + ks * 8 + tig];
                uint32_t bh1 = sVh[(nf * 8 + grp) * APD + ks * 8 + tig + 4];
                uint32_t bl0 = sVl[(nf * 8 + grp) * APD + ks * 8 + tig];
                uint32_t bl1 = sVl[(nf * 8 + grp) * APD + ks * 8 + tig + 4];
                mma_f16(oacc[nf], ph0, ph1, ph2, ph3, bh0, bh1);
                mma_f16(oacc[nf], ph0, ph1, ph2, ph3, bl0, bl1);
                mma_f16(oacc[nf], pl0, pl1, pl2, pl3, bh0, bh1);
            }
        }
    }

    float inv1 = 1.f / lr1, inv2 = 1.f / lr2;
    size_t r1 = (size_t)(b * TT + qb + m0 + grp) * (CC / 2) + hd * 32;
    size_t r2 = r1 + 8 * (CC / 2);
#pragma unroll
    for (int nf = 0; nf < 8; nf++) {
        uint32_t h, l;
        split2(oacc[nf][0] * inv1, oacc[nf][1] * inv1, h, l);
        yh[r1 + nf * 4 + tig] = h; yl[r1 + nf * 4 + tig] = l;
        split2(oacc[nf][2] * inv2, oacc[nf][3] * inv2, h, l);
        yh[r2 + nf * 4 + tig] = h; yl[r2 + nf * 4 + tig] = l;
    }
}

// ---------------- host orchestration ----------------
extern "C" void kernel_launch(void* const* d_in, const int* in_sizes, int n_in,
                              void* d_out, int out_size) {
    const int*   idx   = (const int*)  d_in[0];
    const float* wte   = (const float*)d_in[1];
    const float* wpe   = (const float*)d_in[2];
    const float* ln1_g = (const float*)d_in[3];
    const float* ln1_b = (const float*)d_in[4];
    const float* wqkv  = (const float*)d_in[5];
    const float* bqkv  = (const float*)d_in[6];
    const float* wproj = (const float*)d_in[7];
    const float* bproj = (const float*)d_in[8];
    const float* ln2_g = (const float*)d_in[9];
    const float* ln2_b = (const float*)d_in[10];
    const float* wfc   = (const float*)d_in[11];
    const float* bfc   = (const float*)d_in[12];
    const float* wfc2  = (const float*)d_in[13];
    const float* bfc2  = (const float*)d_in[14];
    const float* lnf_g = (const float*)d_in[15];
    const float* lnf_b = (const float*)d_in[16];
    const float* lm_w  = (const float*)d_in[17];
    float* out = (float*)d_out;

    float *x, *qkv;
    uint32_t *lnh, *lnl, *acth, *actl, *qkh, *qkl;
    uint32_t *wqh, *wql, *wph, *wpl, *wfh, *wfl, *w2h, *w2l, *lmh;
    cudaGetSymbolAddress((void**)&x,    g_x);
    cudaGetSymbolAddress((void**)&qkv,  g_qkv);
    cudaGetSymbolAddress((void**)&lnh,  g_lnh);
    cudaGetSymbolAddress((void**)&lnl,  g_lnl);
    cudaGetSymbolAddress((void**)&acth, g_acth);
    cudaGetSymbolAddress((void**)&actl, g_actl);
    cudaGetSymbolAddress((void**)&qkh,  g_qkh);
    cudaGetSymbolAddress((void**)&qkl,  g_qkl);
    cudaGetSymbolAddress((void**)&wqh,  g_wqkvh);
    cudaGetSymbolAddress((void**)&wql,  g_wqkvl);
    cudaGetSymbolAddress((void**)&wph,  g_wprjh);
    cudaGetSymbolAddress((void**)&wpl,  g_wprjl);
    cudaGetSymbolAddress((void**)&wfh,  g_wfch);
    cudaGetSymbolAddress((void**)&wfl,  g_wfcl);
    cudaGetSymbolAddress((void**)&w2h,  g_wfc2h);
    cudaGetSymbolAddress((void**)&w2l,  g_wfc2l);
    cudaGetSymbolAddress((void**)&lmh,  g_lmwh);

    cudaFuncSetAttribute(gemm_mma<1, 2, 3>, cudaFuncAttributeMaxDynamicSharedMemorySize, GSMEM);
    cudaFuncSetAttribute(gemm_mma<3, 1, 3>, cudaFuncAttributeMaxDynamicSharedMemorySize, GSMEM);
    cudaFuncSetAttribute(gemm_mma<0, 0, 1>, cudaFuncAttributeMaxDynamicSharedMemorySize, GSMEM);
    cudaFuncSetAttribute(gemm_mmaM64<5, 0>, cudaFuncAttributeMaxDynamicSharedMemorySize, GSMEMM);
    cudaFuncSetAttribute(attn_mma_kernel, cudaFuncAttributeMaxDynamicSharedMemorySize, ASMEM);

    // ---- weight conversions (once per call) ----
    convert_w<<<dim3((C3 + 1023) / 1024, LL * CC / 2), 256>>>(wqkv,  wqh, wql, C3, C3);
    convert_w<<<dim3((CC + 1023) / 1024, LL * CC / 2), 256>>>(wproj, wph, wpl, CC, CC);
    convert_w<<<dim3((C4 + 1023) / 1024, LL * CC / 2), 256>>>(wfc,   wfh, wfl, C4, C4);
    convert_w<<<dim3((CC + 1023) / 1024, LL * C4 / 2), 256>>>(wfc2,  w2h, w2l, CC, CC);
    convert_w<<<dim3((VP + 1023) / 1024, CC / 2),      256>>>(lm_w,  lmh, nullptr, VV, VP);

    embed_kernel<<<MR, 256>>>(idx, wte, wpe);

    for (int l = 0; l < LL; l++) {
        ln_kernel<<<MR / 8, 256>>>(x, ln1_g + (size_t)l * CC, ln1_b + (size_t)l * CC, lnh, lnl);

        // qkv: Q,K -> pair planes; V -> fp32  (128-tile, 288 CTAs)
        gemm_mma<1, 2, 3><<<dim3(16, C3 / 128), 256, GSMEM>>>(
            lnh, lnl, CC / 2,
            wqh + (size_t)l * (CC / 2) * C3, wql + (size_t)l * (CC / 2) * C3, C3,
            bqkv + (size_t)l * C3, nullptr, qkv, qkh, qkl, C3);

        attn_mma_kernel<<<dim3(TT / 64, HH, BB), 128, ASMEM>>>(qkh, qkl, qkv, acth, actl);

        // x = x + y @ wproj + bproj  (64x128 tiles: 32x6 = 192 CTAs)
        gemm_mmaM64<5, 0><<<dim3(32, 6), 256, GSMEMM>>>(
            acth, actl, CC / 2,
            wph + (size_t)l * (CC / 2) * CC, wpl + (size_t)l * (CC / 2) * CC, CC,
            bproj + (size_t)l * CC, x, x, nullptr, nullptr, CC);

        ln_kernel<<<MR / 8, 256>>>(x, ln2_g + (size_t)l * CC, ln2_b + (size_t)l * CC, lnh, lnl);

        // fc = gelu(ln @ wfc + bfc), pair-plane out  (128-tile: 16x24 = 384 CTAs)
        gemm_mma<3, 1, 3><<<dim3(16, C4 / 128), 256, GSMEM>>>(
            lnh, lnl, CC / 2,
            wfh + (size_t)l * (CC / 2) * C4, wfl + (size_t)l * (CC / 2) * C4, C4,
            bfc + (size_t)l * C4, nullptr, nullptr, acth, actl, C4);

        // x = x + fc @ wfc2 + bfc2  (64x128 tiles: 32x6 = 192 CTAs, K=3072 deep)
        gemm_mmaM64<5, 0><<<dim3(32, 6), 256, GSMEMM>>>(
            acth, actl, C4 / 2,
            w2h + (size_t)l * (C4 / 2) * CC, w2l + (size_t)l * (C4 / 2) * CC, CC,
            bfc2 + (size_t)l * CC, x, x, nullptr, nullptr, CC);
    }

    ln_kernel<<<MR / 8, 256>>>(x, lnf_g, lnf_b, lnh, lnl);

    // logits = ln @ lm_w  [2048 x 50257] — single-pass fp16 (error leaf)
    gemm_mma<0, 0, 1><<<dim3(16, VP / 128), 256, GSMEM>>>(
        lnh, lnl, CC / 2, lmh, nullptr, VP,
        nullptr, nullptr, out, nullptr, nullptr, VV);
}

// round 17
// speedup vs baseline: 5.1966x; 1.2039x over previous
#include <cuda_runtime.h>
#include <cuda_fp16.h>
#include <math.h>
#include <stdint.h>

// ---------------- problem constants ----------------
#define BB   2
#define TT   1024
#define CC   768
#define HH   12
#define DD   64
#define LL   12
#define VV   50257
#define MR   2048
#define C3   2304
#define C4   3072
#define VP   50304   // VV padded to multiple of 128

// ---------------- fp32 buffers ----------------
__device__ float g_x  [MR*CC];   // residual stream
__device__ float g_qkv[MR*C3];   // qkv fp32 (V columns used by attention)

// ---------------- activation hi/lo pair planes (u32 = half2(k_even, k_odd)) ----------------
__device__ uint32_t g_lnh [MR*(CC/2)], g_lnl [MR*(CC/2)];    // LN outputs
__device__ uint32_t g_acth[MR*(C4/2)], g_actl[MR*(C4/2)];    // y (stride 384) / fc (stride 1536)
__device__ uint32_t g_qkh [MR*768],    g_qkl [MR*768];       // Q,K pair planes (qkv cols 0..1535)

// ---------------- weight hi pair planes (weights run fp16 in 2-pass GEMMs) ----------------
__device__ uint32_t g_wqkvh[LL*(CC/2)*C3];
__device__ uint32_t g_wprjh[LL*(CC/2)*CC];
__device__ uint32_t g_wfch [LL*(CC/2)*C4];
__device__ uint32_t g_wfc2h[LL*(C4/2)*CC];
__device__ uint32_t g_lmwh [(CC/2)*VP];

// ---------------- helpers ----------------
__device__ __forceinline__ uint32_t smem_u32(const void* p) {
    uint32_t a;
    asm("{ .reg .u64 t; cvta.to.shared.u64 t, %1; cvt.u32.u64 %0, t; }" : "=r"(a) : "l"(p));
    return a;
}

__device__ __forceinline__ void mma_f16(float* c, uint32_t a0, uint32_t a1,
                                        uint32_t a2, uint32_t a3,
                                        uint32_t b0, uint32_t b1) {
    asm volatile(
        "mma.sync.aligned.m16n8k16.row.col.f32.f16.f16.f32 "
        "{%0,%1,%2,%3}, {%4,%5,%6,%7}, {%8,%9}, {%0,%1,%2,%3};"
        : "+f"(c[0]), "+f"(c[1]), "+f"(c[2]), "+f"(c[3])
        : "r"(a0), "r"(a1), "r"(a2), "r"(a3), "r"(b0), "r"(b1));
}

// pack two floats into (hi, lo) half2 words; elem0 (low 16 bits) = first arg
__device__ __forceinline__ void split2(float a, float b, uint32_t& hi, uint32_t& lo) {
    __half ha = __float2half_rn(a), hb = __float2half_rn(b);
    float ra = a - __half2float(ha), rb = b - __half2float(hb);
    __half la = __float2half_rn(ra), lb = __float2half_rn(rb);
    hi = (uint32_t)__half_as_ushort(ha) | ((uint32_t)__half_as_ushort(hb) << 16);
    lo = (uint32_t)__half_as_ushort(la) | ((uint32_t)__half_as_ushort(lb) << 16);
}

__device__ __forceinline__ void cp16(uint32_t s, const void* g) {
    asm volatile("cp.async.cg.shared.global [%0], [%1], 16;" :: "r"(s), "l"(g));
}

__device__ __forceinline__ float gelu_f(float x) {
    float x3 = x * x * x;
    return 0.5f * x * (1.0f + tanhf(0.7978845608028654f * (x + 0.044715f * x3)));
}

// ---------------- weight conversion: [K][N] fp32 -> pair planes [K/2][NP] ----------------
__global__ void convert_w(const float* __restrict__ w, uint32_t* __restrict__ ph,
                          uint32_t* __restrict__ pl, int N, int NP) {
    int kp = blockIdx.y;
    int n0 = (blockIdx.x * 256 + threadIdx.x) * 4;
    if (n0 >= NP) return;
    const float* r0 = w + (size_t)(2 * kp) * N;
    const float* r1 = r0 + N;
    uint32_t h[4], l[4];
#pragma unroll
    for (int j = 0; j < 4; j++) {
        int n = n0 + j;
        float a = (n < N) ? r0[n] : 0.f;
        float b = (n < N) ? r1[n] : 0.f;
        split2(a, b, h[j], l[j]);
    }
    *(uint4*)&ph[(size_t)kp * NP + n0] = make_uint4(h[0], h[1], h[2], h[3]);
    if (pl) *(uint4*)&pl[(size_t)kp * NP + n0] = make_uint4(l[0], l[1], l[2], l[3]);
}

// ---------------- embedding ----------------
__global__ void embed_kernel(const int* __restrict__ idx,
                             const float* __restrict__ wte,
                             const float* __restrict__ wpe) {
    int row = blockIdx.x;
    int t   = row % TT;
    int tok = idx[row];
    const float* we = wte + (size_t)tok * CC;
    const float* wp = wpe + (size_t)t   * CC;
    float* out = g_x + (size_t)row * CC;
    for (int i = threadIdx.x; i < CC; i += blockDim.x)
        out[i] = we[i] + wp[i];
}

// ---------------- layernorm: warp-per-row, shuffle-only reduce ----------------
__global__ __launch_bounds__(256)
void ln_kernel(const float* __restrict__ x,
               const float* __restrict__ g,
               const float* __restrict__ b,
               uint32_t* __restrict__ outh, uint32_t* __restrict__ outl) {
    int warp = threadIdx.x >> 5, lane = threadIdx.x & 31;
    int row = blockIdx.x * 8 + warp;
    const float* xr = x + (size_t)row * CC;

    float4 v[6];
    float s = 0.f, s2 = 0.f;
#pragma unroll
    for (int j = 0; j < 6; j++) {
        v[j] = *(const float4*)(xr + (lane + 32 * j) * 4);
        s  += v[j].x + v[j].y + v[j].z + v[j].w;
        s2 += v[j].x * v[j].x + v[j].y * v[j].y + v[j].z * v[j].z + v[j].w * v[j].w;
    }
#pragma unroll
    for (int o = 16; o; o >>= 1) {
        s  += __shfl_xor_sync(0xffffffffu, s,  o);
        s2 += __shfl_xor_sync(0xffffffffu, s2, o);
    }
    float mean = s * (1.0f / CC);
    float var  = s2 * (1.0f / CC) - mean * mean;
    float rstd = rsqrtf(var + 1e-5f);

    size_t ro = (size_t)row * (CC / 2);
#pragma unroll
    for (int j = 0; j < 6; j++) {
        int f = lane + 32 * j;
        float4 gv = *(const float4*)(g + 4 * f);
        float4 bv = *(const float4*)(b + 4 * f);
        float a0 = (v[j].x - mean) * rstd * gv.x + bv.x;
        float a1 = (v[j].y - mean) * rstd * gv.y + bv.y;
        float a2 = (v[j].z - mean) * rstd * gv.z + bv.z;
        float a3 = (v[j].w - mean) * rstd * gv.w + bv.w;
        uint32_t h0, l0, h1, l1;
        split2(a0, a1, h0, l0);
        split2(a2, a3, h1, l1);
        *(uint2*)&outh[ro + 2 * f] = make_uint2(h0, h1);
        *(uint2*)&outl[ro + 2 * f] = make_uint2(l0, l1);
    }
}

// ---------------- fp16-split mma GEMM, 128x128 tile, 3-stage cp.async pipeline ----------------
// EPI bits: 1=+bias, 2=gelu, 4=+residual.
// OUTM: 0 = fp32 C, 1 = pair planes, 2 = qkv hybrid (planes for n<1536, fp32 V for n>=1536).
// PASSES: 2 = A 22-bit x B fp16 (internal), 1 = all fp16 (LM head leaf).
#define PA 20      // u32 row stride of A tile (16 pairs + 4 pad)
#define PB 136     // u32 row stride of B tile (128 + 8 pad, conflict-free)
#define STG 7296   // u32 per stage: 2*128*20 + 16*136
#define OFF_AL 2560
#define OFF_BH 5120
#define GSMEM (3 * STG * 4)   // 87552 bytes (3 stages)

template<int EPI, int OUTM, int PASSES>
__global__ __launch_bounds__(256, 2)
void gemm_mma(const uint32_t* __restrict__ Ah, const uint32_t* __restrict__ Al, int KH,
              const uint32_t* __restrict__ Bh, int NP,
              const float* __restrict__ bias, const float* __restrict__ res,
              float* __restrict__ C, uint32_t* __restrict__ Ch, uint32_t* __restrict__ Cl,
              int N) {
    extern __shared__ __align__(16) uint32_t sm[];
    const int t = threadIdx.x;
    const int wid = t >> 5, lane = t & 31;
    const int grp = lane >> 2, tig = lane & 3;
    const int warp_m = wid >> 2;
    const int warp_n = wid & 3;
    const int m0 = blockIdx.x * 128;
    const int n0 = blockIdx.y * 128;
    const uint32_t sb = smem_u32(sm);

    float acc[4][4][4];
#pragma unroll
    for (int im = 0; im < 4; im++)
#pragma unroll
        for (int in = 0; in < 4; in++)
#pragma unroll
            for (int r = 0; r < 4; r++) acc[im][in][r] = 0.f;

    const int nch = KH / 16;

    auto prefetch = [&](int c, int st) {
        uint32_t base = sb + (uint32_t)st * STG * 4;
        int k0 = c * 16;
#pragma unroll
        for (int i = 0; i < 2; i++) {
            int idx = t + i * 256;
            int row = idx >> 2, ch = (idx & 3) * 4;
            size_t go = (size_t)(m0 + row) * KH + k0 + ch;
            cp16(base + (row * PA + ch) * 4, Ah + go);
            if (PASSES >= 2) cp16(base + (OFF_AL + row * PA + ch) * 4, Al + go);
        }
#pragma unroll
        for (int i = 0; i < 2; i++) {
            int idx = t + i * 256;
            int kp = idx >> 5, ch = (idx & 31) * 4;
            size_t go = (size_t)(k0 + kp) * NP + n0 + ch;
            cp16(base + (OFF_BH + kp * PB + ch) * 4, Bh + go);
        }
        asm volatile("cp.async.commit_group;" ::: "memory");
    };

    prefetch(0, 0);
    if (nch > 1) prefetch(1, 1);
    for (int c = 0; c < nch; c++) {
        if (c + 2 < nch) {
            prefetch(c + 2, (c + 2) % 3);
            asm volatile("cp.async.wait_group 2;" ::: "memory");
        } else if (c + 1 < nch) {
            asm volatile("cp.async.wait_group 1;" ::: "memory");
        } else {
            asm volatile("cp.async.wait_group 0;" ::: "memory");
        }
        __syncthreads();
        const uint32_t* S = sm + (c % 3) * STG;
#pragma unroll
        for (int ks = 0; ks < 2; ks++) {
            const int kb = ks * 8;
            uint32_t ah[4][4], al[4][4];
#pragma unroll
            for (int im = 0; im < 4; im++) {
                int r0 = (warp_m * 64 + im * 16 + grp) * PA;
                int r1 = r0 + 8 * PA;
                ah[im][0] = S[r0 + kb + tig];
                ah[im][1] = S[r1 + kb + tig];
                ah[im][2] = S[r0 + kb + tig + 4];
                ah[im][3] = S[r1 + kb + tig + 4];
                if (PASSES >= 2) {
                    al[im][0] = S[OFF_AL + r0 + kb + tig];
                    al[im][1] = S[OFF_AL + r1 + kb + tig];
                    al[im][2] = S[OFF_AL + r0 + kb + tig + 4];
                    al[im][3] = S[OFF_AL + r1 + kb + tig + 4];
                }
            }
            uint32_t bh[4][2];
#pragma unroll
            for (int in = 0; in < 4; in++) {
                int nb = warp_n * 32 + in * 8 + grp;
                bh[in][0] = S[OFF_BH + (kb + tig) * PB + nb];
                bh[in][1] = S[OFF_BH + (kb + tig + 4) * PB + nb];
            }
#pragma unroll
            for (int im = 0; im < 4; im++)
#pragma unroll
                for (int in = 0; in < 4; in++) {
                    mma_f16(acc[im][in], ah[im][0], ah[im][1], ah[im][2], ah[im][3],
                            bh[in][0], bh[in][1]);
                    if (PASSES >= 2)
                        mma_f16(acc[im][in], al[im][0], al[im][1], al[im][2], al[im][3],
                                bh[in][0], bh[in][1]);
                }
        }
        __syncthreads();
    }

    // ---- epilogue ----
    const bool n2 = ((N & 1) == 0);
#pragma unroll
    for (int im = 0; im < 4; im++) {
        int r0 = m0 + warp_m * 64 + im * 16 + grp;
        int r1 = r0 + 8;
#pragma unroll
        for (int in = 0; in < 4; in++) {
            int nc = n0 + warp_n * 32 + in * 8 + tig * 2;
            float v00 = acc[im][in][0], v01 = acc[im][in][1];
            float v10 = acc[im][in][2], v11 = acc[im][in][3];
            if (EPI & 1) {
                float b0v = (nc < N) ? bias[nc] : 0.f;
                float b1v = (nc + 1 < N) ? bias[nc + 1] : 0.f;
                v00 += b0v; v10 += b0v; v01 += b1v; v11 += b1v;
            }
            if (EPI & 2) {
                v00 = gelu_f(v00); v01 = gelu_f(v01);
                v10 = gelu_f(v10); v11 = gelu_f(v11);
            }
            if (EPI & 4) {
                if (nc < N) { v00 += res[(size_t)r0 * N + nc]; v10 += res[(size_t)r1 * N + nc]; }
                if (nc + 1 < N) { v01 += res[(size_t)r0 * N + nc + 1]; v11 += res[(size_t)r1 * N + nc + 1]; }
            }
            if (OUTM == 1) {
                uint32_t ph, pl;
                split2(v00, v01, ph, pl);
                Ch[(size_t)r0 * (N / 2) + nc / 2] = ph;
                Cl[(size_t)r0 * (N / 2) + nc / 2] = pl;
                split2(v10, v11, ph, pl);
                Ch[(size_t)r1 * (N / 2) + nc / 2] = ph;
                Cl[(size_t)r1 * (N / 2) + nc / 2] = pl;
            } else if (OUTM == 2) {
                if (n0 < 2 * CC) {   // Q,K columns -> pair planes (row stride 768)
                    uint32_t ph, pl;
                    split2(v00, v01, ph, pl);
                    Ch[(size_t)r0 * 768 + nc / 2] = ph;
                    Cl[(size_t)r0 * 768 + nc / 2] = pl;
                    split2(v10, v11, ph, pl);
                    Ch[(size_t)r1 * 768 + nc / 2] = ph;
                    Cl[(size_t)r1 * 768 + nc / 2] = pl;
                } else {             // V columns -> fp32 qkv
                    *(float2*)(C + (size_t)r0 * N + nc) = make_float2(v00, v01);
                    *(float2*)(C + (size_t)r1 * N + nc) = make_float2(v10, v11);
                }
            } else {
                if (n2 && nc + 1 < N) {
                    *(float2*)(C + (size_t)r0 * N + nc) = make_float2(v00, v01);
                    *(float2*)(C + (size_t)r1 * N + nc) = make_float2(v10, v11);
                } else {
                    if (nc < N)     { C[(size_t)r0 * N + nc]     = v00; C[(size_t)r1 * N + nc]     = v10; }
                    if (nc + 1 < N) { C[(size_t)r0 * N + nc + 1] = v01; C[(size_t)r1 * N + nc + 1] = v11; }
                }
            }
        }
    }
}

// ---------------- 64x128-tile variant (proj / fc2), 2-pass, 3-stage pipeline ----------------
#define STGM 4736             // 64*20*2 + 16*136
#define OFF_ALM 1280
#define OFF_BHM 2560
#define GSMEMM (3 * STGM * 4) // 56832 bytes

template<int EPI, int OUTM>
__global__ __launch_bounds__(256, 2)
void gemm_mmaM64(const uint32_t* __restrict__ Ah, const uint32_t* __restrict__ Al, int KH,
                 const uint32_t* __restrict__ Bh, int NP,
                 const float* __restrict__ bias, const float* __restrict__ res,
                 float* __restrict__ C, uint32_t* __restrict__ Ch, uint32_t* __restrict__ Cl,
                 int N) {
    extern __shared__ __align__(16) uint32_t sm[];
    const int t = threadIdx.x;
    const int wid = t >> 5, lane = t & 31;
    const int grp = lane >> 2, tig = lane & 3;
    const int warp_m = wid >> 2;
    const int warp_n = wid & 3;
    const int m0 = blockIdx.x * 64;
    const int n0 = blockIdx.y * 128;
    const uint32_t sb = smem_u32(sm);

    float acc[2][4][4];
#pragma unroll
    for (int im = 0; im < 2; im++)
#pragma unroll
        for (int in = 0; in < 4; in++)
#pragma unroll
            for (int r = 0; r < 4; r++) acc[im][in][r] = 0.f;

    const int nch = KH / 16;

    auto prefetch = [&](int c, int st) {
        uint32_t base = sb + (uint32_t)st * STGM * 4;
        int k0 = c * 16;
        {
            int row = t >> 2, ch = (t & 3) * 4;
            size_t go = (size_t)(m0 + row) * KH + k0 + ch;
            cp16(base + (row * PA + ch) * 4, Ah + go);
            cp16(base + (OFF_ALM + row * PA + ch) * 4, Al + go);
        }
#pragma unroll
        for (int i = 0; i < 2; i++) {
            int idx = t + i * 256;
            int kp = idx >> 5, ch = (idx & 31) * 4;
            size_t go = (size_t)(k0 + kp) * NP + n0 + ch;
            cp16(base + (OFF_BHM + kp * PB + ch) * 4, Bh + go);
        }
        asm volatile("cp.async.commit_group;" ::: "memory");
    };

    prefetch(0, 0);
    if (nch > 1) prefetch(1, 1);
    for (int c = 0; c < nch; c++) {
        if (c + 2 < nch) {
            prefetch(c + 2, (c + 2) % 3);
            asm volatile("cp.async.wait_group 2;" ::: "memory");
        } else if (c + 1 < nch) {
            asm volatile("cp.async.wait_group 1;" ::: "memory");
        } else {
            asm volatile("cp.async.wait_group 0;" ::: "memory");
        }
        __syncthreads();
        const uint32_t* S = sm + (c % 3) * STGM;
#pragma unroll
        for (int ks = 0; ks < 2; ks++) {
            const int kb = ks * 8;
            uint32_t ah[2][4], al[2][4];
#pragma unroll
            for (int im = 0; im < 2; im++) {
                int r0 = (warp_m * 32 + im * 16 + grp) * PA;
                int r1 = r0 + 8 * PA;
                ah[im][0] = S[r0 + kb + tig];
                ah[im][1] = S[r1 + kb + tig];
                ah[im][2] = S[r0 + kb + tig + 4];
                ah[im][3] = S[r1 + kb + tig + 4];
                al[im][0] = S[OFF_ALM + r0 + kb + tig];
                al[im][1] = S[OFF_ALM + r1 + kb + tig];
                al[im][2] = S[OFF_ALM + r0 + kb + tig + 4];
                al[im][3] = S[OFF_ALM + r1 + kb + tig + 4];
            }
            uint32_t bh[4][2];
#pragma unroll
            for (int in = 0; in < 4; in++) {
                int nb = warp_n * 32 + in * 8 + grp;
                bh[in][0] = S[OFF_BHM + (kb + tig) * PB + nb];
                bh[in][1] = S[OFF_BHM + (kb + tig + 4) * PB + nb];
            }
#pragma unroll
            for (int im = 0; im < 2; im++)
#pragma unroll
                for (int in = 0; in < 4; in++) {
                    mma_f16(acc[im][in], ah[im][0], ah[im][1], ah[im][2], ah[im][3],
                            bh[in][0], bh[in][1]);
                    mma_f16(acc[im][in], al[im][0], al[im][1], al[im][2], al[im][3],
                            bh[in][0], bh[in][1]);
                }
        }
        __syncthreads();
    }

    // ---- epilogue ----
#pragma unroll
    for (int im = 0; im < 2; im++) {
        int r0 = m0 + warp_m * 32 + im * 16 + grp;
        int r1 = r0 + 8;
#pragma unroll
        for (int in = 0; in < 4; in++) {
            int nc = n0 + warp_n * 32 + in * 8 + tig * 2;
            float v00 = acc[im][in][0], v01 = acc[im][in][1];
            float v10 = acc[im][in][2], v11 = acc[im][in][3];
            if (EPI & 1) {
                float b0v = bias[nc], b1v = bias[nc + 1];
                v00 += b0v; v10 += b0v; v01 += b1v; v11 += b1v;
            }
            if (EPI & 2) {
                v00 = gelu_f(v00); v01 = gelu_f(v01);
                v10 = gelu_f(v10); v11 = gelu_f(v11);
            }
            if (EPI & 4) {
                v00 += res[(size_t)r0 * N + nc];
                v01 += res[(size_t)r0 * N + nc + 1];
                v10 += res[(size_t)r1 * N + nc];
                v11 += res[(size_t)r1 * N + nc + 1];
            }
            if (OUTM == 1) {
                uint32_t ph, pl;
                split2(v00, v01, ph, pl);
                Ch[(size_t)r0 * (N / 2) + nc / 2] = ph;
                Cl[(size_t)r0 * (N / 2) + nc / 2] = pl;
                split2(v10, v11, ph, pl);
                Ch[(size_t)r1 * (N / 2) + nc / 2] = ph;
                Cl[(size_t)r1 * (N / 2) + nc / 2] = pl;
            } else {
                *(float2*)(C + (size_t)r0 * N + nc) = make_float2(v00, v01);
                *(float2*)(C + (size_t)r1 * N + nc) = make_float2(v10, v11);
            }
        }
    }
}

// ---------------- MMA flash-attention (Q/K planes via cp.async, online softmax) ----------------
#define APD 36
#define APLANE (64 * APD)                // 2304 u32
#define ASMEM (6 * APLANE * 4)           // 55296 bytes

__global__ __launch_bounds__(128, 3)
void attn_mma_kernel(const uint32_t* __restrict__ qkh, const uint32_t* __restrict__ qkl,
                     const float* __restrict__ qkv,
                     uint32_t* __restrict__ yh, uint32_t* __restrict__ yl) {
    extern __shared__ __align__(16) uint32_t as[];
    uint32_t* sQh = as;
    uint32_t* sQl = as + APLANE;
    uint32_t* sKh = as + 2 * APLANE;
    uint32_t* sKl = as + 3 * APLANE;
    uint32_t* sVh = as + 4 * APLANE;     // [d][jpair]
    uint32_t* sVl = as + 5 * APLANE;

    const int t = threadIdx.x;
    const int warp = t >> 5, lane = t & 31;
    const int grp = lane >> 2, tig = lane & 3;
    const int hd = blockIdx.y, b = blockIdx.z;
    const int qblk = gridDim.x - 1 - blockIdx.x;   // long blocks first
    const int qb = qblk * 64;
    const int m0 = warp * 16;

    const uint32_t aQh = smem_u32(sQh), aQl = smem_u32(sQl);
    const uint32_t aKh = smem_u32(sKh), aKl = smem_u32(sKl);

    // ---- stage Q planes via cp.async: 64 rows x 32 u32 per plane (8 x 16B per row) ----
#pragma unroll
    for (int i = 0; i < 8; i++) {
        int idx = t + i * 128;             // 0..1023
        int plane = idx >> 9;              // 0 hi, 1 lo
        int rem = idx & 511;
        int row = rem >> 3, ch = (rem & 7) * 4;   // ch 0..28
        const uint32_t* src = (plane ? qkl : qkh)
            + (size_t)(b * TT + qb + row) * 768 + hd * 32 + ch;
        uint32_t dst = (plane ? aQl : aQh) + (uint32_t)(row * APD + ch) * 4;
        cp16(dst, src);
    }
    asm volatile("cp.async.commit_group;" ::: "memory");

    const float* Vb = qkv + (size_t)b * TT * C3 + 2 * CC + hd * DD;
    const int kcol = 384 + hd * 32;        // K plane column base

    float oacc[8][4];
#pragma unroll
    for (int nf = 0; nf < 8; nf++)
#pragma unroll
        for (int e = 0; e < 4; e++) oacc[nf][e] = 0.f;
    float mr1 = -1e30f, mr2 = -1e30f, lr1 = 0.f, lr2 = 0.f;

    for (int jt = 0; jt <= qblk; jt++) {
        const int j0 = jt * 64;
        __syncthreads();
        // ---- stage K planes via cp.async: 64 rows x 32 u32 per plane ----
#pragma unroll
        for (int i = 0; i < 8; i++) {
            int idx = t + i * 128;
            int plane = idx >> 9;
            int rem = idx & 511;
            int row = rem >> 3, ch = (rem & 7) * 4;
            const uint32_t* src = (plane ? qkl : qkh)
                + (size_t)(b * TT + j0 + row) * 768 + kcol + ch;
            uint32_t dst = (plane ? aKl : aKh) + (uint32_t)(row * APD + ch) * 4;
            cp16(dst, src);
        }
        asm volatile("cp.async.commit_group;" ::: "memory");
        // ---- stage V transposed [d][jpair] from fp32 ----
#pragma unroll
        for (int i = 0; i < 16; i++) {
            int w = t + i * 128;
            int d = w & 63, jp = w >> 6;
            float v0 = Vb[(size_t)(j0 + 2 * jp)     * C3 + d];
            float v1 = Vb[(size_t)(j0 + 2 * jp + 1) * C3 + d];
            uint32_t h, l;
            split2(v0, v1, h, l);
            sVh[d * APD + jp] = h;
            sVl[d * APD + jp] = l;
        }
        asm volatile("cp.async.wait_group 0;" ::: "memory");
        __syncthreads();

        float s[8][4];
#pragma unroll
        for (int nf = 0; nf < 8; nf++)
#pragma unroll
            for (int e = 0; e < 4; e++) s[nf][e] = 0.f;

#pragma unroll
        for (int ks = 0; ks < 4; ks++) {
            const int kb = ks * 8;
            uint32_t qh0 = sQh[(m0 + grp)     * APD + kb + tig];
            uint32_t qh1 = sQh[(m0 + grp + 8) * APD + kb + tig];
            uint32_t qh2 = sQh[(m0 + grp)     * APD + kb + tig + 4];
            uint32_t qh3 = sQh[(m0 + grp + 8) * APD + kb + tig + 4];
            uint32_t ql0 = sQl[(m0 + grp)     * APD + kb + tig];
            uint32_t ql1 = sQl[(m0 + grp + 8) * APD + kb + tig];
            uint32_t ql2 = sQl[(m0 + grp)     * APD + kb + tig + 4];
            uint32_t ql3 = sQl[(m0 + grp + 8) * APD + kb + tig + 4];
#pragma unroll
            for (int nf = 0; nf < 8; nf++) {
                uint32_t bh0 = sKh[(nf * 8 + grp) * APD + kb + tig];
                uint32_t bh1 = sKh[(nf * 8 + grp) * APD + kb + tig + 4];
                uint32_t bl0 = sKl[(nf * 8 + grp) * APD + kb + tig];
                uint32_t bl1 = sKl[(nf * 8 + grp) * APD + kb + tig + 4];
                mma_f16(s[nf], qh0, qh1, qh2, qh3, bh0, bh1);
                mma_f16(s[nf], qh0, qh1, qh2, qh3, bl0, bl1);
                mma_f16(s[nf], ql0, ql1, ql2, ql3, bh0, bh1);
            }
        }

        // softmax scale (Q not pre-scaled)
#pragma unroll
        for (int nf = 0; nf < 8; nf++) {
            s[nf][0] *= 0.125f; s[nf][1] *= 0.125f;
            s[nf][2] *= 0.125f; s[nf][3] *= 0.125f;
        }

        if (jt == qblk) {
#pragma unroll
            for (int nf = 0; nf < 8; nf++) {
                int jc = nf * 8 + 2 * tig;
                int r1 = m0 + grp, r2 = r1 + 8;
                if (jc     > r1) s[nf][0] = -1e30f;
                if (jc + 1 > r1) s[nf][1] = -1e30f;
                if (jc     > r2) s[nf][2] = -1e30f;
                if (jc + 1 > r2) s[nf][3] = -1e30f;
            }
        }

        float tm1 = -1e30f, tm2 = -1e30f;
#pragma unroll
        for (int nf = 0; nf < 8; nf++) {
            tm1 = fmaxf(tm1, fmaxf(s[nf][0], s[nf][1]));
            tm2 = fmaxf(tm2, fmaxf(s[nf][2], s[nf][3]));
        }
        tm1 = fmaxf(tm1, __shfl_xor_sync(0xffffffffu, tm1, 1));
        tm1 = fmaxf(tm1, __shfl_xor_sync(0xffffffffu, tm1, 2));
        tm2 = fmaxf(tm2, __shfl_xor_sync(0xffffffffu, tm2, 1));
        tm2 = fmaxf(tm2, __shfl_xor_sync(0xffffffffu, tm2, 2));
        float mn1 = fmaxf(mr1, tm1), mn2 = fmaxf(mr2, tm2);
        float c1 = __expf(mr1 - mn1), c2 = __expf(mr2 - mn2);
        float ts1 = 0.f, ts2 = 0.f;
#pragma unroll
        for (int nf = 0; nf < 8; nf++) {
            s[nf][0] = __expf(s[nf][0] - mn1);
            s[nf][1] = __expf(s[nf][1] - mn1);
            s[nf][2] = __expf(s[nf][2] - mn2);
            s[nf][3] = __expf(s[nf][3] - mn2);
            ts1 += s[nf][0] + s[nf][1];
            ts2 += s[nf][2] + s[nf][3];
        }
        ts1 += __shfl_xor_sync(0xffffffffu, ts1, 1);
        ts1 += __shfl_xor_sync(0xffffffffu, ts1, 2);
        ts2 += __shfl_xor_sync(0xffffffffu, ts2, 1);
        ts2 += __shfl_xor_sync(0xffffffffu, ts2, 2);
        lr1 = lr1 * c1 + ts1;
        lr2 = lr2 * c2 + ts2;
        mr1 = mn1; mr2 = mn2;
#pragma unroll
        for (int nf = 0; nf < 8; nf++) {
            oacc[nf][0] *= c1; oacc[nf][1] *= c1;
            oacc[nf][2] *= c2; oacc[nf][3] *= c2;
        }

#pragma unroll
        for (int ks = 0; ks < 4; ks++) {
            uint32_t ph0, pl0, ph1, pl1, ph2, pl2, ph3, pl3;
            split2(s[2 * ks][0],     s[2 * ks][1],     ph0, pl0);
            split2(s[2 * ks][2],     s[2 * ks][3],     ph1, pl1);
            split2(s[2 * ks + 1][0], s[2 * ks + 1][1], ph2, pl2);
            split2(s[2 * ks + 1][2], s[2 * ks + 1][3], ph3, pl3);
#pragma unroll
            for (int nf = 0; nf < 8; nf++) {
                uint32_t bh0 = sVh[(nf * 8 + grp) * APD + ks * 8 + tig];
                uint32_t bh1 = sVh[(nf * 8 + grp) * APD + ks * 8 + tig + 4];
                uint32_t bl0 = sVl[(nf * 8 + grp) * APD + ks * 8 + tig];
                uint32_t bl1 = sVl[(nf * 8 + grp) * APD + ks * 8 + tig + 4];
                mma_f16(oacc[nf], ph0, ph1, ph2, ph3, bh0, bh1);
                mma_f16(oacc[nf], ph0, ph1, ph2, ph3, bl0, bl1);
                mma_f16(oacc[nf], pl0, pl1, pl2, pl3, bh0, bh1);
            }
        }
    }

    float inv1 = 1.f / lr1, inv2 = 1.f / lr2;
    size_t r1 = (size_t)(b * TT + qb + m0 + grp) * (CC / 2) + hd * 32;
    size_t r2 = r1 + 8 * (CC / 2);
#pragma unroll
    for (int nf = 0; nf < 8; nf++) {
        uint32_t h, l;
        split2(oacc[nf][0] * inv1, oacc[nf][1] * inv1, h, l);
        yh[r1 + nf * 4 + tig] = h; yl[r1 + nf * 4 + tig] = l;
        split2(oacc[nf][2] * inv2, oacc[nf][3] * inv2, h, l);
        yh[r2 + nf * 4 + tig] = h; yl[r2 + nf * 4 + tig] = l;
    }
}

// ---------------- host orchestration ----------------
extern "C" void kernel_launch(void* const* d_in, const int* in_sizes, int n_in,
                              void* d_out, int out_size) {
    const int*   idx   = (const int*)  d_in[0];
    const float* wte   = (const float*)d_in[1];
    const float* wpe   = (const float*)d_in[2];
    const float* ln1_g = (const float*)d_in[3];
    const float* ln1_b = (const float*)d_in[4];
    const float* wqkv  = (const float*)d_in[5];
    const float* bqkv  = (const float*)d_in[6];
    const float* wproj = (const float*)d_in[7];
    const float* bproj = (const float*)d_in[8];
    const float* ln2_g = (const float*)d_in[9];
    const float* ln2_b = (const float*)d_in[10];
    const float* wfc   = (const float*)d_in[11];
    const float* bfc   = (const float*)d_in[12];
    const float* wfc2  = (const float*)d_in[13];
    const float* bfc2  = (const float*)d_in[14];
    const float* lnf_g = (const float*)d_in[15];
    const float* lnf_b = (const float*)d_in[16];
    const float* lm_w  = (const float*)d_in[17];
    float* out = (float*)d_out;

    float *x, *qkv;
    uint32_t *lnh, *lnl, *acth, *actl, *qkh, *qkl;
    uint32_t *wqh, *wph, *wfh, *w2h, *lmh;
    cudaGetSymbolAddress((void**)&x,    g_x);
    cudaGetSymbolAddress((void**)&qkv,  g_qkv);
    cudaGetSymbolAddress((void**)&lnh,  g_lnh);
    cudaGetSymbolAddress((void**)&lnl,  g_lnl);
    cudaGetSymbolAddress((void**)&acth, g_acth);
    cudaGetSymbolAddress((void**)&actl, g_actl);
    cudaGetSymbolAddress((void**)&qkh,  g_qkh);
    cudaGetSymbolAddress((void**)&qkl,  g_qkl);
    cudaGetSymbolAddress((void**)&wqh,  g_wqkvh);
    cudaGetSymbolAddress((void**)&wph,  g_wprjh);
    cudaGetSymbolAddress((void**)&wfh,  g_wfch);
    cudaGetSymbolAddress((void**)&w2h,  g_wfc2h);
    cudaGetSymbolAddress((void**)&lmh,  g_lmwh);

    cudaFuncSetAttribute(gemm_mma<1, 2, 2>, cudaFuncAttributeMaxDynamicSharedMemorySize, GSMEM);
    cudaFuncSetAttribute(gemm_mma<3, 1, 2>, cudaFuncAttributeMaxDynamicSharedMemorySize, GSMEM);
    cudaFuncSetAttribute(gemm_mma<0, 0, 1>, cudaFuncAttributeMaxDynamicSharedMemorySize, GSMEM);
    cudaFuncSetAttribute(gemm_mmaM64<5, 0>, cudaFuncAttributeMaxDynamicSharedMemorySize, GSMEMM);
    cudaFuncSetAttribute(attn_mma_kernel, cudaFuncAttributeMaxDynamicSharedMemorySize, ASMEM);

    // ---- weight conversions (hi planes only; once per call) ----
    convert_w<<<dim3((C3 + 1023) / 1024, LL * CC / 2), 256>>>(wqkv,  wqh, nullptr, C3, C3);
    convert_w<<<dim3((CC + 1023) / 1024, LL * CC / 2), 256>>>(wproj, wph, nullptr, CC, CC);
    convert_w<<<dim3((C4 + 1023) / 1024, LL * CC / 2), 256>>>(wfc,   wfh, nullptr, C4, C4);
    convert_w<<<dim3((CC + 1023) / 1024, LL * C4 / 2), 256>>>(wfc2,  w2h, nullptr, CC, CC);
    convert_w<<<dim3((VP + 1023) / 1024, CC / 2),      256>>>(lm_w,  lmh, nullptr, VV, VP);

    embed_kernel<<<MR, 256>>>(idx, wte, wpe);

    for (int l = 0; l < LL; l++) {
        ln_kernel<<<MR / 8, 256>>>(x, ln1_g + (size_t)l * CC, ln1_b + (size_t)l * CC, lnh, lnl);

        // qkv: Q,K -> pair planes; V -> fp32  (128-tile, 288 CTAs, 2-pass)
        gemm_mma<1, 2, 2><<<dim3(16, C3 / 128), 256, GSMEM>>>(
            lnh, lnl, CC / 2,
            wqh + (size_t)l * (CC / 2) * C3, C3,
            bqkv + (size_t)l * C3, nullptr, qkv, qkh, qkl, C3);

        attn_mma_kernel<<<dim3(TT / 64, HH, BB), 128, ASMEM>>>(qkh, qkl, qkv, acth, actl);

        // x = x + y @ wproj + bproj  (64x128 tiles: 32x6 = 192 CTAs, 2-pass)
        gemm_mmaM64<5, 0><<<dim3(32, 6), 256, GSMEMM>>>(
            acth, actl, CC / 2,
            wph + (size_t)l * (CC / 2) * CC, CC,
            bproj + (size_t)l * CC, x, x, nullptr, nullptr, CC);

        ln_kernel<<<MR / 8, 256>>>(x, ln2_g + (size_t)l * CC, ln2_b + (size_t)l * CC, lnh, lnl);

        // fc = gelu(ln @ wfc + bfc), pair-plane out  (128-tile: 16x24, 2-pass)
        gemm_mma<3, 1, 2><<<dim3(16, C4 / 128), 256, GSMEM>>>(
            lnh, lnl, CC / 2,
            wfh + (size_t)l * (CC / 2) * C4, C4,
            bfc + (size_t)l * C4, nullptr, nullptr, acth, actl, C4);

        // x = x + fc @ wfc2 + bfc2  (64x128 tiles: 32x6, 2-pass, K=3072)
        gemm_mmaM64<5, 0><<<dim3(32, 6), 256, GSMEMM>>>(
            acth, actl, C4 / 2,
            w2h + (size_t)l * (C4 / 2) * CC, CC,
            bfc2 + (size_t)l * CC, x, x, nullptr, nullptr, CC);
    }

    ln_kernel<<<MR / 8, 256>>>(x, lnf_g, lnf_b, lnh, lnl);

    // logits = ln @ lm_w  [2048 x 50257] — single-pass fp16 (error leaf)
    gemm_mma<0, 0, 1><<<dim3(16, VP / 128), 256, GSMEM>>>(
        lnh, lnl, CC / 2, lmh, VP,
        nullptr, nullptr, out, nullptr, nullptr, VV);
}